// round 1
// baseline (speedup 1.0000x reference)
#include <cuda_runtime.h>
#include <cuda_bf16.h>
#include <math.h>

#define S_  2048
#define N_  64
#define BS_ 16
#define W_  512
#define NH_ 8
#define H_  1024
#define V_  32000
#define DH_ 128
#define T_  3072
#define QB  8
#define SCALE 0.08838834764831845f  // 1/sqrt(128)

// ---------------- scratch (device globals; no allocation) ----------------
__device__ float g_h [T_*H_];
__device__ float g_x [T_*H_];
__device__ float g_q [T_*H_];
__device__ float g_k [T_*H_];
__device__ float g_v [T_*H_];
__device__ float g_kT[T_*H_];
__device__ float g_ao[T_*H_];
__device__ float g_h2[T_*H_];
__device__ float g_inj[N_*H_];
__device__ int   g_pos[T_];

// ---------------- helpers ----------------
__device__ __forceinline__ float wmax(float v){
#pragma unroll
    for (int o=16;o>0;o>>=1) v = fmaxf(v, __shfl_xor_sync(0xffffffffu, v, o));
    return v;
}
__device__ __forceinline__ float wsum(float v){
#pragma unroll
    for (int o=16;o>0;o>>=1) v += __shfl_xor_sync(0xffffffffu, v, o);
    return v;
}

// ---------------- inj[n] = concat(hs0[ctx], hs1[ctx]) @ fc_w ----------------
__global__ void inj_kernel(const float* __restrict__ hs, const int* __restrict__ anchors,
                           const float* __restrict__ fcw, float* __restrict__ inj)
{
    int n = blockIdx.x;
    int c = blockIdx.y * 128 + threadIdx.x;
    int a = anchors[n];
    int ctx = a - 1; if (ctx < 0) ctx = 0;
    const float* h0 = hs + (size_t)ctx * H_;
    const float* h1 = hs + (size_t)S_ * H_ + (size_t)ctx * H_;
    float acc = 0.f;
    for (int k = 0; k < H_; k++) acc += h0[k] * fcw[(size_t)k * H_ + c];
    for (int k = 0; k < H_; k++) acc += h1[k] * fcw[(size_t)(H_ + k) * H_ + c];
    inj[(size_t)n * H_ + c] = acc;
}

// ---------------- h = [embed[ids]; embed[blk_ids] + inj], pos ----------------
__global__ void build_h_kernel(const int* __restrict__ ids, const int* __restrict__ anchors,
                               const float* __restrict__ embed, const float* __restrict__ inj,
                               float* __restrict__ h, int* __restrict__ pos)
{
    int t = blockIdx.x;
    int tok;
    const float* add = nullptr;
    if (t < S_) {
        tok = ids[t];
        if (threadIdx.x == 0) pos[t] = t;
    } else {
        int n = (t - S_) / BS_, j = (t - S_) % BS_;
        int a = anchors[n];
        int ap = a; if (ap < 0) ap = 0; if (ap > S_-1) ap = S_-1;
        tok = (j == 0) ? ids[ap] : 0;   // MASK_TOKEN = 0
        add = inj + (size_t)n * H_;
        if (threadIdx.x == 0) pos[t] = a + j;
    }
    const float* e = embed + (size_t)tok * H_;
    for (int c = threadIdx.x; c < H_; c += blockDim.x)
        h[(size_t)t * H_ + c] = e[c] + (add ? add[c] : 0.f);
}

// ---------------- rmsnorm ----------------
__global__ __launch_bounds__(256) void rmsnorm_kernel(const float* __restrict__ in,
                                                      const float* __restrict__ w,
                                                      float* __restrict__ outp)
{
    int t = blockIdx.x;
    const float* r = in + (size_t)t * H_;
    float ss = 0.f;
    for (int c = threadIdx.x; c < H_; c += 256) { float v = r[c]; ss += v * v; }
    ss = wsum(ss);
    __shared__ float sred[8];
    if ((threadIdx.x & 31) == 0) sred[threadIdx.x >> 5] = ss;
    __syncthreads();
    float tot = 0.f;
#pragma unroll
    for (int i = 0; i < 8; i++) tot += sred[i];
    float inv = rsqrtf(tot * (1.0f / H_) + 1e-6f);
    for (int c = threadIdx.x; c < H_; c += 256)
        outp[(size_t)t * H_ + c] = r[c] * inv * w[c];
}

// ---------------- RoPE on q and k in-place ----------------
__global__ void rope_kernel(float* __restrict__ q, float* __restrict__ k,
                            const int* __restrict__ pos)
{
    int t = blockIdx.x;
    int idx = threadIdx.x;          // 0..511
    int hh = idx >> 6, i = idx & 63;
    int p = pos[t];
    double ang = (double)p * pow(10000.0, -(double)i / 64.0);
    double sd, cd;
    sincos(ang, &sd, &cd);
    float s = (float)sd, c = (float)cd;
    size_t b = (size_t)t * H_ + hh * DH_ + i;
    float x1 = q[b], x2 = q[b + 64];
    q[b]      = x1 * c - x2 * s;
    q[b + 64] = x2 * c + x1 * s;
    x1 = k[b]; x2 = k[b + 64];
    k[b]      = x1 * c - x2 * s;
    k[b + 64] = x2 * c + x1 * s;
}

// ---------------- transpose k [T][H] -> kT [H][T] ----------------
__global__ void transpose_kernel(const float* __restrict__ in, float* __restrict__ out)
{
    __shared__ float tile[32][33];
    int hx = blockIdx.x * 32;   // H base
    int ty = blockIdx.y * 32;   // T base
    int x = threadIdx.x, y0 = threadIdx.y;  // block (32, 8)
#pragma unroll
    for (int dy = 0; dy < 32; dy += 8)
        tile[y0 + dy][x] = in[(size_t)(ty + y0 + dy) * H_ + hx + x];
    __syncthreads();
#pragma unroll
    for (int dy = 0; dy < 32; dy += 8)
        out[(size_t)(hx + y0 + dy) * T_ + ty + x] = tile[x][y0 + dy];
}

// ---------------- attention: 8 queries x 1 head per block, 128 threads ----------------
__global__ __launch_bounds__(128) void attn_kernel(
    const float* __restrict__ q, const float* __restrict__ kT,
    const float* __restrict__ v, const int* __restrict__ anchors,
    float* __restrict__ out)
{
    __shared__ float qs[QB][DH_];
    __shared__ float pbuf[QB][128];
    __shared__ float redm[QB][4];
    __shared__ float reds[QB][4];

    int h   = blockIdx.y;
    int t0  = blockIdx.x * QB;
    int tid = threadIdx.x;
    int w   = tid >> 5, lane = tid & 31;

#pragma unroll
    for (int qi = 0; qi < QB; qi++)
        qs[qi][tid] = q[(size_t)(t0 + qi) * H_ + h * DH_ + tid] * SCALE;
    __syncthreads();

    float m[QB], l[QB], acc[QB];
#pragma unroll
    for (int qi = 0; qi < QB; qi++) { m[qi] = -INFINITY; l[qi] = 0.f; acc[qi] = 0.f; }

    int lo[QB], hi[QB];

    auto proc = [&](int base, int cnt) {
        int k = base + tid;
        bool act = tid < cnt;
        float s[QB];
#pragma unroll
        for (int qi = 0; qi < QB; qi++) s[qi] = -INFINITY;
        if (act) {
#pragma unroll
            for (int qi = 0; qi < QB; qi++) s[qi] = 0.f;
            const float* kp = kT + (size_t)(h * DH_) * T_ + k;
            for (int d = 0; d < DH_; d += 4) {
                float kv0 = kp[(size_t)(d + 0) * T_];
                float kv1 = kp[(size_t)(d + 1) * T_];
                float kv2 = kp[(size_t)(d + 2) * T_];
                float kv3 = kp[(size_t)(d + 3) * T_];
#pragma unroll
                for (int qi = 0; qi < QB; qi++) {
                    float4 qv = *(const float4*)&qs[qi][d];
                    s[qi] += qv.x * kv0 + qv.y * kv1 + qv.z * kv2 + qv.w * kv3;
                }
            }
#pragma unroll
            for (int qi = 0; qi < QB; qi++)
                if (k < lo[qi] || k > hi[qi]) s[qi] = -INFINITY;
        }
        __syncthreads();   // prev chunk's pbuf/red readers done
#pragma unroll
        for (int qi = 0; qi < QB; qi++) {
            float x = wmax(s[qi]);
            if (lane == 0) redm[qi][w] = x;
        }
        __syncthreads();
        float nm[QB];
#pragma unroll
        for (int qi = 0; qi < QB; qi++) {
            float cm = fmaxf(fmaxf(redm[qi][0], redm[qi][1]), fmaxf(redm[qi][2], redm[qi][3]));
            nm[qi] = fmaxf(m[qi], cm);
            float p = (s[qi] == -INFINITY) ? 0.f : expf(s[qi] - nm[qi]);
            pbuf[qi][tid] = p;
            float sp = wsum(p);
            if (lane == 0) reds[qi][w] = sp;
        }
        __syncthreads();
#pragma unroll
        for (int qi = 0; qi < QB; qi++) {
            float f = (m[qi] == -INFINITY) ? 0.f : expf(m[qi] - nm[qi]);
            float cs = reds[qi][0] + reds[qi][1] + reds[qi][2] + reds[qi][3];
            l[qi] = l[qi] * f + cs;
            acc[qi] *= f;
            m[qi] = nm[qi];
        }
        const float* vp = v + (size_t)base * H_ + h * DH_ + tid;
        for (int j = 0; j < cnt; j += 4) {
            float vv0 = vp[(size_t)(j + 0) * H_];
            float vv1 = vp[(size_t)(j + 1) * H_];
            float vv2 = vp[(size_t)(j + 2) * H_];
            float vv3 = vp[(size_t)(j + 3) * H_];
#pragma unroll
            for (int qi = 0; qi < QB; qi++) {
                float4 pv = *(const float4*)&pbuf[qi][j];
                acc[qi] += pv.x * vv0 + pv.y * vv1 + pv.z * vv2 + pv.w * vv3;
            }
        }
    };

    if (t0 < S_) {
        // full queries: causal over full keys only
#pragma unroll
        for (int qi = 0; qi < QB; qi++) { lo[qi] = 0; hi[qi] = t0 + qi; }
        for (int base = 0; base <= t0 + QB - 1; base += 128) proc(base, 128);
    } else {
        int nb = (t0 - S_) / BS_;
        int a  = anchors[nb];
        int ws = a - W_ + 1; if (ws < 0) ws = 0;
        int we = a - 1;
        // window over full keys
#pragma unroll
        for (int qi = 0; qi < QB; qi++) { lo[qi] = ws; hi[qi] = we; }
        for (int base = (ws >> 7) << 7; base <= we; base += 128) proc(base, 128);
        // own block (bidirectional)
        int kb = S_ + nb * BS_;
#pragma unroll
        for (int qi = 0; qi < QB; qi++) { lo[qi] = kb; hi[qi] = kb + BS_ - 1; }
        proc(kb, BS_);
    }

#pragma unroll
    for (int qi = 0; qi < QB; qi++)
        out[(size_t)(t0 + qi) * H_ + h * DH_ + tid] = acc[qi] / l[qi];
}

// ---------------- sgemm: C[M,Nc] = A[M,K] @ B[K,Nc] (+ D), row-major ----------------
// 128x128 tile, BK=8, 256 threads, 8x8 per thread. M%128==0, Nc%128==0, K%8==0.
__global__ __launch_bounds__(256) void sgemm_kernel(
    int M, int Nc, int K,
    const float* __restrict__ A, const float* __restrict__ B,
    float* __restrict__ C, const float* __restrict__ D)
{
    __shared__ float As[8][128];
    __shared__ float Bs[8][128];
    int tid  = threadIdx.x;
    int crow = blockIdx.y * 128;
    int ccol = blockIdx.x * 128;
    int arow = tid >> 1;
    int acol = (tid & 1) * 4;
    int brow = tid >> 5;
    int bcol = (tid & 31) * 4;
    int tr   = (tid >> 4) * 8;
    int tc   = (tid & 15) * 8;

    float acc[8][8];
#pragma unroll
    for (int i = 0; i < 8; i++)
#pragma unroll
        for (int j = 0; j < 8; j++) acc[i][j] = 0.f;

    const float* Ap = A + (size_t)(crow + arow) * K + acol;
    const float* Bp = B + (size_t)brow * Nc + ccol + bcol;

    for (int k0 = 0; k0 < K; k0 += 8) {
        float4 a4 = *(const float4*)(Ap + k0);
        As[acol + 0][arow] = a4.x;
        As[acol + 1][arow] = a4.y;
        As[acol + 2][arow] = a4.z;
        As[acol + 3][arow] = a4.w;
        float4 b4 = *(const float4*)(Bp + (size_t)k0 * Nc);
        *(float4*)&Bs[brow][bcol] = b4;
        __syncthreads();
#pragma unroll
        for (int kk = 0; kk < 8; kk++) {
            float4 a0 = *(const float4*)&As[kk][tr];
            float4 a1 = *(const float4*)&As[kk][tr + 4];
            float4 b0 = *(const float4*)&Bs[kk][tc];
            float4 b1 = *(const float4*)&Bs[kk][tc + 4];
            float ra[8] = {a0.x, a0.y, a0.z, a0.w, a1.x, a1.y, a1.z, a1.w};
            float rb[8] = {b0.x, b0.y, b0.z, b0.w, b1.x, b1.y, b1.z, b1.w};
#pragma unroll
            for (int i = 0; i < 8; i++)
#pragma unroll
                for (int j = 0; j < 8; j++) acc[i][j] += ra[i] * rb[j];
        }
        __syncthreads();
    }

#pragma unroll
    for (int i = 0; i < 8; i++) {
        size_t row = (size_t)(crow + tr + i);
        float* cp = C + row * Nc + ccol + tc;
        if (D) {
            const float* dp = D + row * Nc + ccol + tc;
#pragma unroll
            for (int j = 0; j < 8; j++) cp[j] = acc[i][j] + dp[j];
        } else {
            float4 c0 = make_float4(acc[i][0], acc[i][1], acc[i][2], acc[i][3]);
            float4 c1 = make_float4(acc[i][4], acc[i][5], acc[i][6], acc[i][7]);
            *(float4*)cp       = c0;
            *(float4*)(cp + 4) = c1;
        }
    }
}

// ---------------- launch ----------------
extern "C" void kernel_launch(void* const* d_in, const int* in_sizes, int n_in,
                              void* d_out, int out_size)
{
    const int*   ids     = (const int*)  d_in[0];
    const float* hs      = (const float*)d_in[1];
    const int*   anchors = (const int*)  d_in[2];
    // d_in[3] block_keep_mask: all-true by construction; intentionally unused
    const float* embed   = (const float*)d_in[4];
    const float* Wq      = (const float*)d_in[5];
    const float* Wk      = (const float*)d_in[6];
    const float* Wv      = (const float*)d_in[7];
    const float* Wo      = (const float*)d_in[8];
    const float* fcw     = (const float*)d_in[9];
    const float* lmw     = (const float*)d_in[10];
    const float* normw   = (const float*)d_in[11];

    float *h, *x, *q, *k, *v, *kT, *ao, *h2, *inj;
    int* pos;
    cudaGetSymbolAddress((void**)&h,   g_h);
    cudaGetSymbolAddress((void**)&x,   g_x);
    cudaGetSymbolAddress((void**)&q,   g_q);
    cudaGetSymbolAddress((void**)&k,   g_k);
    cudaGetSymbolAddress((void**)&v,   g_v);
    cudaGetSymbolAddress((void**)&kT,  g_kT);
    cudaGetSymbolAddress((void**)&ao,  g_ao);
    cudaGetSymbolAddress((void**)&h2,  g_h2);
    cudaGetSymbolAddress((void**)&inj, g_inj);
    cudaGetSymbolAddress((void**)&pos, g_pos);

    inj_kernel<<<dim3(N_, H_ / 128), 128>>>(hs, anchors, fcw, inj);
    build_h_kernel<<<T_, 256>>>(ids, anchors, embed, inj, h, pos);
    rmsnorm_kernel<<<T_, 256>>>(h, normw, x);

    dim3 g1(H_ / 128, T_ / 128);
    sgemm_kernel<<<g1, 256>>>(T_, H_, H_, x, Wq, q, nullptr);
    sgemm_kernel<<<g1, 256>>>(T_, H_, H_, x, Wk, k, nullptr);
    sgemm_kernel<<<g1, 256>>>(T_, H_, H_, x, Wv, v, nullptr);

    rope_kernel<<<T_, 512>>>(q, k, pos);
    transpose_kernel<<<dim3(H_ / 32, T_ / 32), dim3(32, 8)>>>(k, kT);

    attn_kernel<<<dim3(T_ / QB, NH_), 128>>>(q, kT, v, anchors, ao);

    sgemm_kernel<<<g1, 256>>>(T_, H_, H_, ao, Wo, h2, h);   // residual fused
    rmsnorm_kernel<<<T_, 256>>>(h2, normw, x);
    sgemm_kernel<<<dim3(V_ / 128, T_ / 128), 256>>>(T_, V_, H_, x, lmw, (float*)d_out, nullptr);
}

// round 4
// speedup vs baseline: 1.8477x; 1.8477x over previous
#include <cuda_runtime.h>
#include <cuda_bf16.h>
#include <math.h>
#include <stdint.h>

#define S_  2048
#define N_  64
#define BS_ 16
#define W_  512
#define NH_ 8
#define H_  1024
#define V_  32000
#define DH_ 128
#define T_  3072
#define QB  8
#define SCALE 0.08838834764831845f  // 1/sqrt(128)

// ---------------- scratch (device globals; no allocation) ----------------
__device__ float g_h [T_*H_];
__device__ float g_x [T_*H_];
__device__ float g_q [T_*H_];
__device__ float g_k [T_*H_];
__device__ float g_v [T_*H_];
__device__ float g_kT[T_*H_];
__device__ float g_ao[T_*H_];
__device__ float g_h2[T_*H_];
__device__ float g_inj[N_*H_];
__device__ int   g_pos[T_];
__device__ float g_lmwT[(size_t)V_*H_];   // lm_head_w^T [V][H]
__device__ float g_WqT[H_*H_];
__device__ float g_WkT[H_*H_];
__device__ float g_WvT[H_*H_];
__device__ float g_WoT[H_*H_];

// ---------------- helpers ----------------
__device__ __forceinline__ float wmax(float v){
#pragma unroll
    for (int o=16;o>0;o>>=1) v = fmaxf(v, __shfl_xor_sync(0xffffffffu, v, o));
    return v;
}
__device__ __forceinline__ float wsum(float v){
#pragma unroll
    for (int o=16;o>0;o>>=1) v += __shfl_xor_sync(0xffffffffu, v, o);
    return v;
}
__device__ __forceinline__ uint32_t smem_u32(const void* p){
    uint32_t a;
    asm("{ .reg .u64 t; cvta.to.shared.u64 t, %1; cvt.u32.u64 %0, t; }" : "=r"(a) : "l"(p));
    return a;
}
__device__ __forceinline__ void ldsm4(uint32_t& r0, uint32_t& r1, uint32_t& r2, uint32_t& r3,
                                      uint32_t addr){
    asm volatile("ldmatrix.sync.aligned.m8n8.x4.shared.b16 {%0,%1,%2,%3}, [%4];"
                 : "=r"(r0), "=r"(r1), "=r"(r2), "=r"(r3) : "r"(addr));
}
__device__ __forceinline__ void mma_bf16(float* c, const uint32_t* a, uint32_t b0, uint32_t b1){
    asm volatile("mma.sync.aligned.m16n8k16.row.col.f32.bf16.bf16.f32 "
                 "{%0,%1,%2,%3}, {%4,%5,%6,%7}, {%8,%9}, {%0,%1,%2,%3};"
                 : "+f"(c[0]), "+f"(c[1]), "+f"(c[2]), "+f"(c[3])
                 : "r"(a[0]), "r"(a[1]), "r"(a[2]), "r"(a[3]), "r"(b0), "r"(b1));
}
__device__ __forceinline__ void split_store(char* hi, char* lo, float4 v){
    __nv_bfloat16 hx = __float2bfloat16(v.x), hy = __float2bfloat16(v.y);
    __nv_bfloat16 hz = __float2bfloat16(v.z), hw = __float2bfloat16(v.w);
    __nv_bfloat16 lx = __float2bfloat16(v.x - __bfloat162float(hx));
    __nv_bfloat16 ly = __float2bfloat16(v.y - __bfloat162float(hy));
    __nv_bfloat16 lz = __float2bfloat16(v.z - __bfloat162float(hz));
    __nv_bfloat16 lw = __float2bfloat16(v.w - __bfloat162float(hw));
    __nv_bfloat162 h01 = __halves2bfloat162(hx, hy);
    __nv_bfloat162 h23 = __halves2bfloat162(hz, hw);
    __nv_bfloat162 l01 = __halves2bfloat162(lx, ly);
    __nv_bfloat162 l23 = __halves2bfloat162(lz, lw);
    *(uint32_t*)(hi + 0) = *(uint32_t*)&h01;
    *(uint32_t*)(hi + 4) = *(uint32_t*)&h23;
    *(uint32_t*)(lo + 0) = *(uint32_t*)&l01;
    *(uint32_t*)(lo + 4) = *(uint32_t*)&l23;
}

// ================ bf16-split tensor-core GEMM ================
// C[M,Nc] = A[M,K] @ BT[Nc,K]^T (+ D).  A, BT fp32 row-major, k-contiguous.
// CTA 128x128, K-chunk 32, double-buffered smem, 8 warps of 64x32.
#define LDSR 40                        // bf16 elements per smem row (32 + 8 pad)
#define HS_STAGE 40960
#define HS_AHI 0
#define HS_ALO 10240
#define HS_BHI 20480
#define HS_BLO 30720
#define HS_TOTAL (2*HS_STAGE)          // 81920 B

__global__ __launch_bounds__(256) void hgemm_kernel(
    int M, int Nc, int K,
    const float* __restrict__ A, const float* __restrict__ BT,
    float* __restrict__ C, const float* __restrict__ D)
{
    extern __shared__ char sm[];
    uint32_t sb = smem_u32(sm);
    int tid  = threadIdx.x, lane = tid & 31, wid = tid >> 5;
    int crow = blockIdx.y * 128, ccol = blockIdx.x * 128;
    int wm   = (wid & 1) * 64,  wn   = (wid >> 1) * 32;

    float acc[4][4][4];
#pragma unroll
    for (int i = 0; i < 4; i++)
#pragma unroll
        for (int j = 0; j < 4; j++)
#pragma unroll
            for (int r = 0; r < 4; r++) acc[i][j][r] = 0.f;

    int lrow = tid >> 1, lc = (tid & 1) * 16;
    const float* Ag = A  + (size_t)(crow + lrow) * K + lc;
    const float* Bg = BT + (size_t)(ccol + lrow) * K + lc;

    // ldmatrix byte offsets within a hi-array
    uint32_t a_off = ((wm + (lane & 15)) * LDSR + (lane >> 4) * 8) * 2;
    uint32_t b_off = ((wn + (lane >> 4) * 8 + (lane & 7)) * LDSR + ((lane >> 3) & 1) * 8) * 2;
    uint32_t s_off = (lrow * LDSR + lc) * 2;

    int kq = K / 32;
    float4 pa[4], pb[4];
#pragma unroll
    for (int i = 0; i < 4; i++) {
        pa[i] = *(const float4*)(Ag + i * 4);
        pb[i] = *(const float4*)(Bg + i * 4);
    }
    {
        char* ah = sm + HS_AHI + s_off;
        char* bh = sm + HS_BHI + s_off;
#pragma unroll
        for (int i = 0; i < 4; i++) {
            split_store(ah + i * 8, ah + (HS_ALO - HS_AHI) + i * 8, pa[i]);
            split_store(bh + i * 8, bh + (HS_BLO - HS_BHI) + i * 8, pb[i]);
        }
    }
    __syncthreads();

    for (int ch = 0; ch < kq; ch++) {
        int st = ch & 1;
        if (ch + 1 < kq) {
#pragma unroll
            for (int i = 0; i < 4; i++) {
                pa[i] = *(const float4*)(Ag + (ch + 1) * 32 + i * 4);
                pb[i] = *(const float4*)(Bg + (ch + 1) * 32 + i * 4);
            }
        }
        uint32_t base = sb + st * HS_STAGE;
#pragma unroll
        for (int ks = 0; ks < 2; ks++) {
            uint32_t ah4[4][4], al4[4][4], bh4[2][4], bl4[2][4];
#pragma unroll
            for (int mi = 0; mi < 4; mi++) {
                uint32_t adr = base + HS_AHI + a_off + mi * (16 * LDSR * 2) + ks * 32;
                ldsm4(ah4[mi][0], ah4[mi][1], ah4[mi][2], ah4[mi][3], adr);
                ldsm4(al4[mi][0], al4[mi][1], al4[mi][2], al4[mi][3], adr + (HS_ALO - HS_AHI));
            }
#pragma unroll
            for (int p = 0; p < 2; p++) {
                uint32_t adr = base + HS_BHI + b_off + p * (16 * LDSR * 2) + ks * 32;
                ldsm4(bh4[p][0], bh4[p][1], bh4[p][2], bh4[p][3], adr);
                ldsm4(bl4[p][0], bl4[p][1], bl4[p][2], bl4[p][3], adr + (HS_BLO - HS_BHI));
            }
#pragma unroll
            for (int mi = 0; mi < 4; mi++)
#pragma unroll
                for (int ni = 0; ni < 4; ni++) {
                    uint32_t b0h = bh4[ni >> 1][(ni & 1) * 2], b1h = bh4[ni >> 1][(ni & 1) * 2 + 1];
                    uint32_t b0l = bl4[ni >> 1][(ni & 1) * 2], b1l = bl4[ni >> 1][(ni & 1) * 2 + 1];
                    mma_bf16(acc[mi][ni], ah4[mi], b0h, b1h);
                    mma_bf16(acc[mi][ni], ah4[mi], b0l, b1l);
                    mma_bf16(acc[mi][ni], al4[mi], b0h, b1h);
                }
        }
        if (ch + 1 < kq) {
            char* dst = sm + ((ch + 1) & 1) * HS_STAGE;
            char* ah = dst + HS_AHI + s_off;
            char* bh = dst + HS_BHI + s_off;
#pragma unroll
            for (int i = 0; i < 4; i++) {
                split_store(ah + i * 8, ah + (HS_ALO - HS_AHI) + i * 8, pa[i]);
                split_store(bh + i * 8, bh + (HS_BLO - HS_BHI) + i * 8, pb[i]);
            }
        }
        __syncthreads();
    }

    // epilogue
#pragma unroll
    for (int mi = 0; mi < 4; mi++)
#pragma unroll
        for (int ni = 0; ni < 4; ni++) {
            size_t r0 = (size_t)(crow + wm + mi * 16 + (lane >> 2));
            int    cc = ccol + wn + ni * 8 + (lane & 3) * 2;
            float2 v0 = make_float2(acc[mi][ni][0], acc[mi][ni][1]);
            float2 v1 = make_float2(acc[mi][ni][2], acc[mi][ni][3]);
            if (D) {
                const float2 d0 = *(const float2*)(D + r0 * Nc + cc);
                const float2 d1 = *(const float2*)(D + (r0 + 8) * Nc + cc);
                v0.x += d0.x; v0.y += d0.y; v1.x += d1.x; v1.y += d1.y;
            }
            *(float2*)(C + r0 * Nc + cc)       = v0;
            *(float2*)(C + (r0 + 8) * Nc + cc) = v1;
        }
}

// ---------------- inj[n] = concat(hs0[ctx], hs1[ctx]) @ fc_w ----------------
__global__ void inj_kernel(const float* __restrict__ hs, const int* __restrict__ anchors,
                           const float* __restrict__ fcw, float* __restrict__ inj)
{
    int n = blockIdx.x;
    int c = blockIdx.y * 128 + threadIdx.x;
    int a = anchors[n];
    int ctx = a - 1; if (ctx < 0) ctx = 0;
    const float* h0 = hs + (size_t)ctx * H_;
    const float* h1 = hs + (size_t)S_ * H_ + (size_t)ctx * H_;
    float acc = 0.f;
    for (int k = 0; k < H_; k++) acc += h0[k] * fcw[(size_t)k * H_ + c];
    for (int k = 0; k < H_; k++) acc += h1[k] * fcw[(size_t)(H_ + k) * H_ + c];
    inj[(size_t)n * H_ + c] = acc;
}

// ---------------- h = [embed[ids]; embed[blk_ids] + inj], pos ----------------
__global__ void build_h_kernel(const int* __restrict__ ids, const int* __restrict__ anchors,
                               const float* __restrict__ embed, const float* __restrict__ inj,
                               float* __restrict__ h, int* __restrict__ pos)
{
    int t = blockIdx.x;
    int tok;
    const float* add = nullptr;
    if (t < S_) {
        tok = ids[t];
        if (threadIdx.x == 0) pos[t] = t;
    } else {
        int n = (t - S_) / BS_, j = (t - S_) % BS_;
        int a = anchors[n];
        int ap = a; if (ap < 0) ap = 0; if (ap > S_-1) ap = S_-1;
        tok = (j == 0) ? ids[ap] : 0;   // MASK_TOKEN = 0
        add = inj + (size_t)n * H_;
        if (threadIdx.x == 0) pos[t] = a + j;
    }
    const float* e = embed + (size_t)tok * H_;
    for (int c = threadIdx.x; c < H_; c += blockDim.x)
        h[(size_t)t * H_ + c] = e[c] + (add ? add[c] : 0.f);
}

// ---------------- rmsnorm ----------------
__global__ __launch_bounds__(256) void rmsnorm_kernel(const float* __restrict__ in,
                                                      const float* __restrict__ w,
                                                      float* __restrict__ outp)
{
    int t = blockIdx.x;
    const float* r = in + (size_t)t * H_;
    float ss = 0.f;
    for (int c = threadIdx.x; c < H_; c += 256) { float v = r[c]; ss += v * v; }
    ss = wsum(ss);
    __shared__ float sred[8];
    if ((threadIdx.x & 31) == 0) sred[threadIdx.x >> 5] = ss;
    __syncthreads();
    float tot = 0.f;
#pragma unroll
    for (int i = 0; i < 8; i++) tot += sred[i];
    float inv = rsqrtf(tot * (1.0f / H_) + 1e-6f);
    for (int c = threadIdx.x; c < H_; c += 256)
        outp[(size_t)t * H_ + c] = r[c] * inv * w[c];
}

// ---------------- RoPE on q and k in-place ----------------
__global__ void rope_kernel(float* __restrict__ q, float* __restrict__ k,
                            const int* __restrict__ pos)
{
    int t = blockIdx.x;
    int idx = threadIdx.x;          // 0..511
    int hh = idx >> 6, i = idx & 63;
    int p = pos[t];
    double ang = (double)p * pow(10000.0, -(double)i / 64.0);
    double sd, cd;
    sincos(ang, &sd, &cd);
    float s = (float)sd, c = (float)cd;
    size_t b = (size_t)t * H_ + hh * DH_ + i;
    float x1 = q[b], x2 = q[b + 64];
    q[b]      = x1 * c - x2 * s;
    q[b + 64] = x2 * c + x1 * s;
    x1 = k[b]; x2 = k[b + 64];
    k[b]      = x1 * c - x2 * s;
    k[b + 64] = x2 * c + x1 * s;
}

// ---------------- generic transpose: in[Kd][Nd] -> out[Nd][Kd] ----------------
__global__ void transposeKN_kernel(const float* __restrict__ in, float* __restrict__ out,
                                   int Kd, int Nd)
{
    __shared__ float tile[32][33];
    int n0 = blockIdx.x * 32;
    int k0 = blockIdx.y * 32;
    int x = threadIdx.x, y0 = threadIdx.y;   // block (32, 8)
#pragma unroll
    for (int dy = 0; dy < 32; dy += 8)
        tile[y0 + dy][x] = in[(size_t)(k0 + y0 + dy) * Nd + n0 + x];
    __syncthreads();
#pragma unroll
    for (int dy = 0; dy < 32; dy += 8)
        out[(size_t)(n0 + y0 + dy) * Kd + k0 + x] = tile[x][y0 + dy];
}

// ---------------- attention: 8 queries x 1 head per block, 128 threads ----------------
__global__ __launch_bounds__(128) void attn_kernel(
    const float* __restrict__ q, const float* __restrict__ kT,
    const float* __restrict__ v, const int* __restrict__ anchors,
    float* __restrict__ out)
{
    __shared__ float qs[QB][DH_];
    __shared__ float pbuf[QB][128];
    __shared__ float redm[QB][4];
    __shared__ float reds[QB][4];

    int h   = blockIdx.y;
    int t0  = blockIdx.x * QB;
    int tid = threadIdx.x;
    int w   = tid >> 5, lane = tid & 31;

#pragma unroll
    for (int qi = 0; qi < QB; qi++)
        qs[qi][tid] = q[(size_t)(t0 + qi) * H_ + h * DH_ + tid] * SCALE;
    __syncthreads();

    float m[QB], l[QB], acc[QB];
#pragma unroll
    for (int qi = 0; qi < QB; qi++) { m[qi] = -INFINITY; l[qi] = 0.f; acc[qi] = 0.f; }

    int lo[QB], hi[QB];

    auto proc = [&](int base, int cnt) {
        int k = base + tid;
        bool act = tid < cnt;
        float s[QB];
#pragma unroll
        for (int qi = 0; qi < QB; qi++) s[qi] = -INFINITY;
        if (act) {
#pragma unroll
            for (int qi = 0; qi < QB; qi++) s[qi] = 0.f;
            const float* kp = kT + (size_t)(h * DH_) * T_ + k;
            for (int d = 0; d < DH_; d += 4) {
                float kv0 = kp[(size_t)(d + 0) * T_];
                float kv1 = kp[(size_t)(d + 1) * T_];
                float kv2 = kp[(size_t)(d + 2) * T_];
                float kv3 = kp[(size_t)(d + 3) * T_];
#pragma unroll
                for (int qi = 0; qi < QB; qi++) {
                    float4 qv = *(const float4*)&qs[qi][d];
                    s[qi] += qv.x * kv0 + qv.y * kv1 + qv.z * kv2 + qv.w * kv3;
                }
            }
#pragma unroll
            for (int qi = 0; qi < QB; qi++)
                if (k < lo[qi] || k > hi[qi]) s[qi] = -INFINITY;
        }
        __syncthreads();
#pragma unroll
        for (int qi = 0; qi < QB; qi++) {
            float x = wmax(s[qi]);
            if (lane == 0) redm[qi][w] = x;
        }
        __syncthreads();
        float nm[QB];
#pragma unroll
        for (int qi = 0; qi < QB; qi++) {
            float cm = fmaxf(fmaxf(redm[qi][0], redm[qi][1]), fmaxf(redm[qi][2], redm[qi][3]));
            nm[qi] = fmaxf(m[qi], cm);
            float p = (s[qi] == -INFINITY) ? 0.f : expf(s[qi] - nm[qi]);
            pbuf[qi][tid] = p;
            float sp = wsum(p);
            if (lane == 0) reds[qi][w] = sp;
        }
        __syncthreads();
#pragma unroll
        for (int qi = 0; qi < QB; qi++) {
            float f = (m[qi] == -INFINITY) ? 0.f : expf(m[qi] - nm[qi]);
            float cs = reds[qi][0] + reds[qi][1] + reds[qi][2] + reds[qi][3];
            l[qi] = l[qi] * f + cs;
            acc[qi] *= f;
            m[qi] = nm[qi];
        }
        const float* vp = v + (size_t)base * H_ + h * DH_ + tid;
        for (int j = 0; j < cnt; j += 4) {
            float vv0 = vp[(size_t)(j + 0) * H_];
            float vv1 = vp[(size_t)(j + 1) * H_];
            float vv2 = vp[(size_t)(j + 2) * H_];
            float vv3 = vp[(size_t)(j + 3) * H_];
#pragma unroll
            for (int qi = 0; qi < QB; qi++) {
                float4 pv = *(const float4*)&pbuf[qi][j];
                acc[qi] += pv.x * vv0 + pv.y * vv1 + pv.z * vv2 + pv.w * vv3;
            }
        }
    };

    if (t0 < S_) {
#pragma unroll
        for (int qi = 0; qi < QB; qi++) { lo[qi] = 0; hi[qi] = t0 + qi; }
        for (int base = 0; base <= t0 + QB - 1; base += 128) proc(base, 128);
    } else {
        int nb = (t0 - S_) / BS_;
        int a  = anchors[nb];
        int ws = a - W_ + 1; if (ws < 0) ws = 0;
        int we = a - 1;
#pragma unroll
        for (int qi = 0; qi < QB; qi++) { lo[qi] = ws; hi[qi] = we; }
        for (int base = (ws >> 7) << 7; base <= we; base += 128) proc(base, 128);
        int kb = S_ + nb * BS_;
#pragma unroll
        for (int qi = 0; qi < QB; qi++) { lo[qi] = kb; hi[qi] = kb + BS_ - 1; }
        proc(kb, BS_);
    }

#pragma unroll
    for (int qi = 0; qi < QB; qi++)
        out[(size_t)(t0 + qi) * H_ + h * DH_ + tid] = acc[qi] / l[qi];
}

// ---------------- launch ----------------
extern "C" void kernel_launch(void* const* d_in, const int* in_sizes, int n_in,
                              void* d_out, int out_size)
{
    const int*   ids     = (const int*)  d_in[0];
    const float* hs      = (const float*)d_in[1];
    const int*   anchors = (const int*)  d_in[2];
    // d_in[3] block_keep_mask: all-true by construction; intentionally unused
    const float* embed   = (const float*)d_in[4];
    const float* Wq      = (const float*)d_in[5];
    const float* Wk      = (const float*)d_in[6];
    const float* Wv      = (const float*)d_in[7];
    const float* Wo      = (const float*)d_in[8];
    const float* fcw     = (const float*)d_in[9];
    const float* lmw     = (const float*)d_in[10];
    const float* normw   = (const float*)d_in[11];

    float *h, *x, *q, *k, *v, *kT, *ao, *h2, *inj, *lmwT, *WqT, *WkT, *WvT, *WoT;
    int* pos;
    cudaGetSymbolAddress((void**)&h,    g_h);
    cudaGetSymbolAddress((void**)&x,    g_x);
    cudaGetSymbolAddress((void**)&q,    g_q);
    cudaGetSymbolAddress((void**)&k,    g_k);
    cudaGetSymbolAddress((void**)&v,    g_v);
    cudaGetSymbolAddress((void**)&kT,   g_kT);
    cudaGetSymbolAddress((void**)&ao,   g_ao);
    cudaGetSymbolAddress((void**)&h2,   g_h2);
    cudaGetSymbolAddress((void**)&inj,  g_inj);
    cudaGetSymbolAddress((void**)&pos,  g_pos);
    cudaGetSymbolAddress((void**)&lmwT, g_lmwT);
    cudaGetSymbolAddress((void**)&WqT,  g_WqT);
    cudaGetSymbolAddress((void**)&WkT,  g_WkT);
    cudaGetSymbolAddress((void**)&WvT,  g_WvT);
    cudaGetSymbolAddress((void**)&WoT,  g_WoT);

    cudaFuncSetAttribute(hgemm_kernel, cudaFuncAttributeMaxDynamicSharedMemorySize, HS_TOTAL);

    // weight transposes ([K][N] -> [N][K])
    dim3 tb(32, 8);
    transposeKN_kernel<<<dim3(H_ / 32, H_ / 32), tb>>>(Wq,  WqT,  H_, H_);
    transposeKN_kernel<<<dim3(H_ / 32, H_ / 32), tb>>>(Wk,  WkT,  H_, H_);
    transposeKN_kernel<<<dim3(H_ / 32, H_ / 32), tb>>>(Wv,  WvT,  H_, H_);
    transposeKN_kernel<<<dim3(H_ / 32, H_ / 32), tb>>>(Wo,  WoT,  H_, H_);
    transposeKN_kernel<<<dim3(V_ / 32, H_ / 32), tb>>>(lmw, lmwT, H_, V_);

    inj_kernel<<<dim3(N_, H_ / 128), 128>>>(hs, anchors, fcw, inj);
    build_h_kernel<<<T_, 256>>>(ids, anchors, embed, inj, h, pos);
    rmsnorm_kernel<<<T_, 256>>>(h, normw, x);

    dim3 g1(H_ / 128, T_ / 128);
    hgemm_kernel<<<g1, 256, HS_TOTAL>>>(T_, H_, H_, x, WqT, q, nullptr);
    hgemm_kernel<<<g1, 256, HS_TOTAL>>>(T_, H_, H_, x, WkT, k, nullptr);
    hgemm_kernel<<<g1, 256, HS_TOTAL>>>(T_, H_, H_, x, WvT, v, nullptr);

    rope_kernel<<<T_, 512>>>(q, k, pos);
    transposeKN_kernel<<<dim3(H_ / 32, T_ / 32), tb>>>(k, kT, T_, H_);

    attn_kernel<<<dim3(T_ / QB, NH_), 128>>>(q, kT, v, anchors, ao);

    hgemm_kernel<<<g1, 256, HS_TOTAL>>>(T_, H_, H_, ao, WoT, h2, h);   // residual fused
    rmsnorm_kernel<<<T_, 256>>>(h2, normw, x);

    hgemm_kernel<<<dim3(V_ / 128, T_ / 128), 256, HS_TOTAL>>>(T_, V_, H_, x, lmwT, (float*)d_out, nullptr);
}

// round 6
// speedup vs baseline: 1.8708x; 1.0125x over previous
#include <cuda_runtime.h>
#include <cuda_bf16.h>
#include <math.h>
#include <stdint.h>

#define S_  2048
#define N_  64
#define BS_ 16
#define W_  512
#define NH_ 8
#define H_  1024
#define V_  32000
#define DH_ 128
#define T_  3072
#define QB  8
#define SCALE 0.08838834764831845f  // 1/sqrt(128)

// ---------------- scratch (device globals; no allocation) ----------------
__device__ float g_h [T_*H_];
__device__ float g_x [T_*H_];
__device__ float g_q [T_*H_];
__device__ float g_k [T_*H_];
__device__ float g_v [T_*H_];
__device__ float g_kT[T_*H_];
__device__ float g_ao[T_*H_];
__device__ float g_h2[T_*H_];
__device__ float g_inj[N_*H_];
__device__ int   g_pos[T_];

// ---------------- helpers ----------------
__device__ __forceinline__ float wmax(float v){
#pragma unroll
    for (int o=16;o>0;o>>=1) v = fmaxf(v, __shfl_xor_sync(0xffffffffu, v, o));
    return v;
}
__device__ __forceinline__ float wsum(float v){
#pragma unroll
    for (int o=16;o>0;o>>=1) v += __shfl_xor_sync(0xffffffffu, v, o);
    return v;
}
__device__ __forceinline__ uint32_t smem_u32(const void* p){
    uint32_t a;
    asm("{ .reg .u64 t; cvta.to.shared.u64 t, %1; cvt.u32.u64 %0, t; }" : "=r"(a) : "l"(p));
    return a;
}
__device__ __forceinline__ void ldsm4(uint32_t& r0, uint32_t& r1, uint32_t& r2, uint32_t& r3,
                                      uint32_t addr){
    asm volatile("ldmatrix.sync.aligned.m8n8.x4.shared.b16 {%0,%1,%2,%3}, [%4];"
                 : "=r"(r0), "=r"(r1), "=r"(r2), "=r"(r3) : "r"(addr));
}
__device__ __forceinline__ void ldsm4t(uint32_t& r0, uint32_t& r1, uint32_t& r2, uint32_t& r3,
                                       uint32_t addr){
    asm volatile("ldmatrix.sync.aligned.m8n8.x4.trans.shared.b16 {%0,%1,%2,%3}, [%4];"
                 : "=r"(r0), "=r"(r1), "=r"(r2), "=r"(r3) : "r"(addr));
}
__device__ __forceinline__ void mma_bf16(float* c, const uint32_t* a, uint32_t b0, uint32_t b1){
    asm volatile("mma.sync.aligned.m16n8k16.row.col.f32.bf16.bf16.f32 "
                 "{%0,%1,%2,%3}, {%4,%5,%6,%7}, {%8,%9}, {%0,%1,%2,%3};"
                 : "+f"(c[0]), "+f"(c[1]), "+f"(c[2]), "+f"(c[3])
                 : "r"(a[0]), "r"(a[1]), "r"(a[2]), "r"(a[3]), "r"(b0), "r"(b1));
}
__device__ __forceinline__ void split_store(char* hi, char* lo, float4 v){
    __nv_bfloat16 hx = __float2bfloat16(v.x), hy = __float2bfloat16(v.y);
    __nv_bfloat16 hz = __float2bfloat16(v.z), hw = __float2bfloat16(v.w);
    __nv_bfloat16 lx = __float2bfloat16(v.x - __bfloat162float(hx));
    __nv_bfloat16 ly = __float2bfloat16(v.y - __bfloat162float(hy));
    __nv_bfloat16 lz = __float2bfloat16(v.z - __bfloat162float(hz));
    __nv_bfloat16 lw = __float2bfloat16(v.w - __bfloat162float(hw));
    __nv_bfloat162 h01 = __halves2bfloat162(hx, hy);
    __nv_bfloat162 h23 = __halves2bfloat162(hz, hw);
    __nv_bfloat162 l01 = __halves2bfloat162(lx, ly);
    __nv_bfloat162 l23 = __halves2bfloat162(lz, lw);
    *(uint32_t*)(hi + 0) = *(uint32_t*)&h01;
    *(uint32_t*)(hi + 4) = *(uint32_t*)&h23;
    *(uint32_t*)(lo + 0) = *(uint32_t*)&l01;
    *(uint32_t*)(lo + 4) = *(uint32_t*)&l23;
}

// ================ bf16-split tensor-core GEMM ================
// C[M,Nc] = A[M,K] @ B[K,Nc] (+ D).  A [M][K], B [K][Nc] fp32 row-major (native layouts).
// CTA 128x128, K-chunk 32, double-buffered smem, 8 warps of 64x32.
// A smem: [128][LDSR] bf16 (k-contig rows), non-trans ldmatrix.
// B smem: [32][LDSB] bf16 (n-contig rows), TRANS ldmatrix -> same col-B fragment.
#define LDSR 40
#define LDSB 136
#define HS_AHI 0
#define HS_ALO 10240
#define HS_BHI 20480
#define HS_BLO 29184
#define HS_STAGE 37888
#define HS_TOTAL (2*HS_STAGE)          // 75776 B

__global__ __launch_bounds__(256) void hgemm_kernel(
    int M, int Nc, int K,
    const float* __restrict__ A, const float* __restrict__ B,
    float* __restrict__ C, const float* __restrict__ D)
{
    extern __shared__ char sm[];
    uint32_t sb = smem_u32(sm);
    int tid  = threadIdx.x, lane = tid & 31, wid = tid >> 5;
    int crow = blockIdx.y * 128, ccol = blockIdx.x * 128;
    int wm   = (wid & 1) * 64,  wn   = (wid >> 1) * 32;

    float acc[4][4][4];
#pragma unroll
    for (int i = 0; i < 4; i++)
#pragma unroll
        for (int j = 0; j < 4; j++)
#pragma unroll
            for (int r = 0; r < 4; r++) acc[i][j][r] = 0.f;

    // A loads: 2 threads per row; thread's float4s at col (tid&1)*4 + i*8 (full sectors per warp)
    int lrow = tid >> 1, lc = (tid & 1) * 4;
    const float* Ag = A + (size_t)(crow + lrow) * K + lc;
    // B loads: thread row kr = tid>>3, float4s at col (tid&7)*4 + i*32
    int kr = tid >> 3, bc = (tid & 7) * 4;
    const float* Bg = B + (size_t)kr * Nc + ccol + bc;

    // ldmatrix byte offsets
    uint32_t a_off = ((wm + (lane & 15)) * LDSR + (lane >> 4) * 8) * 2;
    uint32_t b_off = (uint32_t)(((((lane >> 3) & 1) * 8 + (lane & 7)) * LDSB
                                 + wn + (lane >> 4) * 8) * 2);
    uint32_t sA = (uint32_t)((lrow * LDSR + lc) * 2);
    uint32_t sB = (uint32_t)((kr * LDSB + bc) * 2);

    int kq = K / 32;
    float4 pa[4], pb[4];
#pragma unroll
    for (int i = 0; i < 4; i++) {
        pa[i] = *(const float4*)(Ag + i * 8);
        pb[i] = *(const float4*)(Bg + i * 32);
    }
    {
        char* ah = sm + HS_AHI + sA;
        char* bh = sm + HS_BHI + sB;
#pragma unroll
        for (int i = 0; i < 4; i++) {
            split_store(ah + i * 16, ah + (HS_ALO - HS_AHI) + i * 16, pa[i]);
            split_store(bh + i * 64, bh + (HS_BLO - HS_BHI) + i * 64, pb[i]);
        }
    }
    __syncthreads();

    for (int ch = 0; ch < kq; ch++) {
        int st = ch & 1;
        if (ch + 1 < kq) {
#pragma unroll
            for (int i = 0; i < 4; i++) {
                pa[i] = *(const float4*)(Ag + (ch + 1) * 32 + i * 8);
                pb[i] = *(const float4*)(Bg + (size_t)(ch + 1) * 32 * Nc + i * 32);
            }
        }
        uint32_t base = sb + st * HS_STAGE;
#pragma unroll
        for (int ks = 0; ks < 2; ks++) {
            uint32_t ah4[4][4], al4[4][4], bh4[2][4], bl4[2][4];
#pragma unroll
            for (int mi = 0; mi < 4; mi++) {
                uint32_t adr = base + HS_AHI + a_off + mi * (16 * LDSR * 2) + ks * 32;
                ldsm4(ah4[mi][0], ah4[mi][1], ah4[mi][2], ah4[mi][3], adr);
                ldsm4(al4[mi][0], al4[mi][1], al4[mi][2], al4[mi][3], adr + (HS_ALO - HS_AHI));
            }
#pragma unroll
            for (int p = 0; p < 2; p++) {
                uint32_t adr = base + HS_BHI + b_off + ks * (16 * LDSB * 2) + p * 32;
                ldsm4t(bh4[p][0], bh4[p][1], bh4[p][2], bh4[p][3], adr);
                ldsm4t(bl4[p][0], bl4[p][1], bl4[p][2], bl4[p][3], adr + (HS_BLO - HS_BHI));
            }
#pragma unroll
            for (int mi = 0; mi < 4; mi++)
#pragma unroll
                for (int ni = 0; ni < 4; ni++) {
                    uint32_t b0h = bh4[ni >> 1][(ni & 1) * 2], b1h = bh4[ni >> 1][(ni & 1) * 2 + 1];
                    uint32_t b0l = bl4[ni >> 1][(ni & 1) * 2], b1l = bl4[ni >> 1][(ni & 1) * 2 + 1];
                    mma_bf16(acc[mi][ni], ah4[mi], b0h, b1h);
                    mma_bf16(acc[mi][ni], ah4[mi], b0l, b1l);
                    mma_bf16(acc[mi][ni], al4[mi], b0h, b1h);
                }
        }
        if (ch + 1 < kq) {
            char* dst = sm + ((ch + 1) & 1) * HS_STAGE;
            char* ah = dst + HS_AHI + sA;
            char* bh = dst + HS_BHI + sB;
#pragma unroll
            for (int i = 0; i < 4; i++) {
                split_store(ah + i * 16, ah + (HS_ALO - HS_AHI) + i * 16, pa[i]);
                split_store(bh + i * 64, bh + (HS_BLO - HS_BHI) + i * 64, pb[i]);
            }
        }
        __syncthreads();
    }

    // epilogue
#pragma unroll
    for (int mi = 0; mi < 4; mi++)
#pragma unroll
        for (int ni = 0; ni < 4; ni++) {
            size_t r0 = (size_t)(crow + wm + mi * 16 + (lane >> 2));
            int    cc = ccol + wn + ni * 8 + (lane & 3) * 2;
            float2 v0 = make_float2(acc[mi][ni][0], acc[mi][ni][1]);
            float2 v1 = make_float2(acc[mi][ni][2], acc[mi][ni][3]);
            if (D) {
                const float2 d0 = *(const float2*)(D + r0 * Nc + cc);
                const float2 d1 = *(const float2*)(D + (r0 + 8) * Nc + cc);
                v0.x += d0.x; v0.y += d0.y; v1.x += d1.x; v1.y += d1.y;
            }
            *(float2*)(C + r0 * Nc + cc)       = v0;
            *(float2*)(C + (r0 + 8) * Nc + cc) = v1;
        }
}

// ---------------- inj[n] = concat(hs0[ctx], hs1[ctx]) @ fc_w ----------------
__global__ void inj_kernel(const float* __restrict__ hs, const int* __restrict__ anchors,
                           const float* __restrict__ fcw, float* __restrict__ inj)
{
    int n = blockIdx.x;
    int c = blockIdx.y * 128 + threadIdx.x;
    int a = anchors[n];
    int ctx = a - 1; if (ctx < 0) ctx = 0;
    const float* h0 = hs + (size_t)ctx * H_;
    const float* h1 = hs + (size_t)S_ * H_ + (size_t)ctx * H_;
    float acc = 0.f;
    for (int k = 0; k < H_; k++) acc += h0[k] * fcw[(size_t)k * H_ + c];
    for (int k = 0; k < H_; k++) acc += h1[k] * fcw[(size_t)(H_ + k) * H_ + c];
    inj[(size_t)n * H_ + c] = acc;
}

// ---------------- h = [embed[ids]; embed[blk_ids] + inj], pos ----------------
__global__ void build_h_kernel(const int* __restrict__ ids, const int* __restrict__ anchors,
                               const float* __restrict__ embed, const float* __restrict__ inj,
                               float* __restrict__ h, int* __restrict__ pos)
{
    int t = blockIdx.x;
    int tok;
    const float* add = nullptr;
    if (t < S_) {
        tok = ids[t];
        if (threadIdx.x == 0) pos[t] = t;
    } else {
        int n = (t - S_) / BS_, j = (t - S_) % BS_;
        int a = anchors[n];
        int ap = a; if (ap < 0) ap = 0; if (ap > S_-1) ap = S_-1;
        tok = (j == 0) ? ids[ap] : 0;   // MASK_TOKEN = 0
        add = inj + (size_t)n * H_;
        if (threadIdx.x == 0) pos[t] = a + j;
    }
    const float* e = embed + (size_t)tok * H_;
    for (int c = threadIdx.x; c < H_; c += blockDim.x)
        h[(size_t)t * H_ + c] = e[c] + (add ? add[c] : 0.f);
}

// ---------------- rmsnorm ----------------
__global__ __launch_bounds__(256) void rmsnorm_kernel(const float* __restrict__ in,
                                                      const float* __restrict__ w,
                                                      float* __restrict__ outp)
{
    int t = blockIdx.x;
    const float* r = in + (size_t)t * H_;
    float ss = 0.f;
    for (int c = threadIdx.x; c < H_; c += 256) { float v = r[c]; ss += v * v; }
    ss = wsum(ss);
    __shared__ float sred[8];
    if ((threadIdx.x & 31) == 0) sred[threadIdx.x >> 5] = ss;
    __syncthreads();
    float tot = 0.f;
#pragma unroll
    for (int i = 0; i < 8; i++) tot += sred[i];
    float inv = rsqrtf(tot * (1.0f / H_) + 1e-6f);
    for (int c = threadIdx.x; c < H_; c += 256)
        outp[(size_t)t * H_ + c] = r[c] * inv * w[c];
}

// ---------------- RoPE on q and k in-place ----------------
__global__ void rope_kernel(float* __restrict__ q, float* __restrict__ k,
                            const int* __restrict__ pos)
{
    int t = blockIdx.x;
    int idx = threadIdx.x;          // 0..511
    int hh = idx >> 6, i = idx & 63;
    int p = pos[t];
    double ang = (double)p * pow(10000.0, -(double)i / 64.0);
    double sd, cd;
    sincos(ang, &sd, &cd);
    float s = (float)sd, c = (float)cd;
    size_t b = (size_t)t * H_ + hh * DH_ + i;
    float x1 = q[b], x2 = q[b + 64];
    q[b]      = x1 * c - x2 * s;
    q[b + 64] = x2 * c + x1 * s;
    x1 = k[b]; x2 = k[b + 64];
    k[b]      = x1 * c - x2 * s;
    k[b + 64] = x2 * c + x1 * s;
}

// ---------------- generic transpose: in[Kd][Nd] -> out[Nd][Kd] ----------------
__global__ void transposeKN_kernel(const float* __restrict__ in, float* __restrict__ out,
                                   int Kd, int Nd)
{
    __shared__ float tile[32][33];
    int n0 = blockIdx.x * 32;
    int k0 = blockIdx.y * 32;
    int x = threadIdx.x, y0 = threadIdx.y;   // block (32, 8)
#pragma unroll
    for (int dy = 0; dy < 32; dy += 8)
        tile[y0 + dy][x] = in[(size_t)(k0 + y0 + dy) * Nd + n0 + x];
    __syncthreads();
#pragma unroll
    for (int dy = 0; dy < 32; dy += 8)
        out[(size_t)(n0 + y0 + dy) * Kd + k0 + x] = tile[x][y0 + dy];
}

// ---------------- attention: 8 queries x 1 head per block, 128 threads ----------------
__global__ __launch_bounds__(128) void attn_kernel(
    const float* __restrict__ q, const float* __restrict__ kT,
    const float* __restrict__ v, const int* __restrict__ anchors,
    float* __restrict__ out)
{
    __shared__ float qs[QB][DH_];
    __shared__ float pbuf[QB][128];
    __shared__ float redm[QB][4];
    __shared__ float reds[QB][4];

    int h   = blockIdx.y;
    int t0  = blockIdx.x * QB;
    int tid = threadIdx.x;
    int w   = tid >> 5, lane = tid & 31;

#pragma unroll
    for (int qi = 0; qi < QB; qi++)
        qs[qi][tid] = q[(size_t)(t0 + qi) * H_ + h * DH_ + tid] * SCALE;
    __syncthreads();

    float m[QB], l[QB], acc[QB];
#pragma unroll
    for (int qi = 0; qi < QB; qi++) { m[qi] = -INFINITY; l[qi] = 0.f; acc[qi] = 0.f; }

    int lo[QB], hi[QB];

    auto proc = [&](int base, int cnt) {
        int k = base + tid;
        bool act = tid < cnt;
        float s[QB];
#pragma unroll
        for (int qi = 0; qi < QB; qi++) s[qi] = -INFINITY;
        if (act) {
#pragma unroll
            for (int qi = 0; qi < QB; qi++) s[qi] = 0.f;
            const float* kp = kT + (size_t)(h * DH_) * T_ + k;
            for (int d = 0; d < DH_; d += 4) {
                float kv0 = kp[(size_t)(d + 0) * T_];
                float kv1 = kp[(size_t)(d + 1) * T_];
                float kv2 = kp[(size_t)(d + 2) * T_];
                float kv3 = kp[(size_t)(d + 3) * T_];
#pragma unroll
                for (int qi = 0; qi < QB; qi++) {
                    float4 qv = *(const float4*)&qs[qi][d];
                    s[qi] += qv.x * kv0 + qv.y * kv1 + qv.z * kv2 + qv.w * kv3;
                }
            }
#pragma unroll
            for (int qi = 0; qi < QB; qi++)
                if (k < lo[qi] || k > hi[qi]) s[qi] = -INFINITY;
        }
        __syncthreads();
#pragma unroll
        for (int qi = 0; qi < QB; qi++) {
            float x = wmax(s[qi]);
            if (lane == 0) redm[qi][w] = x;
        }
        __syncthreads();
        float nm[QB];
#pragma unroll
        for (int qi = 0; qi < QB; qi++) {
            float cm = fmaxf(fmaxf(redm[qi][0], redm[qi][1]), fmaxf(redm[qi][2], redm[qi][3]));
            nm[qi] = fmaxf(m[qi], cm);
            float p = (s[qi] == -INFINITY) ? 0.f : expf(s[qi] - nm[qi]);
            pbuf[qi][tid] = p;
            float sp = wsum(p);
            if (lane == 0) reds[qi][w] = sp;
        }
        __syncthreads();
#pragma unroll
        for (int qi = 0; qi < QB; qi++) {
            float f = (m[qi] == -INFINITY) ? 0.f : expf(m[qi] - nm[qi]);
            float cs = reds[qi][0] + reds[qi][1] + reds[qi][2] + reds[qi][3];
            l[qi] = l[qi] * f + cs;
            acc[qi] *= f;
            m[qi] = nm[qi];
        }
        const float* vp = v + (size_t)base * H_ + h * DH_ + tid;
        for (int j = 0; j < cnt; j += 4) {
            float vv0 = vp[(size_t)(j + 0) * H_];
            float vv1 = vp[(size_t)(j + 1) * H_];
            float vv2 = vp[(size_t)(j + 2) * H_];
            float vv3 = vp[(size_t)(j + 3) * H_];
#pragma unroll
            for (int qi = 0; qi < QB; qi++) {
                float4 pv = *(const float4*)&pbuf[qi][j];
                acc[qi] += pv.x * vv0 + pv.y * vv1 + pv.z * vv2 + pv.w * vv3;
            }
        }
    };

    if (t0 < S_) {
#pragma unroll
        for (int qi = 0; qi < QB; qi++) { lo[qi] = 0; hi[qi] = t0 + qi; }
        for (int base = 0; base <= t0 + QB - 1; base += 128) proc(base, 128);
    } else {
        int nb = (t0 - S_) / BS_;
        int a  = anchors[nb];
        int ws = a - W_ + 1; if (ws < 0) ws = 0;
        int we = a - 1;
#pragma unroll
        for (int qi = 0; qi < QB; qi++) { lo[qi] = ws; hi[qi] = we; }
        for (int base = (ws >> 7) << 7; base <= we; base += 128) proc(base, 128);
        int kb = S_ + nb * BS_;
#pragma unroll
        for (int qi = 0; qi < QB; qi++) { lo[qi] = kb; hi[qi] = kb + BS_ - 1; }
        proc(kb, BS_);
    }

#pragma unroll
    for (int qi = 0; qi < QB; qi++)
        out[(size_t)(t0 + qi) * H_ + h * DH_ + tid] = acc[qi] / l[qi];
}

// ---------------- launch ----------------
extern "C" void kernel_launch(void* const* d_in, const int* in_sizes, int n_in,
                              void* d_out, int out_size)
{
    const int*   ids     = (const int*)  d_in[0];
    const float* hs      = (const float*)d_in[1];
    const int*   anchors = (const int*)  d_in[2];
    // d_in[3] block_keep_mask: all-true by construction; intentionally unused
    const float* embed   = (const float*)d_in[4];
    const float* Wq      = (const float*)d_in[5];
    const float* Wk      = (const float*)d_in[6];
    const float* Wv      = (const float*)d_in[7];
    const float* Wo      = (const float*)d_in[8];
    const float* fcw     = (const float*)d_in[9];
    const float* lmw     = (const float*)d_in[10];
    const float* normw   = (const float*)d_in[11];

    float *h, *x, *q, *k, *v, *kT, *ao, *h2, *inj;
    int* pos;
    cudaGetSymbolAddress((void**)&h,    g_h);
    cudaGetSymbolAddress((void**)&x,    g_x);
    cudaGetSymbolAddress((void**)&q,    g_q);
    cudaGetSymbolAddress((void**)&k,    g_k);
    cudaGetSymbolAddress((void**)&v,    g_v);
    cudaGetSymbolAddress((void**)&kT,   g_kT);
    cudaGetSymbolAddress((void**)&ao,   g_ao);
    cudaGetSymbolAddress((void**)&h2,   g_h2);
    cudaGetSymbolAddress((void**)&inj,  g_inj);
    cudaGetSymbolAddress((void**)&pos,  g_pos);

    cudaFuncSetAttribute(hgemm_kernel, cudaFuncAttributeMaxDynamicSharedMemorySize, HS_TOTAL);

    inj_kernel<<<dim3(N_, H_ / 128), 128>>>(hs, anchors, fcw, inj);
    build_h_kernel<<<T_, 256>>>(ids, anchors, embed, inj, h, pos);
    rmsnorm_kernel<<<T_, 256>>>(h, normw, x);

    dim3 g1(H_ / 128, T_ / 128);
    hgemm_kernel<<<g1, 256, HS_TOTAL>>>(T_, H_, H_, x, Wq, q, nullptr);
    hgemm_kernel<<<g1, 256, HS_TOTAL>>>(T_, H_, H_, x, Wk, k, nullptr);
    hgemm_kernel<<<g1, 256, HS_TOTAL>>>(T_, H_, H_, x, Wv, v, nullptr);

    rope_kernel<<<T_, 512>>>(q, k, pos);
    transposeKN_kernel<<<dim3(H_ / 32, T_ / 32), dim3(32, 8)>>>(k, kT, T_, H_);

    attn_kernel<<<dim3(T_ / QB, NH_), 128>>>(q, kT, v, anchors, ao);

    hgemm_kernel<<<g1, 256, HS_TOTAL>>>(T_, H_, H_, ao, Wo, h2, h);   // residual fused
    rmsnorm_kernel<<<T_, 256>>>(h2, normw, x);

    hgemm_kernel<<<dim3(V_ / 128, T_ / 128), 256, HS_TOTAL>>>(T_, V_, H_, x, lmw, (float*)d_out, nullptr);
}

// round 7
// speedup vs baseline: 2.2204x; 1.1868x over previous
#include <cuda_runtime.h>
#include <cuda_bf16.h>
#include <math.h>
#include <stdint.h>

#define S_  2048
#define N_  64
#define BS_ 16
#define W_  512
#define NH_ 8
#define H_  1024
#define V_  32000
#define DH_ 128
#define T_  3072
#define QB  8
#define SCALE 0.08838834764831845f  // 1/sqrt(128)

// ---------------- scratch (device globals; no allocation) ----------------
__device__ float g_h [T_*H_];
__device__ float g_q [T_*H_];
__device__ float g_k [T_*H_];
__device__ float g_v [T_*H_];
__device__ float g_kT[T_*H_];
__device__ float g_h2[T_*H_];
__device__ float g_inj[N_*H_];
__device__ int   g_pos[T_];
__device__ __nv_bfloat16 g_xhi[T_*H_], g_xlo[T_*H_];
__device__ __nv_bfloat16 g_aohi[T_*H_], g_aolo[T_*H_];
__device__ __nv_bfloat16 g_wqhi[H_*H_], g_wqlo[H_*H_];
__device__ __nv_bfloat16 g_wkhi[H_*H_], g_wklo[H_*H_];
__device__ __nv_bfloat16 g_wvhi[H_*H_], g_wvlo[H_*H_];
__device__ __nv_bfloat16 g_wohi[H_*H_], g_wolo[H_*H_];
__device__ __nv_bfloat16 g_lmhi[(size_t)V_*H_], g_lmlo[(size_t)V_*H_];

// ---------------- helpers ----------------
__device__ __forceinline__ float wmax(float v){
#pragma unroll
    for (int o=16;o>0;o>>=1) v = fmaxf(v, __shfl_xor_sync(0xffffffffu, v, o));
    return v;
}
__device__ __forceinline__ float wsum(float v){
#pragma unroll
    for (int o=16;o>0;o>>=1) v += __shfl_xor_sync(0xffffffffu, v, o);
    return v;
}
__device__ __forceinline__ uint32_t smem_u32(const void* p){
    uint32_t a;
    asm("{ .reg .u64 t; cvta.to.shared.u64 t, %1; cvt.u32.u64 %0, t; }" : "=r"(a) : "l"(p));
    return a;
}
__device__ __forceinline__ void ldsm4(uint32_t& r0, uint32_t& r1, uint32_t& r2, uint32_t& r3,
                                      uint32_t addr){
    asm volatile("ldmatrix.sync.aligned.m8n8.x4.shared.b16 {%0,%1,%2,%3}, [%4];"
                 : "=r"(r0), "=r"(r1), "=r"(r2), "=r"(r3) : "r"(addr));
}
__device__ __forceinline__ void ldsm4t(uint32_t& r0, uint32_t& r1, uint32_t& r2, uint32_t& r3,
                                       uint32_t addr){
    asm volatile("ldmatrix.sync.aligned.m8n8.x4.trans.shared.b16 {%0,%1,%2,%3}, [%4];"
                 : "=r"(r0), "=r"(r1), "=r"(r2), "=r"(r3) : "r"(addr));
}
__device__ __forceinline__ void mma_bf16(float* c, const uint32_t* a, uint32_t b0, uint32_t b1){
    asm volatile("mma.sync.aligned.m16n8k16.row.col.f32.bf16.bf16.f32 "
                 "{%0,%1,%2,%3}, {%4,%5,%6,%7}, {%8,%9}, {%0,%1,%2,%3};"
                 : "+f"(c[0]), "+f"(c[1]), "+f"(c[2]), "+f"(c[3])
                 : "r"(a[0]), "r"(a[1]), "r"(a[2]), "r"(a[3]), "r"(b0), "r"(b1));
}
__device__ __forceinline__ void cp16(uint32_t saddr, const void* g){
    asm volatile("cp.async.cg.shared.global [%0], [%1], 16;"
                 :: "r"(saddr), "l"(__cvta_generic_to_global(g)));
}
__device__ __forceinline__ void cp_commit(){ asm volatile("cp.async.commit_group;" ::: "memory"); }
template<int Nn> __device__ __forceinline__ void cp_wait(){
    asm volatile("cp.async.wait_group %0;" :: "n"(Nn) : "memory");
}

// ================ bf16-split tensor-core GEMM (pre-split operands) ================
// C[M,Nc] = (Ahi+Alo)[M,K] @ (Bhi+Blo)[K,Nc] (+ D), dropping AlBl.
// CTA 128x128, K-chunk 32, 3-stage cp.async pipeline, 8 warps of 64x32, 2 CTAs/SM.
#define LDSR 40
#define LDSB 136
#define ST_AHI 0
#define ST_ALO 10240
#define ST_BHI 20480
#define ST_BLO 29184
#define ST_SIZE 37888
#define NSTAGE 3
#define HS_TOTAL (NSTAGE*ST_SIZE)      // 113664 B

__global__ __launch_bounds__(256, 2) void hgemm_kernel(
    int M, int Nc, int K,
    const __nv_bfloat16* __restrict__ Ahi, const __nv_bfloat16* __restrict__ Alo,
    const __nv_bfloat16* __restrict__ Bhi, const __nv_bfloat16* __restrict__ Blo,
    float* __restrict__ C, const float* __restrict__ D)
{
    extern __shared__ char sm[];
    uint32_t sb = smem_u32(sm);
    int tid  = threadIdx.x, lane = tid & 31, wid = tid >> 5;
    int crow = blockIdx.y * 128, ccol = blockIdx.x * 128;
    int wm   = (wid & 1) * 64,  wn   = (wid >> 1) * 32;

    float acc[4][4][4];
#pragma unroll
    for (int i = 0; i < 4; i++)
#pragma unroll
        for (int j = 0; j < 4; j++)
#pragma unroll
            for (int r = 0; r < 4; r++) acc[i][j][r] = 0.f;

    uint32_t a_off = ((wm + (lane & 15)) * LDSR + (lane >> 4) * 8) * 2;
    uint32_t b_off = (uint32_t)(((((lane >> 3) & 1) * 8 + (lane & 7)) * LDSB
                                 + wn + (lane >> 4) * 8) * 2);
    int kq = K / 32;

    auto issue = [&](int ch){
        uint32_t st = sb + (ch % NSTAGE) * ST_SIZE;
        int kb = ch * 32;
#pragma unroll
        for (int r = 0; r < 2; r++) {
            int seg = tid + r * 256;
            int ar = seg >> 2, ac = (seg & 3) * 8;
            size_t ga = (size_t)(crow + ar) * K + kb + ac;
            uint32_t sa = st + ST_AHI + (uint32_t)(ar * LDSR + ac) * 2;
            cp16(sa, Ahi + ga);
            cp16(sa + (ST_ALO - ST_AHI), Alo + ga);
            int br = seg >> 4, bcx = (seg & 15) * 8;
            size_t gb = (size_t)(kb + br) * Nc + ccol + bcx;
            uint32_t sbo = st + ST_BHI + (uint32_t)(br * LDSB + bcx) * 2;
            cp16(sbo, Bhi + gb);
            cp16(sbo + (ST_BLO - ST_BHI), Blo + gb);
        }
    };

    for (int s = 0; s < NSTAGE - 1; s++) { issue(s); cp_commit(); }

    for (int ch = 0; ch < kq; ch++) {
        if (ch + NSTAGE - 1 < kq) issue(ch + NSTAGE - 1);
        cp_commit();
        cp_wait<NSTAGE - 1>();
        __syncthreads();

        uint32_t base = sb + (ch % NSTAGE) * ST_SIZE;
#pragma unroll
        for (int ks = 0; ks < 2; ks++) {
            uint32_t bh4[2][4], bl4[2][4];
#pragma unroll
            for (int p = 0; p < 2; p++) {
                uint32_t adr = base + ST_BHI + b_off + ks * (16 * LDSB * 2) + p * 32;
                ldsm4t(bh4[p][0], bh4[p][1], bh4[p][2], bh4[p][3], adr);
                ldsm4t(bl4[p][0], bl4[p][1], bl4[p][2], bl4[p][3], adr + (ST_BLO - ST_BHI));
            }
#pragma unroll
            for (int mi = 0; mi < 4; mi++) {
                uint32_t ah[4], al[4];
                uint32_t adr = base + ST_AHI + a_off + mi * (16 * LDSR * 2) + ks * 32;
                ldsm4(ah[0], ah[1], ah[2], ah[3], adr);
                ldsm4(al[0], al[1], al[2], al[3], adr + (ST_ALO - ST_AHI));
#pragma unroll
                for (int ni = 0; ni < 4; ni++) {
                    uint32_t b0h = bh4[ni >> 1][(ni & 1) * 2], b1h = bh4[ni >> 1][(ni & 1) * 2 + 1];
                    uint32_t b0l = bl4[ni >> 1][(ni & 1) * 2], b1l = bl4[ni >> 1][(ni & 1) * 2 + 1];
                    mma_bf16(acc[mi][ni], ah, b0h, b1h);
                    mma_bf16(acc[mi][ni], ah, b0l, b1l);
                    mma_bf16(acc[mi][ni], al, b0h, b1h);
                }
            }
        }
        __syncthreads();
    }

    // epilogue
#pragma unroll
    for (int mi = 0; mi < 4; mi++)
#pragma unroll
        for (int ni = 0; ni < 4; ni++) {
            size_t r0 = (size_t)(crow + wm + mi * 16 + (lane >> 2));
            int    cc = ccol + wn + ni * 8 + (lane & 3) * 2;
            float2 v0 = make_float2(acc[mi][ni][0], acc[mi][ni][1]);
            float2 v1 = make_float2(acc[mi][ni][2], acc[mi][ni][3]);
            if (D) {
                const float2 d0 = *(const float2*)(D + r0 * Nc + cc);
                const float2 d1 = *(const float2*)(D + (r0 + 8) * Nc + cc);
                v0.x += d0.x; v0.y += d0.y; v1.x += d1.x; v1.y += d1.y;
            }
            *(float2*)(C + r0 * Nc + cc)       = v0;
            *(float2*)(C + (r0 + 8) * Nc + cc) = v1;
        }
}

// ---------------- split fp32 -> bf16 hi/lo ----------------
__global__ __launch_bounds__(256) void split_kernel(const float* __restrict__ in,
                                                    __nv_bfloat16* __restrict__ hi,
                                                    __nv_bfloat16* __restrict__ lo)
{
    size_t i = ((size_t)blockIdx.x * 256 + threadIdx.x) * 4;
    float4 v = *(const float4*)(in + i);
    __nv_bfloat16 hx = __float2bfloat16(v.x), hy = __float2bfloat16(v.y);
    __nv_bfloat16 hz = __float2bfloat16(v.z), hw = __float2bfloat16(v.w);
    __nv_bfloat162 h01 = __halves2bfloat162(hx, hy);
    __nv_bfloat162 h23 = __halves2bfloat162(hz, hw);
    __nv_bfloat162 l01 = __halves2bfloat162(__float2bfloat16(v.x - __bfloat162float(hx)),
                                            __float2bfloat16(v.y - __bfloat162float(hy)));
    __nv_bfloat162 l23 = __halves2bfloat162(__float2bfloat16(v.z - __bfloat162float(hz)),
                                            __float2bfloat16(v.w - __bfloat162float(hw)));
    uint2 hh = make_uint2(*(uint32_t*)&h01, *(uint32_t*)&h23);
    uint2 ll = make_uint2(*(uint32_t*)&l01, *(uint32_t*)&l23);
    *(uint2*)(hi + i) = hh;
    *(uint2*)(lo + i) = ll;
}

// ---------------- inj[n] = concat(hs0[ctx], hs1[ctx]) @ fc_w ----------------
__global__ void inj_kernel(const float* __restrict__ hs, const int* __restrict__ anchors,
                           const float* __restrict__ fcw, float* __restrict__ inj)
{
    int n = blockIdx.x;
    int c = blockIdx.y * 128 + threadIdx.x;
    int a = anchors[n];
    int ctx = a - 1; if (ctx < 0) ctx = 0;
    const float* h0 = hs + (size_t)ctx * H_;
    const float* h1 = hs + (size_t)S_ * H_ + (size_t)ctx * H_;
    float acc = 0.f;
    for (int k = 0; k < H_; k++) acc += h0[k] * fcw[(size_t)k * H_ + c];
    for (int k = 0; k < H_; k++) acc += h1[k] * fcw[(size_t)(H_ + k) * H_ + c];
    inj[(size_t)n * H_ + c] = acc;
}

// ---------------- h = [embed[ids]; embed[blk_ids] + inj], pos ----------------
__global__ void build_h_kernel(const int* __restrict__ ids, const int* __restrict__ anchors,
                               const float* __restrict__ embed, const float* __restrict__ inj,
                               float* __restrict__ h, int* __restrict__ pos)
{
    int t = blockIdx.x;
    int tok;
    const float* add = nullptr;
    if (t < S_) {
        tok = ids[t];
        if (threadIdx.x == 0) pos[t] = t;
    } else {
        int n = (t - S_) / BS_, j = (t - S_) % BS_;
        int a = anchors[n];
        int ap = a; if (ap < 0) ap = 0; if (ap > S_-1) ap = S_-1;
        tok = (j == 0) ? ids[ap] : 0;   // MASK_TOKEN = 0
        add = inj + (size_t)n * H_;
        if (threadIdx.x == 0) pos[t] = a + j;
    }
    const float* e = embed + (size_t)tok * H_;
    for (int c = threadIdx.x; c < H_; c += blockDim.x)
        h[(size_t)t * H_ + c] = e[c] + (add ? add[c] : 0.f);
}

// ---------------- rmsnorm with fused bf16 hi/lo split output ----------------
__global__ __launch_bounds__(256) void rmsnorm_split_kernel(const float* __restrict__ in,
                                                            const float* __restrict__ w,
                                                            __nv_bfloat16* __restrict__ hi,
                                                            __nv_bfloat16* __restrict__ lo)
{
    int t = blockIdx.x;
    const float* r = in + (size_t)t * H_;
    float ss = 0.f;
    for (int c = threadIdx.x; c < H_; c += 256) { float v = r[c]; ss += v * v; }
    ss = wsum(ss);
    __shared__ float sred[8];
    if ((threadIdx.x & 31) == 0) sred[threadIdx.x >> 5] = ss;
    __syncthreads();
    float tot = 0.f;
#pragma unroll
    for (int i = 0; i < 8; i++) tot += sred[i];
    float inv = rsqrtf(tot * (1.0f / H_) + 1e-6f);
    for (int c = threadIdx.x; c < H_; c += 256) {
        float xv = r[c] * inv * w[c];
        __nv_bfloat16 hb = __float2bfloat16(xv);
        hi[(size_t)t * H_ + c] = hb;
        lo[(size_t)t * H_ + c] = __float2bfloat16(xv - __bfloat162float(hb));
    }
}

// ---------------- RoPE on q and k in-place ----------------
__global__ void rope_kernel(float* __restrict__ q, float* __restrict__ k,
                            const int* __restrict__ pos)
{
    int t = blockIdx.x;
    int idx = threadIdx.x;          // 0..511
    int hh = idx >> 6, i = idx & 63;
    int p = pos[t];
    double ang = (double)p * pow(10000.0, -(double)i / 64.0);
    double sd, cd;
    sincos(ang, &sd, &cd);
    float s = (float)sd, c = (float)cd;
    size_t b = (size_t)t * H_ + hh * DH_ + i;
    float x1 = q[b], x2 = q[b + 64];
    q[b]      = x1 * c - x2 * s;
    q[b + 64] = x2 * c + x1 * s;
    x1 = k[b]; x2 = k[b + 64];
    k[b]      = x1 * c - x2 * s;
    k[b + 64] = x2 * c + x1 * s;
}

// ---------------- transpose k [T][H] -> kT [H][T] ----------------
__global__ void transposeKN_kernel(const float* __restrict__ in, float* __restrict__ out,
                                   int Kd, int Nd)
{
    __shared__ float tile[32][33];
    int n0 = blockIdx.x * 32;
    int k0 = blockIdx.y * 32;
    int x = threadIdx.x, y0 = threadIdx.y;   // block (32, 8)
#pragma unroll
    for (int dy = 0; dy < 32; dy += 8)
        tile[y0 + dy][x] = in[(size_t)(k0 + y0 + dy) * Nd + n0 + x];
    __syncthreads();
#pragma unroll
    for (int dy = 0; dy < 32; dy += 8)
        out[(size_t)(n0 + y0 + dy) * Kd + k0 + x] = tile[x][y0 + dy];
}

// ---------------- attention: 8 queries x 1 head per block, 128 threads ----------------
__global__ __launch_bounds__(128) void attn_kernel(
    const float* __restrict__ q, const float* __restrict__ kT,
    const float* __restrict__ v, const int* __restrict__ anchors,
    __nv_bfloat16* __restrict__ ohi, __nv_bfloat16* __restrict__ olo)
{
    __shared__ float qs[QB][DH_];
    __shared__ float pbuf[QB][128];
    __shared__ float redm[QB][4];
    __shared__ float reds[QB][4];

    int h   = blockIdx.y;
    int t0  = blockIdx.x * QB;
    int tid = threadIdx.x;
    int w   = tid >> 5, lane = tid & 31;

#pragma unroll
    for (int qi = 0; qi < QB; qi++)
        qs[qi][tid] = q[(size_t)(t0 + qi) * H_ + h * DH_ + tid] * SCALE;
    __syncthreads();

    float m[QB], l[QB], acc[QB];
#pragma unroll
    for (int qi = 0; qi < QB; qi++) { m[qi] = -INFINITY; l[qi] = 0.f; acc[qi] = 0.f; }

    int lo[QB], hi[QB];

    auto proc = [&](int base, int cnt) {
        int k = base + tid;
        bool act = tid < cnt;
        float s[QB];
#pragma unroll
        for (int qi = 0; qi < QB; qi++) s[qi] = -INFINITY;
        if (act) {
#pragma unroll
            for (int qi = 0; qi < QB; qi++) s[qi] = 0.f;
            const float* kp = kT + (size_t)(h * DH_) * T_ + k;
            for (int d = 0; d < DH_; d += 4) {
                float kv0 = kp[(size_t)(d + 0) * T_];
                float kv1 = kp[(size_t)(d + 1) * T_];
                float kv2 = kp[(size_t)(d + 2) * T_];
                float kv3 = kp[(size_t)(d + 3) * T_];
#pragma unroll
                for (int qi = 0; qi < QB; qi++) {
                    float4 qv = *(const float4*)&qs[qi][d];
                    s[qi] += qv.x * kv0 + qv.y * kv1 + qv.z * kv2 + qv.w * kv3;
                }
            }
#pragma unroll
            for (int qi = 0; qi < QB; qi++)
                if (k < lo[qi] || k > hi[qi]) s[qi] = -INFINITY;
        }
        __syncthreads();
#pragma unroll
        for (int qi = 0; qi < QB; qi++) {
            float x = wmax(s[qi]);
            if (lane == 0) redm[qi][w] = x;
        }
        __syncthreads();
        float nm[QB];
#pragma unroll
        for (int qi = 0; qi < QB; qi++) {
            float cm = fmaxf(fmaxf(redm[qi][0], redm[qi][1]), fmaxf(redm[qi][2], redm[qi][3]));
            nm[qi] = fmaxf(m[qi], cm);
            float p = (s[qi] == -INFINITY) ? 0.f : expf(s[qi] - nm[qi]);
            pbuf[qi][tid] = p;
            float sp = wsum(p);
            if (lane == 0) reds[qi][w] = sp;
        }
        __syncthreads();
#pragma unroll
        for (int qi = 0; qi < QB; qi++) {
            float f = (m[qi] == -INFINITY) ? 0.f : expf(m[qi] - nm[qi]);
            float cs = reds[qi][0] + reds[qi][1] + reds[qi][2] + reds[qi][3];
            l[qi] = l[qi] * f + cs;
            acc[qi] *= f;
            m[qi] = nm[qi];
        }
        const float* vp = v + (size_t)base * H_ + h * DH_ + tid;
        for (int j = 0; j < cnt; j += 4) {
            float vv0 = vp[(size_t)(j + 0) * H_];
            float vv1 = vp[(size_t)(j + 1) * H_];
            float vv2 = vp[(size_t)(j + 2) * H_];
            float vv3 = vp[(size_t)(j + 3) * H_];
#pragma unroll
            for (int qi = 0; qi < QB; qi++) {
                float4 pv = *(const float4*)&pbuf[qi][j];
                acc[qi] += pv.x * vv0 + pv.y * vv1 + pv.z * vv2 + pv.w * vv3;
            }
        }
    };

    if (t0 < S_) {
#pragma unroll
        for (int qi = 0; qi < QB; qi++) { lo[qi] = 0; hi[qi] = t0 + qi; }
        for (int base = 0; base <= t0 + QB - 1; base += 128) proc(base, 128);
    } else {
        int nb = (t0 - S_) / BS_;
        int a  = anchors[nb];
        int ws = a - W_ + 1; if (ws < 0) ws = 0;
        int we = a - 1;
#pragma unroll
        for (int qi = 0; qi < QB; qi++) { lo[qi] = ws; hi[qi] = we; }
        for (int base = (ws >> 7) << 7; base <= we; base += 128) proc(base, 128);
        int kb = S_ + nb * BS_;
#pragma unroll
        for (int qi = 0; qi < QB; qi++) { lo[qi] = kb; hi[qi] = kb + BS_ - 1; }
        proc(kb, BS_);
    }

#pragma unroll
    for (int qi = 0; qi < QB; qi++) {
        float o = acc[qi] / l[qi];
        size_t idx = (size_t)(t0 + qi) * H_ + h * DH_ + tid;
        __nv_bfloat16 hb = __float2bfloat16(o);
        ohi[idx] = hb;
        olo[idx] = __float2bfloat16(o - __bfloat162float(hb));
    }
}

// ---------------- launch ----------------
extern "C" void kernel_launch(void* const* d_in, const int* in_sizes, int n_in,
                              void* d_out, int out_size)
{
    const int*   ids     = (const int*)  d_in[0];
    const float* hs      = (const float*)d_in[1];
    const int*   anchors = (const int*)  d_in[2];
    // d_in[3] block_keep_mask: all-true by construction; intentionally unused
    const float* embed   = (const float*)d_in[4];
    const float* Wq      = (const float*)d_in[5];
    const float* Wk      = (const float*)d_in[6];
    const float* Wv      = (const float*)d_in[7];
    const float* Wo      = (const float*)d_in[8];
    const float* fcw     = (const float*)d_in[9];
    const float* lmw     = (const float*)d_in[10];
    const float* normw   = (const float*)d_in[11];

    float *h, *q, *k, *v, *kT, *h2, *inj;
    int* pos;
    __nv_bfloat16 *xhi, *xlo, *aohi, *aolo;
    __nv_bfloat16 *wqhi, *wqlo, *wkhi, *wklo, *wvhi, *wvlo, *wohi, *wolo, *lmhi, *lmlo;
    cudaGetSymbolAddress((void**)&h,    g_h);
    cudaGetSymbolAddress((void**)&q,    g_q);
    cudaGetSymbolAddress((void**)&k,    g_k);
    cudaGetSymbolAddress((void**)&v,    g_v);
    cudaGetSymbolAddress((void**)&kT,   g_kT);
    cudaGetSymbolAddress((void**)&h2,   g_h2);
    cudaGetSymbolAddress((void**)&inj,  g_inj);
    cudaGetSymbolAddress((void**)&pos,  g_pos);
    cudaGetSymbolAddress((void**)&xhi,  g_xhi);
    cudaGetSymbolAddress((void**)&xlo,  g_xlo);
    cudaGetSymbolAddress((void**)&aohi, g_aohi);
    cudaGetSymbolAddress((void**)&aolo, g_aolo);
    cudaGetSymbolAddress((void**)&wqhi, g_wqhi);
    cudaGetSymbolAddress((void**)&wqlo, g_wqlo);
    cudaGetSymbolAddress((void**)&wkhi, g_wkhi);
    cudaGetSymbolAddress((void**)&wklo, g_wklo);
    cudaGetSymbolAddress((void**)&wvhi, g_wvhi);
    cudaGetSymbolAddress((void**)&wvlo, g_wvlo);
    cudaGetSymbolAddress((void**)&wohi, g_wohi);
    cudaGetSymbolAddress((void**)&wolo, g_wolo);
    cudaGetSymbolAddress((void**)&lmhi, g_lmhi);
    cudaGetSymbolAddress((void**)&lmlo, g_lmlo);

    cudaFuncSetAttribute(hgemm_kernel, cudaFuncAttributeMaxDynamicSharedMemorySize, HS_TOTAL);

    // weight splits (fp32 -> bf16 hi/lo)
    split_kernel<<<H_*H_/1024, 256>>>(Wq,  wqhi, wqlo);
    split_kernel<<<H_*H_/1024, 256>>>(Wk,  wkhi, wklo);
    split_kernel<<<H_*H_/1024, 256>>>(Wv,  wvhi, wvlo);
    split_kernel<<<H_*H_/1024, 256>>>(Wo,  wohi, wolo);
    split_kernel<<<(int)((size_t)V_*H_/1024), 256>>>(lmw, lmhi, lmlo);

    inj_kernel<<<dim3(N_, H_ / 128), 128>>>(hs, anchors, fcw, inj);
    build_h_kernel<<<T_, 256>>>(ids, anchors, embed, inj, h, pos);
    rmsnorm_split_kernel<<<T_, 256>>>(h, normw, xhi, xlo);

    dim3 g1(H_ / 128, T_ / 128);
    hgemm_kernel<<<g1, 256, HS_TOTAL>>>(T_, H_, H_, xhi, xlo, wqhi, wqlo, q, nullptr);
    hgemm_kernel<<<g1, 256, HS_TOTAL>>>(T_, H_, H_, xhi, xlo, wkhi, wklo, k, nullptr);
    hgemm_kernel<<<g1, 256, HS_TOTAL>>>(T_, H_, H_, xhi, xlo, wvhi, wvlo, v, nullptr);

    rope_kernel<<<T_, 512>>>(q, k, pos);
    transposeKN_kernel<<<dim3(H_ / 32, T_ / 32), dim3(32, 8)>>>(k, kT, T_, H_);

    attn_kernel<<<dim3(T_ / QB, NH_), 128>>>(q, kT, v, anchors, aohi, aolo);

    hgemm_kernel<<<g1, 256, HS_TOTAL>>>(T_, H_, H_, aohi, aolo, wohi, wolo, h2, h);  // +residual
    rmsnorm_split_kernel<<<T_, 256>>>(h2, normw, xhi, xlo);

    hgemm_kernel<<<dim3(V_ / 128, T_ / 128), 256, HS_TOTAL>>>(T_, V_, H_,
                                                              xhi, xlo, lmhi, lmlo,
                                                              (float*)d_out, nullptr);
}

// round 8
// speedup vs baseline: 2.2578x; 1.0169x over previous
#include <cuda_runtime.h>
#include <cuda_bf16.h>
#include <math.h>
#include <stdint.h>

#define S_  2048
#define N_  64
#define BS_ 16
#define W_  512
#define NH_ 8
#define H_  1024
#define V_  32000
#define DH_ 128
#define T_  3072
#define QB  8
#define SCALE 0.08838834764831845f  // 1/sqrt(128)

// ---------------- scratch (device globals; no allocation) ----------------
__device__ float g_h [T_*H_];
__device__ float g_q [T_*H_];
__device__ float g_k [T_*H_];
__device__ float g_v [T_*H_];
__device__ float g_kT[T_*H_];
__device__ float g_h2[T_*H_];
__device__ float g_inj[N_*H_];
__device__ int   g_pos[T_];
__device__ __nv_bfloat16 g_xhi[T_*H_], g_xlo[T_*H_];
__device__ __nv_bfloat16 g_aohi[T_*H_], g_aolo[T_*H_];
__device__ __nv_bfloat16 g_wqhi[H_*H_], g_wqlo[H_*H_];
__device__ __nv_bfloat16 g_wkhi[H_*H_], g_wklo[H_*H_];
__device__ __nv_bfloat16 g_wvhi[H_*H_], g_wvlo[H_*H_];
__device__ __nv_bfloat16 g_wohi[H_*H_], g_wolo[H_*H_];
__device__ __nv_bfloat16 g_lmhi[(size_t)V_*H_], g_lmlo[(size_t)V_*H_];

// ---------------- helpers ----------------
__device__ __forceinline__ float wmax(float v){
#pragma unroll
    for (int o=16;o>0;o>>=1) v = fmaxf(v, __shfl_xor_sync(0xffffffffu, v, o));
    return v;
}
__device__ __forceinline__ float wsum(float v){
#pragma unroll
    for (int o=16;o>0;o>>=1) v += __shfl_xor_sync(0xffffffffu, v, o);
    return v;
}
__device__ __forceinline__ uint32_t smem_u32(const void* p){
    uint32_t a;
    asm("{ .reg .u64 t; cvta.to.shared.u64 t, %1; cvt.u32.u64 %0, t; }" : "=r"(a) : "l"(p));
    return a;
}
__device__ __forceinline__ void ldsm4(uint32_t& r0, uint32_t& r1, uint32_t& r2, uint32_t& r3,
                                      uint32_t addr){
    asm volatile("ldmatrix.sync.aligned.m8n8.x4.shared.b16 {%0,%1,%2,%3}, [%4];"
                 : "=r"(r0), "=r"(r1), "=r"(r2), "=r"(r3) : "r"(addr));
}
__device__ __forceinline__ void ldsm4t(uint32_t& r0, uint32_t& r1, uint32_t& r2, uint32_t& r3,
                                       uint32_t addr){
    asm volatile("ldmatrix.sync.aligned.m8n8.x4.trans.shared.b16 {%0,%1,%2,%3}, [%4];"
                 : "=r"(r0), "=r"(r1), "=r"(r2), "=r"(r3) : "r"(addr));
}
__device__ __forceinline__ void mma_bf16(float* c, const uint32_t* a, uint32_t b0, uint32_t b1){
    asm volatile("mma.sync.aligned.m16n8k16.row.col.f32.bf16.bf16.f32 "
                 "{%0,%1,%2,%3}, {%4,%5,%6,%7}, {%8,%9}, {%0,%1,%2,%3};"
                 : "+f"(c[0]), "+f"(c[1]), "+f"(c[2]), "+f"(c[3])
                 : "r"(a[0]), "r"(a[1]), "r"(a[2]), "r"(a[3]), "r"(b0), "r"(b1));
}
__device__ __forceinline__ void cp16(uint32_t saddr, const void* g){
    asm volatile("cp.async.cg.shared.global [%0], [%1], 16;"
                 :: "r"(saddr), "l"(__cvta_generic_to_global(g)));
}
__device__ __forceinline__ void cp_commit(){ asm volatile("cp.async.commit_group;" ::: "memory"); }
template<int Nn> __device__ __forceinline__ void cp_wait(){
    asm volatile("cp.async.wait_group %0;" :: "n"(Nn) : "memory");
}

// ================ bf16-split tensor-core GEMM core ================
#define LDSR 40
#define LDSB 136
#define ST_AHI 0
#define ST_ALO 10240
#define ST_BHI 20480
#define ST_BLO 29184
#define ST_SIZE 37888
#define NSTAGE 3
#define HS_TOTAL (NSTAGE*ST_SIZE)      // 113664 B

__device__ __forceinline__ void gemm_core(
    int Nc, int K, int crow, int ccol,
    const __nv_bfloat16* __restrict__ Ahi, const __nv_bfloat16* __restrict__ Alo,
    const __nv_bfloat16* __restrict__ Bhi, const __nv_bfloat16* __restrict__ Blo,
    float* __restrict__ C, const float* __restrict__ D, char* sm)
{
    uint32_t sb = smem_u32(sm);
    int tid  = threadIdx.x, lane = tid & 31, wid = tid >> 5;
    int wm   = (wid & 1) * 64,  wn   = (wid >> 1) * 32;

    float acc[4][4][4];
#pragma unroll
    for (int i = 0; i < 4; i++)
#pragma unroll
        for (int j = 0; j < 4; j++)
#pragma unroll
            for (int r = 0; r < 4; r++) acc[i][j][r] = 0.f;

    uint32_t a_off = ((wm + (lane & 15)) * LDSR + (lane >> 4) * 8) * 2;
    uint32_t b_off = (uint32_t)(((((lane >> 3) & 1) * 8 + (lane & 7)) * LDSB
                                 + wn + (lane >> 4) * 8) * 2);
    int kq = K / 32;

    auto issue = [&](int ch){
        uint32_t st = sb + (ch % NSTAGE) * ST_SIZE;
        int kb = ch * 32;
#pragma unroll
        for (int r = 0; r < 2; r++) {
            int seg = tid + r * 256;
            int ar = seg >> 2, ac = (seg & 3) * 8;
            size_t ga = (size_t)(crow + ar) * K + kb + ac;
            uint32_t sa = st + ST_AHI + (uint32_t)(ar * LDSR + ac) * 2;
            cp16(sa, Ahi + ga);
            cp16(sa + (ST_ALO - ST_AHI), Alo + ga);
            int br = seg >> 4, bcx = (seg & 15) * 8;
            size_t gb = (size_t)(kb + br) * Nc + ccol + bcx;
            uint32_t sbo = st + ST_BHI + (uint32_t)(br * LDSB + bcx) * 2;
            cp16(sbo, Bhi + gb);
            cp16(sbo + (ST_BLO - ST_BHI), Blo + gb);
        }
    };

    issue(0); cp_commit();
    issue(1); cp_commit();

    for (int ch = 0; ch < kq; ch++) {
        cp_wait<NSTAGE - 2>();       // chunk ch resident
        __syncthreads();             // all warps done reading stage (ch+2)%3 (= ch-1)
        if (ch + 2 < kq) issue(ch + 2);
        cp_commit();

        uint32_t base = sb + (ch % NSTAGE) * ST_SIZE;
#pragma unroll
        for (int ks = 0; ks < 2; ks++) {
            uint32_t bh4[2][4], bl4[2][4];
#pragma unroll
            for (int p = 0; p < 2; p++) {
                uint32_t adr = base + ST_BHI + b_off + ks * (16 * LDSB * 2) + p * 32;
                ldsm4t(bh4[p][0], bh4[p][1], bh4[p][2], bh4[p][3], adr);
                ldsm4t(bl4[p][0], bl4[p][1], bl4[p][2], bl4[p][3], adr + (ST_BLO - ST_BHI));
            }
#pragma unroll
            for (int mi = 0; mi < 4; mi++) {
                uint32_t ah[4], al[4];
                uint32_t adr = base + ST_AHI + a_off + mi * (16 * LDSR * 2) + ks * 32;
                ldsm4(ah[0], ah[1], ah[2], ah[3], adr);
                ldsm4(al[0], al[1], al[2], al[3], adr + (ST_ALO - ST_AHI));
#pragma unroll
                for (int ni = 0; ni < 4; ni++) {
                    uint32_t b0h = bh4[ni >> 1][(ni & 1) * 2], b1h = bh4[ni >> 1][(ni & 1) * 2 + 1];
                    uint32_t b0l = bl4[ni >> 1][(ni & 1) * 2], b1l = bl4[ni >> 1][(ni & 1) * 2 + 1];
                    mma_bf16(acc[mi][ni], ah, b0h, b1h);
                    mma_bf16(acc[mi][ni], ah, b0l, b1l);
                    mma_bf16(acc[mi][ni], al, b0h, b1h);
                }
            }
        }
    }

    // epilogue
#pragma unroll
    for (int mi = 0; mi < 4; mi++)
#pragma unroll
        for (int ni = 0; ni < 4; ni++) {
            size_t r0 = (size_t)(crow + wm + mi * 16 + (lane >> 2));
            int    cc = ccol + wn + ni * 8 + (lane & 3) * 2;
            float2 v0 = make_float2(acc[mi][ni][0], acc[mi][ni][1]);
            float2 v1 = make_float2(acc[mi][ni][2], acc[mi][ni][3]);
            if (D) {
                const float2 d0 = *(const float2*)(D + r0 * Nc + cc);
                const float2 d1 = *(const float2*)(D + (r0 + 8) * Nc + cc);
                v0.x += d0.x; v0.y += d0.y; v1.x += d1.x; v1.y += d1.y;
            }
            *(float2*)(C + r0 * Nc + cc)       = v0;
            *(float2*)(C + (r0 + 8) * Nc + cc) = v1;
        }
}

// grid: (M/128, Nc/128)  — M tile on x so waves share B columns (L2 reuse)
__global__ __launch_bounds__(256, 2) void hgemm_kernel(
    int M, int Nc, int K,
    const __nv_bfloat16* __restrict__ Ahi, const __nv_bfloat16* __restrict__ Alo,
    const __nv_bfloat16* __restrict__ Bhi, const __nv_bfloat16* __restrict__ Blo,
    float* __restrict__ C, const float* __restrict__ D)
{
    extern __shared__ char sm[];
    gemm_core(Nc, K, blockIdx.x * 128, blockIdx.y * 128, Ahi, Alo, Bhi, Blo, C, D, sm);
}

// fused QKV: grid (T/128, H/128, 3)
__global__ __launch_bounds__(256, 2) void hgemm_qkv_kernel(
    const __nv_bfloat16* __restrict__ Ahi, const __nv_bfloat16* __restrict__ Alo,
    const __nv_bfloat16* __restrict__ qh, const __nv_bfloat16* __restrict__ ql,
    const __nv_bfloat16* __restrict__ kh, const __nv_bfloat16* __restrict__ kl,
    const __nv_bfloat16* __restrict__ vh, const __nv_bfloat16* __restrict__ vl,
    float* __restrict__ q, float* __restrict__ k, float* __restrict__ v)
{
    extern __shared__ char sm[];
    const __nv_bfloat16 *Bhi, *Blo;
    float* C;
    if (blockIdx.z == 0)      { Bhi = qh; Blo = ql; C = q; }
    else if (blockIdx.z == 1) { Bhi = kh; Blo = kl; C = k; }
    else                      { Bhi = vh; Blo = vl; C = v; }
    gemm_core(H_, H_, blockIdx.x * 128, blockIdx.y * 128, Ahi, Alo, Bhi, Blo, C, nullptr, sm);
}

// ---------------- split fp32 -> bf16 hi/lo ----------------
__global__ __launch_bounds__(256) void split_kernel(const float* __restrict__ in,
                                                    __nv_bfloat16* __restrict__ hi,
                                                    __nv_bfloat16* __restrict__ lo)
{
    size_t i = ((size_t)blockIdx.x * 256 + threadIdx.x) * 4;
    float4 v = *(const float4*)(in + i);
    __nv_bfloat16 hx = __float2bfloat16(v.x), hy = __float2bfloat16(v.y);
    __nv_bfloat16 hz = __float2bfloat16(v.z), hw = __float2bfloat16(v.w);
    __nv_bfloat162 h01 = __halves2bfloat162(hx, hy);
    __nv_bfloat162 h23 = __halves2bfloat162(hz, hw);
    __nv_bfloat162 l01 = __halves2bfloat162(__float2bfloat16(v.x - __bfloat162float(hx)),
                                            __float2bfloat16(v.y - __bfloat162float(hy)));
    __nv_bfloat162 l23 = __halves2bfloat162(__float2bfloat16(v.z - __bfloat162float(hz)),
                                            __float2bfloat16(v.w - __bfloat162float(hw)));
    uint2 hh = make_uint2(*(uint32_t*)&h01, *(uint32_t*)&h23);
    uint2 ll = make_uint2(*(uint32_t*)&l01, *(uint32_t*)&l23);
    *(uint2*)(hi + i) = hh;
    *(uint2*)(lo + i) = ll;
}

// ---------------- inj[n] = concat(hs0[ctx], hs1[ctx]) @ fc_w ----------------
__global__ void inj_kernel(const float* __restrict__ hs, const int* __restrict__ anchors,
                           const float* __restrict__ fcw, float* __restrict__ inj)
{
    int n = blockIdx.x;
    int c = blockIdx.y * 128 + threadIdx.x;
    int a = anchors[n];
    int ctx = a - 1; if (ctx < 0) ctx = 0;
    const float* h0 = hs + (size_t)ctx * H_;
    const float* h1 = hs + (size_t)S_ * H_ + (size_t)ctx * H_;
    float acc = 0.f;
    for (int k = 0; k < H_; k++) acc += h0[k] * fcw[(size_t)k * H_ + c];
    for (int k = 0; k < H_; k++) acc += h1[k] * fcw[(size_t)(H_ + k) * H_ + c];
    inj[(size_t)n * H_ + c] = acc;
}

// ---------------- h = [embed[ids]; embed[blk_ids] + inj], pos ----------------
__global__ void build_h_kernel(const int* __restrict__ ids, const int* __restrict__ anchors,
                               const float* __restrict__ embed, const float* __restrict__ inj,
                               float* __restrict__ h, int* __restrict__ pos)
{
    int t = blockIdx.x;
    int tok;
    const float* add = nullptr;
    if (t < S_) {
        tok = ids[t];
        if (threadIdx.x == 0) pos[t] = t;
    } else {
        int n = (t - S_) / BS_, j = (t - S_) % BS_;
        int a = anchors[n];
        int ap = a; if (ap < 0) ap = 0; if (ap > S_-1) ap = S_-1;
        tok = (j == 0) ? ids[ap] : 0;   // MASK_TOKEN = 0
        add = inj + (size_t)n * H_;
        if (threadIdx.x == 0) pos[t] = a + j;
    }
    const float* e = embed + (size_t)tok * H_;
    for (int c = threadIdx.x; c < H_; c += blockDim.x)
        h[(size_t)t * H_ + c] = e[c] + (add ? add[c] : 0.f);
}

// ---------------- rmsnorm with fused bf16 hi/lo split output ----------------
__global__ __launch_bounds__(256) void rmsnorm_split_kernel(const float* __restrict__ in,
                                                            const float* __restrict__ w,
                                                            __nv_bfloat16* __restrict__ hi,
                                                            __nv_bfloat16* __restrict__ lo)
{
    int t = blockIdx.x;
    const float* r = in + (size_t)t * H_;
    float ss = 0.f;
    for (int c = threadIdx.x; c < H_; c += 256) { float v = r[c]; ss += v * v; }
    ss = wsum(ss);
    __shared__ float sred[8];
    if ((threadIdx.x & 31) == 0) sred[threadIdx.x >> 5] = ss;
    __syncthreads();
    float tot = 0.f;
#pragma unroll
    for (int i = 0; i < 8; i++) tot += sred[i];
    float inv = rsqrtf(tot * (1.0f / H_) + 1e-6f);
    for (int c = threadIdx.x; c < H_; c += 256) {
        float xv = r[c] * inv * w[c];
        __nv_bfloat16 hb = __float2bfloat16(xv);
        hi[(size_t)t * H_ + c] = hb;
        lo[(size_t)t * H_ + c] = __float2bfloat16(xv - __bfloat162float(hb));
    }
}

// ---------------- RoPE on q and k in-place ----------------
__global__ void rope_kernel(float* __restrict__ q, float* __restrict__ k,
                            const int* __restrict__ pos)
{
    int t = blockIdx.x;
    int idx = threadIdx.x;          // 0..511
    int hh = idx >> 6, i = idx & 63;
    int p = pos[t];
    double ang = (double)p * pow(10000.0, -(double)i / 64.0);
    double sd, cd;
    sincos(ang, &sd, &cd);
    float s = (float)sd, c = (float)cd;
    size_t b = (size_t)t * H_ + hh * DH_ + i;
    float x1 = q[b], x2 = q[b + 64];
    q[b]      = x1 * c - x2 * s;
    q[b + 64] = x2 * c + x1 * s;
    x1 = k[b]; x2 = k[b + 64];
    k[b]      = x1 * c - x2 * s;
    k[b + 64] = x2 * c + x1 * s;
}

// ---------------- transpose in[Kd][Nd] -> out[Nd][Kd] ----------------
__global__ void transposeKN_kernel(const float* __restrict__ in, float* __restrict__ out,
                                   int Kd, int Nd)
{
    __shared__ float tile[32][33];
    int n0 = blockIdx.x * 32;
    int k0 = blockIdx.y * 32;
    int x = threadIdx.x, y0 = threadIdx.y;   // block (32, 8)
#pragma unroll
    for (int dy = 0; dy < 32; dy += 8)
        tile[y0 + dy][x] = in[(size_t)(k0 + y0 + dy) * Nd + n0 + x];
    __syncthreads();
#pragma unroll
    for (int dy = 0; dy < 32; dy += 8)
        out[(size_t)(n0 + y0 + dy) * Kd + k0 + x] = tile[x][y0 + dy];
}

// ---------------- attention: 8 queries x 1 head per block, 128 threads ----------------
__global__ __launch_bounds__(128) void attn_kernel(
    const float* __restrict__ q, const float* __restrict__ kT,
    const float* __restrict__ v, const int* __restrict__ anchors,
    __nv_bfloat16* __restrict__ ohi, __nv_bfloat16* __restrict__ olo)
{
    __shared__ float qs[QB][DH_];
    __shared__ float pbuf[QB][128];
    __shared__ float redm[QB][4];
    __shared__ float reds[QB][4];

    int h   = blockIdx.y;
    int t0  = blockIdx.x * QB;
    int tid = threadIdx.x;
    int w   = tid >> 5, lane = tid & 31;

#pragma unroll
    for (int qi = 0; qi < QB; qi++)
        qs[qi][tid] = q[(size_t)(t0 + qi) * H_ + h * DH_ + tid] * SCALE;
    __syncthreads();

    float m[QB], l[QB], acc[QB];
#pragma unroll
    for (int qi = 0; qi < QB; qi++) { m[qi] = -INFINITY; l[qi] = 0.f; acc[qi] = 0.f; }

    int lo[QB], hi[QB];

    auto proc = [&](int base, int cnt) {
        int k = base + tid;
        bool act = tid < cnt;
        float s[QB];
#pragma unroll
        for (int qi = 0; qi < QB; qi++) s[qi] = -INFINITY;
        if (act) {
#pragma unroll
            for (int qi = 0; qi < QB; qi++) s[qi] = 0.f;
            const float* kp = kT + (size_t)(h * DH_) * T_ + k;
            for (int d = 0; d < DH_; d += 4) {
                float kv0 = kp[(size_t)(d + 0) * T_];
                float kv1 = kp[(size_t)(d + 1) * T_];
                float kv2 = kp[(size_t)(d + 2) * T_];
                float kv3 = kp[(size_t)(d + 3) * T_];
#pragma unroll
                for (int qi = 0; qi < QB; qi++) {
                    float4 qv = *(const float4*)&qs[qi][d];
                    s[qi] += qv.x * kv0 + qv.y * kv1 + qv.z * kv2 + qv.w * kv3;
                }
            }
#pragma unroll
            for (int qi = 0; qi < QB; qi++)
                if (k < lo[qi] || k > hi[qi]) s[qi] = -INFINITY;
        }
        __syncthreads();
#pragma unroll
        for (int qi = 0; qi < QB; qi++) {
            float x = wmax(s[qi]);
            if (lane == 0) redm[qi][w] = x;
        }
        __syncthreads();
        float nm[QB];
#pragma unroll
        for (int qi = 0; qi < QB; qi++) {
            float cm = fmaxf(fmaxf(redm[qi][0], redm[qi][1]), fmaxf(redm[qi][2], redm[qi][3]));
            nm[qi] = fmaxf(m[qi], cm);
            float p = (s[qi] == -INFINITY) ? 0.f : expf(s[qi] - nm[qi]);
            pbuf[qi][tid] = p;
            float sp = wsum(p);
            if (lane == 0) reds[qi][w] = sp;
        }
        __syncthreads();
#pragma unroll
        for (int qi = 0; qi < QB; qi++) {
            float f = (m[qi] == -INFINITY) ? 0.f : expf(m[qi] - nm[qi]);
            float cs = reds[qi][0] + reds[qi][1] + reds[qi][2] + reds[qi][3];
            l[qi] = l[qi] * f + cs;
            acc[qi] *= f;
            m[qi] = nm[qi];
        }
        const float* vp = v + (size_t)base * H_ + h * DH_ + tid;
        for (int j = 0; j < cnt; j += 4) {
            float vv0 = vp[(size_t)(j + 0) * H_];
            float vv1 = vp[(size_t)(j + 1) * H_];
            float vv2 = vp[(size_t)(j + 2) * H_];
            float vv3 = vp[(size_t)(j + 3) * H_];
#pragma unroll
            for (int qi = 0; qi < QB; qi++) {
                float4 pv = *(const float4*)&pbuf[qi][j];
                acc[qi] += pv.x * vv0 + pv.y * vv1 + pv.z * vv2 + pv.w * vv3;
            }
        }
    };

    if (t0 < S_) {
#pragma unroll
        for (int qi = 0; qi < QB; qi++) { lo[qi] = 0; hi[qi] = t0 + qi; }
        for (int base = 0; base <= t0 + QB - 1; base += 128) proc(base, 128);
    } else {
        int nb = (t0 - S_) / BS_;
        int a  = anchors[nb];
        int ws = a - W_ + 1; if (ws < 0) ws = 0;
        int we = a - 1;
#pragma unroll
        for (int qi = 0; qi < QB; qi++) { lo[qi] = ws; hi[qi] = we; }
        for (int base = (ws >> 7) << 7; base <= we; base += 128) proc(base, 128);
        int kb = S_ + nb * BS_;
#pragma unroll
        for (int qi = 0; qi < QB; qi++) { lo[qi] = kb; hi[qi] = kb + BS_ - 1; }
        proc(kb, BS_);
    }

#pragma unroll
    for (int qi = 0; qi < QB; qi++) {
        float o = acc[qi] / l[qi];
        size_t idx = (size_t)(t0 + qi) * H_ + h * DH_ + tid;
        __nv_bfloat16 hb = __float2bfloat16(o);
        ohi[idx] = hb;
        olo[idx] = __float2bfloat16(o - __bfloat162float(hb));
    }
}

// ---------------- launch ----------------
extern "C" void kernel_launch(void* const* d_in, const int* in_sizes, int n_in,
                              void* d_out, int out_size)
{
    const int*   ids     = (const int*)  d_in[0];
    const float* hs      = (const float*)d_in[1];
    const int*   anchors = (const int*)  d_in[2];
    // d_in[3] block_keep_mask: all-true by construction; intentionally unused
    const float* embed   = (const float*)d_in[4];
    const float* Wq      = (const float*)d_in[5];
    const float* Wk      = (const float*)d_in[6];
    const float* Wv      = (const float*)d_in[7];
    const float* Wo      = (const float*)d_in[8];
    const float* fcw     = (const float*)d_in[9];
    const float* lmw     = (const float*)d_in[10];
    const float* normw   = (const float*)d_in[11];

    float *h, *q, *k, *v, *kT, *h2, *inj;
    int* pos;
    __nv_bfloat16 *xhi, *xlo, *aohi, *aolo;
    __nv_bfloat16 *wqhi, *wqlo, *wkhi, *wklo, *wvhi, *wvlo, *wohi, *wolo, *lmhi, *lmlo;
    cudaGetSymbolAddress((void**)&h,    g_h);
    cudaGetSymbolAddress((void**)&q,    g_q);
    cudaGetSymbolAddress((void**)&k,    g_k);
    cudaGetSymbolAddress((void**)&v,    g_v);
    cudaGetSymbolAddress((void**)&kT,   g_kT);
    cudaGetSymbolAddress((void**)&h2,   g_h2);
    cudaGetSymbolAddress((void**)&inj,  g_inj);
    cudaGetSymbolAddress((void**)&pos,  g_pos);
    cudaGetSymbolAddress((void**)&xhi,  g_xhi);
    cudaGetSymbolAddress((void**)&xlo,  g_xlo);
    cudaGetSymbolAddress((void**)&aohi, g_aohi);
    cudaGetSymbolAddress((void**)&aolo, g_aolo);
    cudaGetSymbolAddress((void**)&wqhi, g_wqhi);
    cudaGetSymbolAddress((void**)&wqlo, g_wqlo);
    cudaGetSymbolAddress((void**)&wkhi, g_wkhi);
    cudaGetSymbolAddress((void**)&wklo, g_wklo);
    cudaGetSymbolAddress((void**)&wvhi, g_wvhi);
    cudaGetSymbolAddress((void**)&wvlo, g_wvlo);
    cudaGetSymbolAddress((void**)&wohi, g_wohi);
    cudaGetSymbolAddress((void**)&wolo, g_wolo);
    cudaGetSymbolAddress((void**)&lmhi, g_lmhi);
    cudaGetSymbolAddress((void**)&lmlo, g_lmlo);

    cudaFuncSetAttribute(hgemm_kernel, cudaFuncAttributeMaxDynamicSharedMemorySize, HS_TOTAL);
    cudaFuncSetAttribute(hgemm_qkv_kernel, cudaFuncAttributeMaxDynamicSharedMemorySize, HS_TOTAL);

    // weight splits (fp32 -> bf16 hi/lo)
    split_kernel<<<H_*H_/1024, 256>>>(Wq,  wqhi, wqlo);
    split_kernel<<<H_*H_/1024, 256>>>(Wk,  wkhi, wklo);
    split_kernel<<<H_*H_/1024, 256>>>(Wv,  wvhi, wvlo);
    split_kernel<<<H_*H_/1024, 256>>>(Wo,  wohi, wolo);
    split_kernel<<<(int)((size_t)V_*H_/1024), 256>>>(lmw, lmhi, lmlo);

    inj_kernel<<<dim3(N_, H_ / 128), 128>>>(hs, anchors, fcw, inj);
    build_h_kernel<<<T_, 256>>>(ids, anchors, embed, inj, h, pos);
    rmsnorm_split_kernel<<<T_, 256>>>(h, normw, xhi, xlo);

    hgemm_qkv_kernel<<<dim3(T_ / 128, H_ / 128, 3), 256, HS_TOTAL>>>(
        xhi, xlo, wqhi, wqlo, wkhi, wklo, wvhi, wvlo, q, k, v);

    rope_kernel<<<T_, 512>>>(q, k, pos);
    transposeKN_kernel<<<dim3(H_ / 32, T_ / 32), dim3(32, 8)>>>(k, kT, T_, H_);

    attn_kernel<<<dim3(T_ / QB, NH_), 128>>>(q, kT, v, anchors, aohi, aolo);

    hgemm_kernel<<<dim3(T_ / 128, H_ / 128), 256, HS_TOTAL>>>(
        T_, H_, H_, aohi, aolo, wohi, wolo, h2, h);   // +residual
    rmsnorm_split_kernel<<<T_, 256>>>(h2, normw, xhi, xlo);

    hgemm_kernel<<<dim3(T_ / 128, V_ / 128), 256, HS_TOTAL>>>(
        T_, V_, H_, xhi, xlo, lmhi, lmlo, (float*)d_out, nullptr);
}

// round 9
// speedup vs baseline: 2.5218x; 1.1169x over previous
#include <cuda_runtime.h>
#include <cuda_bf16.h>
#include <math.h>
#include <stdint.h>

#define S_  2048
#define N_  64
#define BS_ 16
#define W_  512
#define NH_ 8
#define H_  1024
#define V_  32000
#define DH_ 128
#define T_  3072
#define QB  8
#define SCALE 0.08838834764831845f  // 1/sqrt(128)

// ---------------- scratch (device globals; no allocation) ----------------
__device__ float g_h [T_*H_];
__device__ float g_q [T_*H_];
__device__ float g_k [T_*H_];
__device__ float g_v [T_*H_];
__device__ float g_kT[T_*H_];
__device__ float g_h2[T_*H_];
__device__ float g_inj[N_*H_];
__device__ int   g_pos[T_];
__device__ __nv_bfloat16 g_xhi[T_*H_], g_xlo[T_*H_];
__device__ __nv_bfloat16 g_aohi[T_*H_], g_aolo[T_*H_];
__device__ __nv_bfloat16 g_wqhi[H_*H_], g_wqlo[H_*H_];
__device__ __nv_bfloat16 g_wkhi[H_*H_], g_wklo[H_*H_];
__device__ __nv_bfloat16 g_wvhi[H_*H_], g_wvlo[H_*H_];
__device__ __nv_bfloat16 g_wohi[H_*H_], g_wolo[H_*H_];
__device__ __nv_bfloat16 g_lmhi[(size_t)V_*H_], g_lmlo[(size_t)V_*H_];

// ---------------- helpers ----------------
__device__ __forceinline__ float wsum(float v){
#pragma unroll
    for (int o=16;o>0;o>>=1) v += __shfl_xor_sync(0xffffffffu, v, o);
    return v;
}
__device__ __forceinline__ float wmax(float v){
#pragma unroll
    for (int o=16;o>0;o>>=1) v = fmaxf(v, __shfl_xor_sync(0xffffffffu, v, o));
    return v;
}
__device__ __forceinline__ uint32_t smem_u32(const void* p){
    uint32_t a;
    asm("{ .reg .u64 t; cvta.to.shared.u64 t, %1; cvt.u32.u64 %0, t; }" : "=r"(a) : "l"(p));
    return a;
}
__device__ __forceinline__ void ldsm4(uint32_t& r0, uint32_t& r1, uint32_t& r2, uint32_t& r3,
                                      uint32_t addr){
    asm volatile("ldmatrix.sync.aligned.m8n8.x4.shared.b16 {%0,%1,%2,%3}, [%4];"
                 : "=r"(r0), "=r"(r1), "=r"(r2), "=r"(r3) : "r"(addr));
}
__device__ __forceinline__ void ldsm4t(uint32_t& r0, uint32_t& r1, uint32_t& r2, uint32_t& r3,
                                       uint32_t addr){
    asm volatile("ldmatrix.sync.aligned.m8n8.x4.trans.shared.b16 {%0,%1,%2,%3}, [%4];"
                 : "=r"(r0), "=r"(r1), "=r"(r2), "=r"(r3) : "r"(addr));
}
__device__ __forceinline__ void mma_bf16(float* c, const uint32_t* a, uint32_t b0, uint32_t b1){
    asm volatile("mma.sync.aligned.m16n8k16.row.col.f32.bf16.bf16.f32 "
                 "{%0,%1,%2,%3}, {%4,%5,%6,%7}, {%8,%9}, {%0,%1,%2,%3};"
                 : "+f"(c[0]), "+f"(c[1]), "+f"(c[2]), "+f"(c[3])
                 : "r"(a[0]), "r"(a[1]), "r"(a[2]), "r"(a[3]), "r"(b0), "r"(b1));
}
__device__ __forceinline__ void cp16(uint32_t saddr, const void* g){
    asm volatile("cp.async.cg.shared.global [%0], [%1], 16;"
                 :: "r"(saddr), "l"(__cvta_generic_to_global(g)));
}
__device__ __forceinline__ void cp_commit(){ asm volatile("cp.async.commit_group;" ::: "memory"); }
template<int Nn> __device__ __forceinline__ void cp_wait(){
    asm volatile("cp.async.wait_group %0;" :: "n"(Nn) : "memory");
}

// ================ bf16-split tensor-core GEMM core ================
#define LDSR 40
#define LDSB 136
#define ST_AHI 0
#define ST_ALO 10240
#define ST_BHI 20480
#define ST_BLO 29184
#define ST_SIZE 37888
#define NSTAGE 3
#define HS_TOTAL (NSTAGE*ST_SIZE)      // 113664 B

__device__ __forceinline__ void gemm_core(
    int Nc, int K, int crow, int ccol,
    const __nv_bfloat16* __restrict__ Ahi, const __nv_bfloat16* __restrict__ Alo,
    const __nv_bfloat16* __restrict__ Bhi, const __nv_bfloat16* __restrict__ Blo,
    float* __restrict__ C, const float* __restrict__ D, char* sm)
{
    uint32_t sb = smem_u32(sm);
    int tid  = threadIdx.x, lane = tid & 31, wid = tid >> 5;
    int wm   = (wid & 1) * 64,  wn   = (wid >> 1) * 32;

    float acc[4][4][4];
#pragma unroll
    for (int i = 0; i < 4; i++)
#pragma unroll
        for (int j = 0; j < 4; j++)
#pragma unroll
            for (int r = 0; r < 4; r++) acc[i][j][r] = 0.f;

    uint32_t a_off = ((wm + (lane & 15)) * LDSR + (lane >> 4) * 8) * 2;
    uint32_t b_off = (uint32_t)(((((lane >> 3) & 1) * 8 + (lane & 7)) * LDSB
                                 + wn + (lane >> 4) * 8) * 2);
    int kq = K / 32;

    auto issue = [&](int ch){
        uint32_t st = sb + (ch % NSTAGE) * ST_SIZE;
        int kb = ch * 32;
#pragma unroll
        for (int r = 0; r < 2; r++) {
            int seg = tid + r * 256;
            int ar = seg >> 2, ac = (seg & 3) * 8;
            size_t ga = (size_t)(crow + ar) * K + kb + ac;
            uint32_t sa = st + ST_AHI + (uint32_t)(ar * LDSR + ac) * 2;
            cp16(sa, Ahi + ga);
            cp16(sa + (ST_ALO - ST_AHI), Alo + ga);
            int br = seg >> 4, bcx = (seg & 15) * 8;
            size_t gb = (size_t)(kb + br) * Nc + ccol + bcx;
            uint32_t sbo = st + ST_BHI + (uint32_t)(br * LDSB + bcx) * 2;
            cp16(sbo, Bhi + gb);
            cp16(sbo + (ST_BLO - ST_BHI), Blo + gb);
        }
    };

    issue(0); cp_commit();
    issue(1); cp_commit();

    for (int ch = 0; ch < kq; ch++) {
        cp_wait<NSTAGE - 2>();
        __syncthreads();
        if (ch + 2 < kq) issue(ch + 2);
        cp_commit();

        uint32_t base = sb + (ch % NSTAGE) * ST_SIZE;
#pragma unroll
        for (int ks = 0; ks < 2; ks++) {
            uint32_t bh4[2][4], bl4[2][4];
#pragma unroll
            for (int p = 0; p < 2; p++) {
                uint32_t adr = base + ST_BHI + b_off + ks * (16 * LDSB * 2) + p * 32;
                ldsm4t(bh4[p][0], bh4[p][1], bh4[p][2], bh4[p][3], adr);
                ldsm4t(bl4[p][0], bl4[p][1], bl4[p][2], bl4[p][3], adr + (ST_BLO - ST_BHI));
            }
#pragma unroll
            for (int mi = 0; mi < 4; mi++) {
                uint32_t ah[4], al[4];
                uint32_t adr = base + ST_AHI + a_off + mi * (16 * LDSR * 2) + ks * 32;
                ldsm4(ah[0], ah[1], ah[2], ah[3], adr);
                ldsm4(al[0], al[1], al[2], al[3], adr + (ST_ALO - ST_AHI));
#pragma unroll
                for (int ni = 0; ni < 4; ni++) {
                    uint32_t b0h = bh4[ni >> 1][(ni & 1) * 2], b1h = bh4[ni >> 1][(ni & 1) * 2 + 1];
                    uint32_t b0l = bl4[ni >> 1][(ni & 1) * 2], b1l = bl4[ni >> 1][(ni & 1) * 2 + 1];
                    mma_bf16(acc[mi][ni], ah, b0h, b1h);
                    mma_bf16(acc[mi][ni], ah, b0l, b1l);
                    mma_bf16(acc[mi][ni], al, b0h, b1h);
                }
            }
        }
    }

    // epilogue
#pragma unroll
    for (int mi = 0; mi < 4; mi++)
#pragma unroll
        for (int ni = 0; ni < 4; ni++) {
            size_t r0 = (size_t)(crow + wm + mi * 16 + (lane >> 2));
            int    cc = ccol + wn + ni * 8 + (lane & 3) * 2;
            float2 v0 = make_float2(acc[mi][ni][0], acc[mi][ni][1]);
            float2 v1 = make_float2(acc[mi][ni][2], acc[mi][ni][3]);
            if (D) {
                const float2 d0 = *(const float2*)(D + r0 * Nc + cc);
                const float2 d1 = *(const float2*)(D + (r0 + 8) * Nc + cc);
                v0.x += d0.x; v0.y += d0.y; v1.x += d1.x; v1.y += d1.y;
            }
            *(float2*)(C + r0 * Nc + cc)       = v0;
            *(float2*)(C + (r0 + 8) * Nc + cc) = v1;
        }
}

__global__ __launch_bounds__(256, 2) void hgemm_kernel(
    int M, int Nc, int K,
    const __nv_bfloat16* __restrict__ Ahi, const __nv_bfloat16* __restrict__ Alo,
    const __nv_bfloat16* __restrict__ Bhi, const __nv_bfloat16* __restrict__ Blo,
    float* __restrict__ C, const float* __restrict__ D)
{
    extern __shared__ char sm[];
    gemm_core(Nc, K, blockIdx.x * 128, blockIdx.y * 128, Ahi, Alo, Bhi, Blo, C, D, sm);
}

// fused QKV: grid (T/128, H/128, 3)
__global__ __launch_bounds__(256, 2) void hgemm_qkv_kernel(
    const __nv_bfloat16* __restrict__ Ahi, const __nv_bfloat16* __restrict__ Alo,
    const __nv_bfloat16* __restrict__ qh, const __nv_bfloat16* __restrict__ ql,
    const __nv_bfloat16* __restrict__ kh, const __nv_bfloat16* __restrict__ kl,
    const __nv_bfloat16* __restrict__ vh, const __nv_bfloat16* __restrict__ vl,
    float* __restrict__ q, float* __restrict__ k, float* __restrict__ v)
{
    extern __shared__ char sm[];
    const __nv_bfloat16 *Bhi, *Blo;
    float* C;
    if (blockIdx.z == 0)      { Bhi = qh; Blo = ql; C = q; }
    else if (blockIdx.z == 1) { Bhi = kh; Blo = kl; C = k; }
    else                      { Bhi = vh; Blo = vl; C = v; }
    gemm_core(H_, H_, blockIdx.x * 128, blockIdx.y * 128, Ahi, Alo, Bhi, Blo, C, nullptr, sm);
}

// ---------------- fused split of all 5 weight matrices ----------------
__device__ __forceinline__ void split4(const float* __restrict__ in, size_t i,
                                       __nv_bfloat16* __restrict__ hi,
                                       __nv_bfloat16* __restrict__ lo)
{
    float4 v = *(const float4*)(in + i);
    __nv_bfloat16 hx = __float2bfloat16(v.x), hy = __float2bfloat16(v.y);
    __nv_bfloat16 hz = __float2bfloat16(v.z), hw = __float2bfloat16(v.w);
    __nv_bfloat162 h01 = __halves2bfloat162(hx, hy);
    __nv_bfloat162 h23 = __halves2bfloat162(hz, hw);
    __nv_bfloat162 l01 = __halves2bfloat162(__float2bfloat16(v.x - __bfloat162float(hx)),
                                            __float2bfloat16(v.y - __bfloat162float(hy)));
    __nv_bfloat162 l23 = __halves2bfloat162(__float2bfloat16(v.z - __bfloat162float(hz)),
                                            __float2bfloat16(v.w - __bfloat162float(hw)));
    *(uint2*)(hi + i) = make_uint2(*(uint32_t*)&h01, *(uint32_t*)&h23);
    *(uint2*)(lo + i) = make_uint2(*(uint32_t*)&l01, *(uint32_t*)&l23);
}

#define SPLIT_BLKS_SMALL (H_*H_/1024)               // 1024
#define SPLIT_BLKS_LM    ((int)((size_t)V_*H_/1024)) // 32000
#define SPLIT_BLKS_ALL   (4*SPLIT_BLKS_SMALL + SPLIT_BLKS_LM)

__global__ __launch_bounds__(256) void split_all_kernel(
    const float* __restrict__ Wq, const float* __restrict__ Wk,
    const float* __restrict__ Wv, const float* __restrict__ Wo,
    const float* __restrict__ lmw,
    __nv_bfloat16* __restrict__ wqhi, __nv_bfloat16* __restrict__ wqlo,
    __nv_bfloat16* __restrict__ wkhi, __nv_bfloat16* __restrict__ wklo,
    __nv_bfloat16* __restrict__ wvhi, __nv_bfloat16* __restrict__ wvlo,
    __nv_bfloat16* __restrict__ wohi, __nv_bfloat16* __restrict__ wolo,
    __nv_bfloat16* __restrict__ lmhi, __nv_bfloat16* __restrict__ lmlo)
{
    int b = blockIdx.x;
    const float* src; __nv_bfloat16 *hi, *lo; int base;
    if      (b < 1 * SPLIT_BLKS_SMALL) { src = Wq;  hi = wqhi; lo = wqlo; base = 0; }
    else if (b < 2 * SPLIT_BLKS_SMALL) { src = Wk;  hi = wkhi; lo = wklo; base = SPLIT_BLKS_SMALL; }
    else if (b < 3 * SPLIT_BLKS_SMALL) { src = Wv;  hi = wvhi; lo = wvlo; base = 2 * SPLIT_BLKS_SMALL; }
    else if (b < 4 * SPLIT_BLKS_SMALL) { src = Wo;  hi = wohi; lo = wolo; base = 3 * SPLIT_BLKS_SMALL; }
    else                               { src = lmw; hi = lmhi; lo = lmlo; base = 4 * SPLIT_BLKS_SMALL; }
    size_t i = ((size_t)(b - base) * 256 + threadIdx.x) * 4;
    split4(src, i, hi, lo);
}

// ---------------- inj[n] = concat(hs0[ctx], hs1[ctx]) @ fc_w ----------------
__global__ void inj_kernel(const float* __restrict__ hs, const int* __restrict__ anchors,
                           const float* __restrict__ fcw, float* __restrict__ inj)
{
    int n = blockIdx.x;
    int c = blockIdx.y * 128 + threadIdx.x;
    int a = anchors[n];
    int ctx = a - 1; if (ctx < 0) ctx = 0;
    const float* h0 = hs + (size_t)ctx * H_;
    const float* h1 = hs + (size_t)S_ * H_ + (size_t)ctx * H_;
    float acc = 0.f;
    for (int k = 0; k < H_; k++) acc += h0[k] * fcw[(size_t)k * H_ + c];
    for (int k = 0; k < H_; k++) acc += h1[k] * fcw[(size_t)(H_ + k) * H_ + c];
    inj[(size_t)n * H_ + c] = acc;
}

// ---------------- fused: h = embed[.] (+inj), pos, rmsnorm -> xhi/xlo ----------------
__global__ __launch_bounds__(256) void buildnorm_kernel(
    const int* __restrict__ ids, const int* __restrict__ anchors,
    const float* __restrict__ embed, const float* __restrict__ inj,
    const float* __restrict__ w,
    float* __restrict__ h, int* __restrict__ pos,
    __nv_bfloat16* __restrict__ hi, __nv_bfloat16* __restrict__ lo)
{
    int t = blockIdx.x;
    int tok;
    const float* add = nullptr;
    if (t < S_) {
        tok = ids[t];
        if (threadIdx.x == 0) pos[t] = t;
    } else {
        int n = (t - S_) / BS_, j = (t - S_) % BS_;
        int a = anchors[n];
        int ap = a; if (ap < 0) ap = 0; if (ap > S_-1) ap = S_-1;
        tok = (j == 0) ? ids[ap] : 0;   // MASK_TOKEN = 0
        add = inj + (size_t)n * H_;
        if (threadIdx.x == 0) pos[t] = a + j;
    }
    int c = threadIdx.x * 4;
    float4 v = *(const float4*)(embed + (size_t)tok * H_ + c);
    if (add) {
        float4 a4 = *(const float4*)(add + c);
        v.x += a4.x; v.y += a4.y; v.z += a4.z; v.w += a4.w;
    }
    *(float4*)(h + (size_t)t * H_ + c) = v;

    float ss = v.x * v.x + v.y * v.y + v.z * v.z + v.w * v.w;
    ss = wsum(ss);
    __shared__ float sred[8];
    if ((threadIdx.x & 31) == 0) sred[threadIdx.x >> 5] = ss;
    __syncthreads();
    float tot = 0.f;
#pragma unroll
    for (int i = 0; i < 8; i++) tot += sred[i];
    float inv = rsqrtf(tot * (1.0f / H_) + 1e-6f);
    float4 wv = *(const float4*)(w + c);
    float o0 = v.x * inv * wv.x, o1 = v.y * inv * wv.y;
    float o2 = v.z * inv * wv.z, o3 = v.w * inv * wv.w;
    __nv_bfloat16 h0 = __float2bfloat16(o0), h1b = __float2bfloat16(o1);
    __nv_bfloat16 h2 = __float2bfloat16(o2), h3 = __float2bfloat16(o3);
    __nv_bfloat162 p01 = __halves2bfloat162(h0, h1b), p23 = __halves2bfloat162(h2, h3);
    __nv_bfloat162 q01 = __halves2bfloat162(__float2bfloat16(o0 - __bfloat162float(h0)),
                                            __float2bfloat16(o1 - __bfloat162float(h1b)));
    __nv_bfloat162 q23 = __halves2bfloat162(__float2bfloat16(o2 - __bfloat162float(h2)),
                                            __float2bfloat16(o3 - __bfloat162float(h3)));
    *(uint2*)(hi + (size_t)t * H_ + c) = make_uint2(*(uint32_t*)&p01, *(uint32_t*)&p23);
    *(uint2*)(lo + (size_t)t * H_ + c) = make_uint2(*(uint32_t*)&q01, *(uint32_t*)&q23);
}

// ---------------- rmsnorm with fused bf16 hi/lo split output ----------------
__global__ __launch_bounds__(256) void rmsnorm_split_kernel(const float* __restrict__ in,
                                                            const float* __restrict__ w,
                                                            __nv_bfloat16* __restrict__ hi,
                                                            __nv_bfloat16* __restrict__ lo)
{
    int t = blockIdx.x;
    const float* r = in + (size_t)t * H_;
    float ss = 0.f;
    for (int c = threadIdx.x; c < H_; c += 256) { float v = r[c]; ss += v * v; }
    ss = wsum(ss);
    __shared__ float sred[8];
    if ((threadIdx.x & 31) == 0) sred[threadIdx.x >> 5] = ss;
    __syncthreads();
    float tot = 0.f;
#pragma unroll
    for (int i = 0; i < 8; i++) tot += sred[i];
    float inv = rsqrtf(tot * (1.0f / H_) + 1e-6f);
    for (int c = threadIdx.x; c < H_; c += 256) {
        float xv = r[c] * inv * w[c];
        __nv_bfloat16 hb = __float2bfloat16(xv);
        hi[(size_t)t * H_ + c] = hb;
        lo[(size_t)t * H_ + c] = __float2bfloat16(xv - __bfloat162float(hb));
    }
}

// ---------------- RoPE on q and k in-place (fp32, matches reference dtype) ----------------
__global__ void rope_kernel(float* __restrict__ q, float* __restrict__ k,
                            const int* __restrict__ pos)
{
    int t = blockIdx.x;
    int idx = threadIdx.x;          // 0..511
    int hh = idx >> 6, i = idx & 63;
    int p = pos[t];
    // inv_freq = 10000^{-i/64} = exp2(-i/64 * log2(10000))
    float inv_freq = exp2f(-(float)i * (13.287712379549449f / 64.0f));
    float ang = (float)p * inv_freq;
    float s, c;
    sincosf(ang, &s, &c);
    size_t b = (size_t)t * H_ + hh * DH_ + i;
    float x1 = q[b], x2 = q[b + 64];
    q[b]      = x1 * c - x2 * s;
    q[b + 64] = x2 * c + x1 * s;
    x1 = k[b]; x2 = k[b + 64];
    k[b]      = x1 * c - x2 * s;
    k[b + 64] = x2 * c + x1 * s;
}

// ---------------- transpose in[Kd][Nd] -> out[Nd][Kd] ----------------
__global__ void transposeKN_kernel(const float* __restrict__ in, float* __restrict__ out,
                                   int Kd, int Nd)
{
    __shared__ float tile[32][33];
    int n0 = blockIdx.x * 32;
    int k0 = blockIdx.y * 32;
    int x = threadIdx.x, y0 = threadIdx.y;   // block (32, 8)
#pragma unroll
    for (int dy = 0; dy < 32; dy += 8)
        tile[y0 + dy][x] = in[(size_t)(k0 + y0 + dy) * Nd + n0 + x];
    __syncthreads();
#pragma unroll
    for (int dy = 0; dy < 32; dy += 8)
        out[(size_t)(n0 + y0 + dy) * Kd + k0 + x] = tile[x][y0 + dy];
}

// ---------------- attention: 8 queries x 1 head per block, 128 threads ----------------
__global__ __launch_bounds__(128) void attn_kernel(
    const float* __restrict__ q, const float* __restrict__ kT,
    const float* __restrict__ v, const int* __restrict__ anchors,
    __nv_bfloat16* __restrict__ ohi, __nv_bfloat16* __restrict__ olo)
{
    __shared__ float qs[QB][DH_];
    __shared__ float pbuf[QB][128];
    __shared__ float redm[QB][4];
    __shared__ float reds[QB][4];

    int h   = blockIdx.y;
    int t0  = blockIdx.x * QB;
    int tid = threadIdx.x;
    int w   = tid >> 5, lane = tid & 31;

#pragma unroll
    for (int qi = 0; qi < QB; qi++)
        qs[qi][tid] = q[(size_t)(t0 + qi) * H_ + h * DH_ + tid] * SCALE;
    __syncthreads();

    float m[QB], l[QB], acc[QB];
#pragma unroll
    for (int qi = 0; qi < QB; qi++) { m[qi] = -INFINITY; l[qi] = 0.f; acc[qi] = 0.f; }

    int lo[QB], hi[QB];

    auto proc = [&](int base, int cnt) {
        int k = base + tid;
        bool act = tid < cnt;
        float s[QB];
#pragma unroll
        for (int qi = 0; qi < QB; qi++) s[qi] = -INFINITY;
        if (act) {
#pragma unroll
            for (int qi = 0; qi < QB; qi++) s[qi] = 0.f;
            const float* kp = kT + (size_t)(h * DH_) * T_ + k;
            for (int d = 0; d < DH_; d += 4) {
                float kv0 = kp[(size_t)(d + 0) * T_];
                float kv1 = kp[(size_t)(d + 1) * T_];
                float kv2 = kp[(size_t)(d + 2) * T_];
                float kv3 = kp[(size_t)(d + 3) * T_];
#pragma unroll
                for (int qi = 0; qi < QB; qi++) {
                    float4 qv = *(const float4*)&qs[qi][d];
                    s[qi] += qv.x * kv0 + qv.y * kv1 + qv.z * kv2 + qv.w * kv3;
                }
            }
#pragma unroll
            for (int qi = 0; qi < QB; qi++)
                if (k < lo[qi] || k > hi[qi]) s[qi] = -INFINITY;
        }
        __syncthreads();
#pragma unroll
        for (int qi = 0; qi < QB; qi++) {
            float x = wmax(s[qi]);
            if (lane == 0) redm[qi][w] = x;
        }
        __syncthreads();
        float nm[QB];
#pragma unroll
        for (int qi = 0; qi < QB; qi++) {
            float cm = fmaxf(fmaxf(redm[qi][0], redm[qi][1]), fmaxf(redm[qi][2], redm[qi][3]));
            nm[qi] = fmaxf(m[qi], cm);
            float p = (s[qi] == -INFINITY) ? 0.f : expf(s[qi] - nm[qi]);
            pbuf[qi][tid] = p;
            float sp = wsum(p);
            if (lane == 0) reds[qi][w] = sp;
        }
        __syncthreads();
#pragma unroll
        for (int qi = 0; qi < QB; qi++) {
            float f = (m[qi] == -INFINITY) ? 0.f : expf(m[qi] - nm[qi]);
            float cs = reds[qi][0] + reds[qi][1] + reds[qi][2] + reds[qi][3];
            l[qi] = l[qi] * f + cs;
            acc[qi] *= f;
            m[qi] = nm[qi];
        }
        const float* vp = v + (size_t)base * H_ + h * DH_ + tid;
        for (int j = 0; j < cnt; j += 4) {
            float vv0 = vp[(size_t)(j + 0) * H_];
            float vv1 = vp[(size_t)(j + 1) * H_];
            float vv2 = vp[(size_t)(j + 2) * H_];
            float vv3 = vp[(size_t)(j + 3) * H_];
#pragma unroll
            for (int qi = 0; qi < QB; qi++) {
                float4 pv = *(const float4*)&pbuf[qi][j];
                acc[qi] += pv.x * vv0 + pv.y * vv1 + pv.z * vv2 + pv.w * vv3;
            }
        }
    };

    if (t0 < S_) {
#pragma unroll
        for (int qi = 0; qi < QB; qi++) { lo[qi] = 0; hi[qi] = t0 + qi; }
        for (int base = 0; base <= t0 + QB - 1; base += 128) proc(base, 128);
    } else {
        int nb = (t0 - S_) / BS_;
        int a  = anchors[nb];
        int ws = a - W_ + 1; if (ws < 0) ws = 0;
        int we = a - 1;
#pragma unroll
        for (int qi = 0; qi < QB; qi++) { lo[qi] = ws; hi[qi] = we; }
        for (int base = (ws >> 7) << 7; base <= we; base += 128) proc(base, 128);
        int kb = S_ + nb * BS_;
#pragma unroll
        for (int qi = 0; qi < QB; qi++) { lo[qi] = kb; hi[qi] = kb + BS_ - 1; }
        proc(kb, BS_);
    }

#pragma unroll
    for (int qi = 0; qi < QB; qi++) {
        float o = acc[qi] / l[qi];
        size_t idx = (size_t)(t0 + qi) * H_ + h * DH_ + tid;
        __nv_bfloat16 hb = __float2bfloat16(o);
        ohi[idx] = hb;
        olo[idx] = __float2bfloat16(o - __bfloat162float(hb));
    }
}

// ---------------- launch ----------------
extern "C" void kernel_launch(void* const* d_in, const int* in_sizes, int n_in,
                              void* d_out, int out_size)
{
    const int*   ids     = (const int*)  d_in[0];
    const float* hs      = (const float*)d_in[1];
    const int*   anchors = (const int*)  d_in[2];
    // d_in[3] block_keep_mask: all-true by construction; intentionally unused
    const float* embed   = (const float*)d_in[4];
    const float* Wq      = (const float*)d_in[5];
    const float* Wk      = (const float*)d_in[6];
    const float* Wv      = (const float*)d_in[7];
    const float* Wo      = (const float*)d_in[8];
    const float* fcw     = (const float*)d_in[9];
    const float* lmw     = (const float*)d_in[10];
    const float* normw   = (const float*)d_in[11];

    float *h, *q, *k, *v, *kT, *h2, *inj;
    int* pos;
    __nv_bfloat16 *xhi, *xlo, *aohi, *aolo;
    __nv_bfloat16 *wqhi, *wqlo, *wkhi, *wklo, *wvhi, *wvlo, *wohi, *wolo, *lmhi, *lmlo;
    cudaGetSymbolAddress((void**)&h,    g_h);
    cudaGetSymbolAddress((void**)&q,    g_q);
    cudaGetSymbolAddress((void**)&k,    g_k);
    cudaGetSymbolAddress((void**)&v,    g_v);
    cudaGetSymbolAddress((void**)&kT,   g_kT);
    cudaGetSymbolAddress((void**)&h2,   g_h2);
    cudaGetSymbolAddress((void**)&inj,  g_inj);
    cudaGetSymbolAddress((void**)&pos,  g_pos);
    cudaGetSymbolAddress((void**)&xhi,  g_xhi);
    cudaGetSymbolAddress((void**)&xlo,  g_xlo);
    cudaGetSymbolAddress((void**)&aohi, g_aohi);
    cudaGetSymbolAddress((void**)&aolo, g_aolo);
    cudaGetSymbolAddress((void**)&wqhi, g_wqhi);
    cudaGetSymbolAddress((void**)&wqlo, g_wqlo);
    cudaGetSymbolAddress((void**)&wkhi, g_wkhi);
    cudaGetSymbolAddress((void**)&wklo, g_wklo);
    cudaGetSymbolAddress((void**)&wvhi, g_wvhi);
    cudaGetSymbolAddress((void**)&wvlo, g_wvlo);
    cudaGetSymbolAddress((void**)&wohi, g_wohi);
    cudaGetSymbolAddress((void**)&wolo, g_wolo);
    cudaGetSymbolAddress((void**)&lmhi, g_lmhi);
    cudaGetSymbolAddress((void**)&lmlo, g_lmlo);

    cudaFuncSetAttribute(hgemm_kernel, cudaFuncAttributeMaxDynamicSharedMemorySize, HS_TOTAL);
    cudaFuncSetAttribute(hgemm_qkv_kernel, cudaFuncAttributeMaxDynamicSharedMemorySize, HS_TOTAL);

    // 1: all weight splits in one launch
    split_all_kernel<<<SPLIT_BLKS_ALL, 256>>>(Wq, Wk, Wv, Wo, lmw,
                                              wqhi, wqlo, wkhi, wklo, wvhi, wvlo,
                                              wohi, wolo, lmhi, lmlo);
    // 2
    inj_kernel<<<dim3(N_, H_ / 128), 128>>>(hs, anchors, fcw, inj);
    // 3: build h + rmsnorm + split fused
    buildnorm_kernel<<<T_, 256>>>(ids, anchors, embed, inj, normw, h, pos, xhi, xlo);
    // 4: fused QKV GEMM  (profiled launch)
    hgemm_qkv_kernel<<<dim3(T_ / 128, H_ / 128, 3), 256, HS_TOTAL>>>(
        xhi, xlo, wqhi, wqlo, wkhi, wklo, wvhi, wvlo, q, k, v);
    // 5
    rope_kernel<<<T_, 512>>>(q, k, pos);
    // 6
    transposeKN_kernel<<<dim3(H_ / 32, T_ / 32), dim3(32, 8)>>>(k, kT, T_, H_);
    // 7
    attn_kernel<<<dim3(T_ / QB, NH_), 128>>>(q, kT, v, anchors, aohi, aolo);
    // 8
    hgemm_kernel<<<dim3(T_ / 128, H_ / 128), 256, HS_TOTAL>>>(
        T_, H_, H_, aohi, aolo, wohi, wolo, h2, h);   // +residual
    // 9
    rmsnorm_split_kernel<<<T_, 256>>>(h2, normw, xhi, xlo);
    // 10
    hgemm_kernel<<<dim3(T_ / 128, V_ / 128), 256, HS_TOTAL>>>(
        T_, V_, H_, xhi, xlo, lmhi, lmlo, (float*)d_out, nullptr);
}

// round 10
// speedup vs baseline: 2.5785x; 1.0225x over previous
#include <cuda_runtime.h>
#include <cuda_bf16.h>
#include <math.h>
#include <stdint.h>

#define S_  2048
#define N_  64
#define BS_ 16
#define W_  512
#define NH_ 8
#define H_  1024
#define V_  32000
#define DH_ 128
#define T_  3072
#define QB  16
#define SCALE 0.08838834764831845f  // 1/sqrt(128)

// ---------------- scratch (device globals; no allocation) ----------------
__device__ float g_h [T_*H_];
__device__ float g_q [T_*H_];
__device__ float g_k [T_*H_];
__device__ float g_v [T_*H_];
__device__ float g_kT[T_*H_];
__device__ float g_h2[T_*H_];
__device__ float g_inj[N_*H_];
__device__ int   g_pos[T_];
__device__ __nv_bfloat16 g_xhi[T_*H_], g_xlo[T_*H_];
__device__ __nv_bfloat16 g_aohi[T_*H_], g_aolo[T_*H_];
__device__ __nv_bfloat16 g_wqhi[H_*H_], g_wqlo[H_*H_];
__device__ __nv_bfloat16 g_wkhi[H_*H_], g_wklo[H_*H_];
__device__ __nv_bfloat16 g_wvhi[H_*H_], g_wvlo[H_*H_];
__device__ __nv_bfloat16 g_wohi[H_*H_], g_wolo[H_*H_];
__device__ __nv_bfloat16 g_lmhi[(size_t)V_*H_], g_lmlo[(size_t)V_*H_];

// ---------------- helpers ----------------
__device__ __forceinline__ float wsum(float v){
#pragma unroll
    for (int o=16;o>0;o>>=1) v += __shfl_xor_sync(0xffffffffu, v, o);
    return v;
}
__device__ __forceinline__ float wmax(float v){
#pragma unroll
    for (int o=16;o>0;o>>=1) v = fmaxf(v, __shfl_xor_sync(0xffffffffu, v, o));
    return v;
}
__device__ __forceinline__ uint32_t smem_u32(const void* p){
    uint32_t a;
    asm("{ .reg .u64 t; cvta.to.shared.u64 t, %1; cvt.u32.u64 %0, t; }" : "=r"(a) : "l"(p));
    return a;
}
__device__ __forceinline__ void ldsm4(uint32_t& r0, uint32_t& r1, uint32_t& r2, uint32_t& r3,
                                      uint32_t addr){
    asm volatile("ldmatrix.sync.aligned.m8n8.x4.shared.b16 {%0,%1,%2,%3}, [%4];"
                 : "=r"(r0), "=r"(r1), "=r"(r2), "=r"(r3) : "r"(addr));
}
__device__ __forceinline__ void ldsm4t(uint32_t& r0, uint32_t& r1, uint32_t& r2, uint32_t& r3,
                                       uint32_t addr){
    asm volatile("ldmatrix.sync.aligned.m8n8.x4.trans.shared.b16 {%0,%1,%2,%3}, [%4];"
                 : "=r"(r0), "=r"(r1), "=r"(r2), "=r"(r3) : "r"(addr));
}
__device__ __forceinline__ void mma_bf16(float* c, const uint32_t* a, uint32_t b0, uint32_t b1){
    asm volatile("mma.sync.aligned.m16n8k16.row.col.f32.bf16.bf16.f32 "
                 "{%0,%1,%2,%3}, {%4,%5,%6,%7}, {%8,%9}, {%0,%1,%2,%3};"
                 : "+f"(c[0]), "+f"(c[1]), "+f"(c[2]), "+f"(c[3])
                 : "r"(a[0]), "r"(a[1]), "r"(a[2]), "r"(a[3]), "r"(b0), "r"(b1));
}
__device__ __forceinline__ void cp16(uint32_t saddr, const void* g){
    asm volatile("cp.async.cg.shared.global [%0], [%1], 16;"
                 :: "r"(saddr), "l"(__cvta_generic_to_global(g)));
}
__device__ __forceinline__ void cp_commit(){ asm volatile("cp.async.commit_group;" ::: "memory"); }
template<int Nn> __device__ __forceinline__ void cp_wait(){
    asm volatile("cp.async.wait_group %0;" :: "n"(Nn) : "memory");
}

// ================ bf16-split tensor-core GEMM core ================
#define LDSR 40
#define LDSB 136
#define ST_AHI 0
#define ST_ALO 10240
#define ST_BHI 20480
#define ST_BLO 29184
#define ST_SIZE 37888
#define NSTAGE 3
#define HS_TOTAL (NSTAGE*ST_SIZE)      // 113664 B

__device__ __forceinline__ void gemm_core(
    int Nc, int K, int crow, int ccol,
    const __nv_bfloat16* __restrict__ Ahi, const __nv_bfloat16* __restrict__ Alo,
    const __nv_bfloat16* __restrict__ Bhi, const __nv_bfloat16* __restrict__ Blo,
    float* __restrict__ C, const float* __restrict__ D, char* sm)
{
    uint32_t sb = smem_u32(sm);
    int tid  = threadIdx.x, lane = tid & 31, wid = tid >> 5;
    int wm   = (wid & 1) * 64,  wn   = (wid >> 1) * 32;

    float acc[4][4][4];
#pragma unroll
    for (int i = 0; i < 4; i++)
#pragma unroll
        for (int j = 0; j < 4; j++)
#pragma unroll
            for (int r = 0; r < 4; r++) acc[i][j][r] = 0.f;

    uint32_t a_off = ((wm + (lane & 15)) * LDSR + (lane >> 4) * 8) * 2;
    uint32_t b_off = (uint32_t)(((((lane >> 3) & 1) * 8 + (lane & 7)) * LDSB
                                 + wn + (lane >> 4) * 8) * 2);
    int kq = K / 32;

    auto issue = [&](int ch){
        uint32_t st = sb + (ch % NSTAGE) * ST_SIZE;
        int kb = ch * 32;
#pragma unroll
        for (int r = 0; r < 2; r++) {
            int seg = tid + r * 256;
            int ar = seg >> 2, ac = (seg & 3) * 8;
            size_t ga = (size_t)(crow + ar) * K + kb + ac;
            uint32_t sa = st + ST_AHI + (uint32_t)(ar * LDSR + ac) * 2;
            cp16(sa, Ahi + ga);
            cp16(sa + (ST_ALO - ST_AHI), Alo + ga);
            int br = seg >> 4, bcx = (seg & 15) * 8;
            size_t gb = (size_t)(kb + br) * Nc + ccol + bcx;
            uint32_t sbo = st + ST_BHI + (uint32_t)(br * LDSB + bcx) * 2;
            cp16(sbo, Bhi + gb);
            cp16(sbo + (ST_BLO - ST_BHI), Blo + gb);
        }
    };

    issue(0); cp_commit();
    issue(1); cp_commit();

    for (int ch = 0; ch < kq; ch++) {
        cp_wait<NSTAGE - 2>();
        __syncthreads();
        if (ch + 2 < kq) issue(ch + 2);
        cp_commit();

        uint32_t base = sb + (ch % NSTAGE) * ST_SIZE;
#pragma unroll
        for (int ks = 0; ks < 2; ks++) {
            uint32_t bh4[2][4], bl4[2][4];
#pragma unroll
            for (int p = 0; p < 2; p++) {
                uint32_t adr = base + ST_BHI + b_off + ks * (16 * LDSB * 2) + p * 32;
                ldsm4t(bh4[p][0], bh4[p][1], bh4[p][2], bh4[p][3], adr);
                ldsm4t(bl4[p][0], bl4[p][1], bl4[p][2], bl4[p][3], adr + (ST_BLO - ST_BHI));
            }
#pragma unroll
            for (int mi = 0; mi < 4; mi++) {
                uint32_t ah[4], al[4];
                uint32_t adr = base + ST_AHI + a_off + mi * (16 * LDSR * 2) + ks * 32;
                ldsm4(ah[0], ah[1], ah[2], ah[3], adr);
                ldsm4(al[0], al[1], al[2], al[3], adr + (ST_ALO - ST_AHI));
#pragma unroll
                for (int ni = 0; ni < 4; ni++) {
                    uint32_t b0h = bh4[ni >> 1][(ni & 1) * 2], b1h = bh4[ni >> 1][(ni & 1) * 2 + 1];
                    uint32_t b0l = bl4[ni >> 1][(ni & 1) * 2], b1l = bl4[ni >> 1][(ni & 1) * 2 + 1];
                    mma_bf16(acc[mi][ni], ah, b0h, b1h);
                    mma_bf16(acc[mi][ni], ah, b0l, b1l);
                    mma_bf16(acc[mi][ni], al, b0h, b1h);
                }
            }
        }
    }

    // epilogue
#pragma unroll
    for (int mi = 0; mi < 4; mi++)
#pragma unroll
        for (int ni = 0; ni < 4; ni++) {
            size_t r0 = (size_t)(crow + wm + mi * 16 + (lane >> 2));
            int    cc = ccol + wn + ni * 8 + (lane & 3) * 2;
            float2 v0 = make_float2(acc[mi][ni][0], acc[mi][ni][1]);
            float2 v1 = make_float2(acc[mi][ni][2], acc[mi][ni][3]);
            if (D) {
                const float2 d0 = *(const float2*)(D + r0 * Nc + cc);
                const float2 d1 = *(const float2*)(D + (r0 + 8) * Nc + cc);
                v0.x += d0.x; v0.y += d0.y; v1.x += d1.x; v1.y += d1.y;
            }
            *(float2*)(C + r0 * Nc + cc)       = v0;
            *(float2*)(C + (r0 + 8) * Nc + cc) = v1;
        }
}

__global__ __launch_bounds__(256, 2) void hgemm_kernel(
    int M, int Nc, int K,
    const __nv_bfloat16* __restrict__ Ahi, const __nv_bfloat16* __restrict__ Alo,
    const __nv_bfloat16* __restrict__ Bhi, const __nv_bfloat16* __restrict__ Blo,
    float* __restrict__ C, const float* __restrict__ D)
{
    extern __shared__ char sm[];
    gemm_core(Nc, K, blockIdx.x * 128, blockIdx.y * 128, Ahi, Alo, Bhi, Blo, C, D, sm);
}

// fused QKV: grid (T/128, H/128, 3)
__global__ __launch_bounds__(256, 2) void hgemm_qkv_kernel(
    const __nv_bfloat16* __restrict__ Ahi, const __nv_bfloat16* __restrict__ Alo,
    const __nv_bfloat16* __restrict__ qh, const __nv_bfloat16* __restrict__ ql,
    const __nv_bfloat16* __restrict__ kh, const __nv_bfloat16* __restrict__ kl,
    const __nv_bfloat16* __restrict__ vh, const __nv_bfloat16* __restrict__ vl,
    float* __restrict__ q, float* __restrict__ k, float* __restrict__ v)
{
    extern __shared__ char sm[];
    const __nv_bfloat16 *Bhi, *Blo;
    float* C;
    if (blockIdx.z == 0)      { Bhi = qh; Blo = ql; C = q; }
    else if (blockIdx.z == 1) { Bhi = kh; Blo = kl; C = k; }
    else                      { Bhi = vh; Blo = vl; C = v; }
    gemm_core(H_, H_, blockIdx.x * 128, blockIdx.y * 128, Ahi, Alo, Bhi, Blo, C, nullptr, sm);
}

// ---------------- fused split of all 5 weight matrices ----------------
__device__ __forceinline__ void split4(const float* __restrict__ in, size_t i,
                                       __nv_bfloat16* __restrict__ hi,
                                       __nv_bfloat16* __restrict__ lo)
{
    float4 v = *(const float4*)(in + i);
    __nv_bfloat16 hx = __float2bfloat16(v.x), hy = __float2bfloat16(v.y);
    __nv_bfloat16 hz = __float2bfloat16(v.z), hw = __float2bfloat16(v.w);
    __nv_bfloat162 h01 = __halves2bfloat162(hx, hy);
    __nv_bfloat162 h23 = __halves2bfloat162(hz, hw);
    __nv_bfloat162 l01 = __halves2bfloat162(__float2bfloat16(v.x - __bfloat162float(hx)),
                                            __float2bfloat16(v.y - __bfloat162float(hy)));
    __nv_bfloat162 l23 = __halves2bfloat162(__float2bfloat16(v.z - __bfloat162float(hz)),
                                            __float2bfloat16(v.w - __bfloat162float(hw)));
    *(uint2*)(hi + i) = make_uint2(*(uint32_t*)&h01, *(uint32_t*)&h23);
    *(uint2*)(lo + i) = make_uint2(*(uint32_t*)&l01, *(uint32_t*)&l23);
}

#define SPLIT_BLKS_SMALL (H_*H_/1024)               // 1024
#define SPLIT_BLKS_LM    ((int)((size_t)V_*H_/1024)) // 32000
#define SPLIT_BLKS_ALL   (4*SPLIT_BLKS_SMALL + SPLIT_BLKS_LM)

__global__ __launch_bounds__(256) void split_all_kernel(
    const float* __restrict__ Wq, const float* __restrict__ Wk,
    const float* __restrict__ Wv, const float* __restrict__ Wo,
    const float* __restrict__ lmw,
    __nv_bfloat16* __restrict__ wqhi, __nv_bfloat16* __restrict__ wqlo,
    __nv_bfloat16* __restrict__ wkhi, __nv_bfloat16* __restrict__ wklo,
    __nv_bfloat16* __restrict__ wvhi, __nv_bfloat16* __restrict__ wvlo,
    __nv_bfloat16* __restrict__ wohi, __nv_bfloat16* __restrict__ wolo,
    __nv_bfloat16* __restrict__ lmhi, __nv_bfloat16* __restrict__ lmlo)
{
    int b = blockIdx.x;
    const float* src; __nv_bfloat16 *hi, *lo; int base;
    if      (b < 1 * SPLIT_BLKS_SMALL) { src = Wq;  hi = wqhi; lo = wqlo; base = 0; }
    else if (b < 2 * SPLIT_BLKS_SMALL) { src = Wk;  hi = wkhi; lo = wklo; base = SPLIT_BLKS_SMALL; }
    else if (b < 3 * SPLIT_BLKS_SMALL) { src = Wv;  hi = wvhi; lo = wvlo; base = 2 * SPLIT_BLKS_SMALL; }
    else if (b < 4 * SPLIT_BLKS_SMALL) { src = Wo;  hi = wohi; lo = wolo; base = 3 * SPLIT_BLKS_SMALL; }
    else                               { src = lmw; hi = lmhi; lo = lmlo; base = 4 * SPLIT_BLKS_SMALL; }
    size_t i = ((size_t)(b - base) * 256 + threadIdx.x) * 4;
    split4(src, i, hi, lo);
}

// ---------------- inj[n] = concat(hs0[ctx], hs1[ctx]) @ fc_w ----------------
__global__ void inj_kernel(const float* __restrict__ hs, const int* __restrict__ anchors,
                           const float* __restrict__ fcw, float* __restrict__ inj)
{
    int n = blockIdx.x;
    int c = blockIdx.y * 128 + threadIdx.x;
    int a = anchors[n];
    int ctx = a - 1; if (ctx < 0) ctx = 0;
    const float* h0 = hs + (size_t)ctx * H_;
    const float* h1 = hs + (size_t)S_ * H_ + (size_t)ctx * H_;
    float acc = 0.f;
    for (int k = 0; k < H_; k++) acc += h0[k] * fcw[(size_t)k * H_ + c];
    for (int k = 0; k < H_; k++) acc += h1[k] * fcw[(size_t)(H_ + k) * H_ + c];
    inj[(size_t)n * H_ + c] = acc;
}

// ---------------- fused: h = embed[.] (+inj), pos, rmsnorm -> xhi/xlo ----------------
__global__ __launch_bounds__(256) void buildnorm_kernel(
    const int* __restrict__ ids, const int* __restrict__ anchors,
    const float* __restrict__ embed, const float* __restrict__ inj,
    const float* __restrict__ w,
    float* __restrict__ h, int* __restrict__ pos,
    __nv_bfloat16* __restrict__ hi, __nv_bfloat16* __restrict__ lo)
{
    int t = blockIdx.x;
    int tok;
    const float* add = nullptr;
    if (t < S_) {
        tok = ids[t];
        if (threadIdx.x == 0) pos[t] = t;
    } else {
        int n = (t - S_) / BS_, j = (t - S_) % BS_;
        int a = anchors[n];
        int ap = a; if (ap < 0) ap = 0; if (ap > S_-1) ap = S_-1;
        tok = (j == 0) ? ids[ap] : 0;   // MASK_TOKEN = 0
        add = inj + (size_t)n * H_;
        if (threadIdx.x == 0) pos[t] = a + j;
    }
    int c = threadIdx.x * 4;
    float4 v = *(const float4*)(embed + (size_t)tok * H_ + c);
    if (add) {
        float4 a4 = *(const float4*)(add + c);
        v.x += a4.x; v.y += a4.y; v.z += a4.z; v.w += a4.w;
    }
    *(float4*)(h + (size_t)t * H_ + c) = v;

    float ss = v.x * v.x + v.y * v.y + v.z * v.z + v.w * v.w;
    ss = wsum(ss);
    __shared__ float sred[8];
    if ((threadIdx.x & 31) == 0) sred[threadIdx.x >> 5] = ss;
    __syncthreads();
    float tot = 0.f;
#pragma unroll
    for (int i = 0; i < 8; i++) tot += sred[i];
    float inv = rsqrtf(tot * (1.0f / H_) + 1e-6f);
    float4 wv = *(const float4*)(w + c);
    float o0 = v.x * inv * wv.x, o1 = v.y * inv * wv.y;
    float o2 = v.z * inv * wv.z, o3 = v.w * inv * wv.w;
    __nv_bfloat16 h0 = __float2bfloat16(o0), h1b = __float2bfloat16(o1);
    __nv_bfloat16 h2 = __float2bfloat16(o2), h3 = __float2bfloat16(o3);
    __nv_bfloat162 p01 = __halves2bfloat162(h0, h1b), p23 = __halves2bfloat162(h2, h3);
    __nv_bfloat162 q01 = __halves2bfloat162(__float2bfloat16(o0 - __bfloat162float(h0)),
                                            __float2bfloat16(o1 - __bfloat162float(h1b)));
    __nv_bfloat162 q23 = __halves2bfloat162(__float2bfloat16(o2 - __bfloat162float(h2)),
                                            __float2bfloat16(o3 - __bfloat162float(h3)));
    *(uint2*)(hi + (size_t)t * H_ + c) = make_uint2(*(uint32_t*)&p01, *(uint32_t*)&p23);
    *(uint2*)(lo + (size_t)t * H_ + c) = make_uint2(*(uint32_t*)&q01, *(uint32_t*)&q23);
}

// ---------------- rmsnorm with fused bf16 hi/lo split output (float4) ----------------
__global__ __launch_bounds__(256) void rmsnorm_split_kernel(const float* __restrict__ in,
                                                            const float* __restrict__ w,
                                                            __nv_bfloat16* __restrict__ hi,
                                                            __nv_bfloat16* __restrict__ lo)
{
    int t = blockIdx.x;
    int c = threadIdx.x * 4;
    float4 v = *(const float4*)(in + (size_t)t * H_ + c);
    float ss = v.x * v.x + v.y * v.y + v.z * v.z + v.w * v.w;
    ss = wsum(ss);
    __shared__ float sred[8];
    if ((threadIdx.x & 31) == 0) sred[threadIdx.x >> 5] = ss;
    __syncthreads();
    float tot = 0.f;
#pragma unroll
    for (int i = 0; i < 8; i++) tot += sred[i];
    float inv = rsqrtf(tot * (1.0f / H_) + 1e-6f);
    float4 wv = *(const float4*)(w + c);
    float o0 = v.x * inv * wv.x, o1 = v.y * inv * wv.y;
    float o2 = v.z * inv * wv.z, o3 = v.w * inv * wv.w;
    __nv_bfloat16 h0 = __float2bfloat16(o0), h1b = __float2bfloat16(o1);
    __nv_bfloat16 h2 = __float2bfloat16(o2), h3 = __float2bfloat16(o3);
    __nv_bfloat162 p01 = __halves2bfloat162(h0, h1b), p23 = __halves2bfloat162(h2, h3);
    __nv_bfloat162 q01 = __halves2bfloat162(__float2bfloat16(o0 - __bfloat162float(h0)),
                                            __float2bfloat16(o1 - __bfloat162float(h1b)));
    __nv_bfloat162 q23 = __halves2bfloat162(__float2bfloat16(o2 - __bfloat162float(h2)),
                                            __float2bfloat16(o3 - __bfloat162float(h3)));
    *(uint2*)(hi + (size_t)t * H_ + c) = make_uint2(*(uint32_t*)&p01, *(uint32_t*)&p23);
    *(uint2*)(lo + (size_t)t * H_ + c) = make_uint2(*(uint32_t*)&q01, *(uint32_t*)&q23);
}

// ---------------- RoPE on q and k in-place (fp32) ----------------
__global__ void rope_kernel(float* __restrict__ q, float* __restrict__ k,
                            const int* __restrict__ pos)
{
    int t = blockIdx.x;
    int idx = threadIdx.x;          // 0..511
    int hh = idx >> 6, i = idx & 63;
    int p = pos[t];
    float inv_freq = exp2f(-(float)i * (13.287712379549449f / 64.0f));
    float ang = (float)p * inv_freq;
    float s, c;
    sincosf(ang, &s, &c);
    size_t b = (size_t)t * H_ + hh * DH_ + i;
    float x1 = q[b], x2 = q[b + 64];
    q[b]      = x1 * c - x2 * s;
    q[b + 64] = x2 * c + x1 * s;
    x1 = k[b]; x2 = k[b + 64];
    k[b]      = x1 * c - x2 * s;
    k[b + 64] = x2 * c + x1 * s;
}

// ---------------- transpose in[Kd][Nd] -> out[Nd][Kd] ----------------
__global__ void transposeKN_kernel(const float* __restrict__ in, float* __restrict__ out,
                                   int Kd, int Nd)
{
    __shared__ float tile[32][33];
    int n0 = blockIdx.x * 32;
    int k0 = blockIdx.y * 32;
    int x = threadIdx.x, y0 = threadIdx.y;   // block (32, 8)
#pragma unroll
    for (int dy = 0; dy < 32; dy += 8)
        tile[y0 + dy][x] = in[(size_t)(k0 + y0 + dy) * Nd + n0 + x];
    __syncthreads();
#pragma unroll
    for (int dy = 0; dy < 32; dy += 8)
        out[(size_t)(n0 + y0 + dy) * Kd + k0 + x] = tile[x][y0 + dy];
}

// ---------------- attention: 16 queries x 1 head per block, 128 threads ----------------
__global__ __launch_bounds__(128) void attn_kernel(
    const float* __restrict__ q, const float* __restrict__ kT,
    const float* __restrict__ v, const int* __restrict__ anchors,
    __nv_bfloat16* __restrict__ ohi, __nv_bfloat16* __restrict__ olo)
{
    __shared__ float qs[QB][DH_];
    __shared__ float pbuf[QB][128];
    __shared__ float redm[QB][4];
    __shared__ float reds[QB][4];

    int h   = blockIdx.y;
    int t0  = blockIdx.x * QB;
    int tid = threadIdx.x;
    int w   = tid >> 5, lane = tid & 31;

#pragma unroll
    for (int qi = 0; qi < QB; qi++)
        qs[qi][tid] = q[(size_t)(t0 + qi) * H_ + h * DH_ + tid] * SCALE;
    __syncthreads();

    float m[QB], l[QB], acc[QB];
#pragma unroll
    for (int qi = 0; qi < QB; qi++) { m[qi] = -INFINITY; l[qi] = 0.f; acc[qi] = 0.f; }

    int lo[QB], hi[QB];

    auto proc = [&](int base, int cnt) {
        int k = base + tid;
        bool act = tid < cnt;
        float s[QB];
#pragma unroll
        for (int qi = 0; qi < QB; qi++) s[qi] = -INFINITY;
        if (act) {
#pragma unroll
            for (int qi = 0; qi < QB; qi++) s[qi] = 0.f;
            const float* kp = kT + (size_t)(h * DH_) * T_ + k;
            for (int d = 0; d < DH_; d += 4) {
                float kv0 = kp[(size_t)(d + 0) * T_];
                float kv1 = kp[(size_t)(d + 1) * T_];
                float kv2 = kp[(size_t)(d + 2) * T_];
                float kv3 = kp[(size_t)(d + 3) * T_];
#pragma unroll
                for (int qi = 0; qi < QB; qi++) {
                    float4 qv = *(const float4*)&qs[qi][d];
                    s[qi] += qv.x * kv0 + qv.y * kv1 + qv.z * kv2 + qv.w * kv3;
                }
            }
#pragma unroll
            for (int qi = 0; qi < QB; qi++)
                if (k < lo[qi] || k > hi[qi]) s[qi] = -INFINITY;
        }
        __syncthreads();
#pragma unroll
        for (int qi = 0; qi < QB; qi++) {
            float x = wmax(s[qi]);
            if (lane == 0) redm[qi][w] = x;
        }
        __syncthreads();
        float nm[QB];
#pragma unroll
        for (int qi = 0; qi < QB; qi++) {
            float cm = fmaxf(fmaxf(redm[qi][0], redm[qi][1]), fmaxf(redm[qi][2], redm[qi][3]));
            nm[qi] = fmaxf(m[qi], cm);
            float p = (s[qi] == -INFINITY) ? 0.f : expf(s[qi] - nm[qi]);
            pbuf[qi][tid] = p;
            float sp = wsum(p);
            if (lane == 0) reds[qi][w] = sp;
        }
        __syncthreads();
#pragma unroll
        for (int qi = 0; qi < QB; qi++) {
            float f = (m[qi] == -INFINITY) ? 0.f : expf(m[qi] - nm[qi]);
            float cs = reds[qi][0] + reds[qi][1] + reds[qi][2] + reds[qi][3];
            l[qi] = l[qi] * f + cs;
            acc[qi] *= f;
            m[qi] = nm[qi];
        }
        const float* vp = v + (size_t)base * H_ + h * DH_ + tid;
        for (int j = 0; j < cnt; j += 4) {
            float vv0 = vp[(size_t)(j + 0) * H_];
            float vv1 = vp[(size_t)(j + 1) * H_];
            float vv2 = vp[(size_t)(j + 2) * H_];
            float vv3 = vp[(size_t)(j + 3) * H_];
#pragma unroll
            for (int qi = 0; qi < QB; qi++) {
                float4 pv = *(const float4*)&pbuf[qi][j];
                acc[qi] += pv.x * vv0 + pv.y * vv1 + pv.z * vv2 + pv.w * vv3;
            }
        }
    };

    if (t0 < S_) {
#pragma unroll
        for (int qi = 0; qi < QB; qi++) { lo[qi] = 0; hi[qi] = t0 + qi; }
        for (int base = 0; base <= t0 + QB - 1; base += 128) proc(base, 128);
    } else {
        int nb = (t0 - S_) / BS_;       // QB == BS_: one block per CTA
        int a  = anchors[nb];
        int ws = a - W_ + 1; if (ws < 0) ws = 0;
        int we = a - 1;
#pragma unroll
        for (int qi = 0; qi < QB; qi++) { lo[qi] = ws; hi[qi] = we; }
        for (int base = (ws >> 7) << 7; base <= we; base += 128) proc(base, 128);
        int kb = S_ + nb * BS_;
#pragma unroll
        for (int qi = 0; qi < QB; qi++) { lo[qi] = kb; hi[qi] = kb + BS_ - 1; }
        proc(kb, BS_);
    }

#pragma unroll
    for (int qi = 0; qi < QB; qi++) {
        float o = acc[qi] / l[qi];
        size_t idx = (size_t)(t0 + qi) * H_ + h * DH_ + tid;
        __nv_bfloat16 hb = __float2bfloat16(o);
        ohi[idx] = hb;
        olo[idx] = __float2bfloat16(o - __bfloat162float(hb));
    }
}

// ---------------- launch ----------------
extern "C" void kernel_launch(void* const* d_in, const int* in_sizes, int n_in,
                              void* d_out, int out_size)
{
    const int*   ids     = (const int*)  d_in[0];
    const float* hs      = (const float*)d_in[1];
    const int*   anchors = (const int*)  d_in[2];
    // d_in[3] block_keep_mask: all-true by construction; intentionally unused
    const float* embed   = (const float*)d_in[4];
    const float* Wq      = (const float*)d_in[5];
    const float* Wk      = (const float*)d_in[6];
    const float* Wv      = (const float*)d_in[7];
    const float* Wo      = (const float*)d_in[8];
    const float* fcw     = (const float*)d_in[9];
    const float* lmw     = (const float*)d_in[10];
    const float* normw   = (const float*)d_in[11];

    float *h, *q, *k, *v, *kT, *h2, *inj;
    int* pos;
    __nv_bfloat16 *xhi, *xlo, *aohi, *aolo;
    __nv_bfloat16 *wqhi, *wqlo, *wkhi, *wklo, *wvhi, *wvlo, *wohi, *wolo, *lmhi, *lmlo;
    cudaGetSymbolAddress((void**)&h,    g_h);
    cudaGetSymbolAddress((void**)&q,    g_q);
    cudaGetSymbolAddress((void**)&k,    g_k);
    cudaGetSymbolAddress((void**)&v,    g_v);
    cudaGetSymbolAddress((void**)&kT,   g_kT);
    cudaGetSymbolAddress((void**)&h2,   g_h2);
    cudaGetSymbolAddress((void**)&inj,  g_inj);
    cudaGetSymbolAddress((void**)&pos,  g_pos);
    cudaGetSymbolAddress((void**)&xhi,  g_xhi);
    cudaGetSymbolAddress((void**)&xlo,  g_xlo);
    cudaGetSymbolAddress((void**)&aohi, g_aohi);
    cudaGetSymbolAddress((void**)&aolo, g_aolo);
    cudaGetSymbolAddress((void**)&wqhi, g_wqhi);
    cudaGetSymbolAddress((void**)&wqlo, g_wqlo);
    cudaGetSymbolAddress((void**)&wkhi, g_wkhi);
    cudaGetSymbolAddress((void**)&wklo, g_wklo);
    cudaGetSymbolAddress((void**)&wvhi, g_wvhi);
    cudaGetSymbolAddress((void**)&wvlo, g_wvlo);
    cudaGetSymbolAddress((void**)&wohi, g_wohi);
    cudaGetSymbolAddress((void**)&wolo, g_wolo);
    cudaGetSymbolAddress((void**)&lmhi, g_lmhi);
    cudaGetSymbolAddress((void**)&lmlo, g_lmlo);

    cudaFuncSetAttribute(hgemm_kernel, cudaFuncAttributeMaxDynamicSharedMemorySize, HS_TOTAL);
    cudaFuncSetAttribute(hgemm_qkv_kernel, cudaFuncAttributeMaxDynamicSharedMemorySize, HS_TOTAL);

    split_all_kernel<<<SPLIT_BLKS_ALL, 256>>>(Wq, Wk, Wv, Wo, lmw,
                                              wqhi, wqlo, wkhi, wklo, wvhi, wvlo,
                                              wohi, wolo, lmhi, lmlo);
    inj_kernel<<<dim3(N_, H_ / 128), 128>>>(hs, anchors, fcw, inj);
    buildnorm_kernel<<<T_, 256>>>(ids, anchors, embed, inj, normw, h, pos, xhi, xlo);
    hgemm_qkv_kernel<<<dim3(T_ / 128, H_ / 128, 3), 256, HS_TOTAL>>>(
        xhi, xlo, wqhi, wqlo, wkhi, wklo, wvhi, wvlo, q, k, v);
    rope_kernel<<<T_, 512>>>(q, k, pos);
    transposeKN_kernel<<<dim3(H_ / 32, T_ / 32), dim3(32, 8)>>>(k, kT, T_, H_);
    attn_kernel<<<dim3(T_ / QB, NH_), 128>>>(q, kT, v, anchors, aohi, aolo);
    hgemm_kernel<<<dim3(T_ / 128, H_ / 128), 256, HS_TOTAL>>>(
        T_, H_, H_, aohi, aolo, wohi, wolo, h2, h);   // +residual
    rmsnorm_split_kernel<<<T_, 256>>>(h2, normw, xhi, xlo);
    hgemm_kernel<<<dim3(T_ / 128, V_ / 128), 256, HS_TOTAL>>>(
        T_, V_, H_, xhi, xlo, lmhi, lmlo, (float*)d_out, nullptr);
}

// round 15
// speedup vs baseline: 2.9710x; 1.1522x over previous
#include <cuda_runtime.h>
#include <cuda_bf16.h>
#include <math.h>
#include <stdint.h>

#define S_  2048
#define N_  64
#define BS_ 16
#define W_  512
#define NH_ 8
#define H_  1024
#define V_  32000
#define DH_ 128
#define T_  3072
#define QB  16
#define SCALE 0.08838834764831845f  // 1/sqrt(128)

// ---------------- scratch (device globals; no allocation) ----------------
__device__ float g_h [T_*H_];
__device__ float g_q [T_*H_];
__device__ float g_k [T_*H_];
__device__ float g_v [T_*H_];
__device__ float g_kT[T_*H_];
__device__ float g_h2[T_*H_];
__device__ float g_inj[N_*H_];
__device__ int   g_pos[T_];
__device__ __nv_bfloat16 g_xhi[T_*H_], g_xlo[T_*H_];
__device__ __nv_bfloat16 g_aohi[T_*H_], g_aolo[T_*H_];
__device__ __nv_bfloat16 g_qhi[T_*H_], g_qlo[T_*H_];
__device__ __nv_bfloat16 g_khi[T_*H_], g_klo[T_*H_];
__device__ __nv_bfloat16 g_vhi[T_*H_], g_vlo[T_*H_];
__device__ __nv_bfloat16 g_wqhi[H_*H_], g_wqlo[H_*H_];
__device__ __nv_bfloat16 g_wkhi[H_*H_], g_wklo[H_*H_];
__device__ __nv_bfloat16 g_wvhi[H_*H_], g_wvlo[H_*H_];
__device__ __nv_bfloat16 g_wohi[H_*H_], g_wolo[H_*H_];
__device__ __nv_bfloat16 g_lmhi[(size_t)V_*H_], g_lmlo[(size_t)V_*H_];

// ---------------- helpers ----------------
__device__ __forceinline__ float wsum(float v){
#pragma unroll
    for (int o=16;o>0;o>>=1) v += __shfl_xor_sync(0xffffffffu, v, o);
    return v;
}
__device__ __forceinline__ float wmax(float v){
#pragma unroll
    for (int o=16;o>0;o>>=1) v = fmaxf(v, __shfl_xor_sync(0xffffffffu, v, o));
    return v;
}
__device__ __forceinline__ uint32_t smem_u32(const void* p){
    uint32_t a;
    asm("{ .reg .u64 t; cvta.to.shared.u64 t, %1; cvt.u32.u64 %0, t; }" : "=r"(a) : "l"(p));
    return a;
}
__device__ __forceinline__ void ldsm4(uint32_t& r0, uint32_t& r1, uint32_t& r2, uint32_t& r3,
                                      uint32_t addr){
    asm volatile("ldmatrix.sync.aligned.m8n8.x4.shared.b16 {%0,%1,%2,%3}, [%4];"
                 : "=r"(r0), "=r"(r1), "=r"(r2), "=r"(r3) : "r"(addr));
}
__device__ __forceinline__ void ldsm4t(uint32_t& r0, uint32_t& r1, uint32_t& r2, uint32_t& r3,
                                       uint32_t addr){
    asm volatile("ldmatrix.sync.aligned.m8n8.x4.trans.shared.b16 {%0,%1,%2,%3}, [%4];"
                 : "=r"(r0), "=r"(r1), "=r"(r2), "=r"(r3) : "r"(addr));
}
__device__ __forceinline__ void mma_bf16(float* c, const uint32_t* a, uint32_t b0, uint32_t b1){
    asm volatile("mma.sync.aligned.m16n8k16.row.col.f32.bf16.bf16.f32 "
                 "{%0,%1,%2,%3}, {%4,%5,%6,%7}, {%8,%9}, {%0,%1,%2,%3};"
                 : "+f"(c[0]), "+f"(c[1]), "+f"(c[2]), "+f"(c[3])
                 : "r"(a[0]), "r"(a[1]), "r"(a[2]), "r"(a[3]), "r"(b0), "r"(b1));
}
__device__ __forceinline__ void cp16(uint32_t saddr, const void* g){
    asm volatile("cp.async.cg.shared.global [%0], [%1], 16;"
                 :: "r"(saddr), "l"(__cvta_generic_to_global(g)));
}
__device__ __forceinline__ void cp_commit(){ asm volatile("cp.async.commit_group;" ::: "memory"); }
template<int Nn> __device__ __forceinline__ void cp_wait(){
    asm volatile("cp.async.wait_group %0;" :: "n"(Nn) : "memory");
}
__device__ __forceinline__ uint32_t bf16pair(float a, float b){
    __nv_bfloat162 p = __halves2bfloat162(__float2bfloat16(a), __float2bfloat16(b));
    return *(uint32_t*)&p;
}
__device__ __forceinline__ void split2(float a, float b, uint32_t& hi, uint32_t& lo){
    __nv_bfloat16 ha = __float2bfloat16(a), hb = __float2bfloat16(b);
    hi = bf16pair(a, b);
    lo = bf16pair(a - __bfloat162float(ha), b - __bfloat162float(hb));
}

// ================ bf16-split tensor-core GEMM core ================
#define LDSR 40
#define LDSB 136
#define ST_AHI 0
#define ST_ALO 10240
#define ST_BHI 20480
#define ST_BLO 29184
#define ST_SIZE 37888
#define NSTAGE 3
#define HS_TOTAL (NSTAGE*ST_SIZE)      // 113664 B

__device__ __forceinline__ void gemm_core(
    int Nc, int K, int crow, int ccol,
    const __nv_bfloat16* __restrict__ Ahi, const __nv_bfloat16* __restrict__ Alo,
    const __nv_bfloat16* __restrict__ Bhi, const __nv_bfloat16* __restrict__ Blo,
    float* __restrict__ C, const float* __restrict__ D, char* sm)
{
    uint32_t sb = smem_u32(sm);
    int tid  = threadIdx.x, lane = tid & 31, wid = tid >> 5;
    int wm   = (wid & 1) * 64,  wn   = (wid >> 1) * 32;

    float acc[4][4][4];
#pragma unroll
    for (int i = 0; i < 4; i++)
#pragma unroll
        for (int j = 0; j < 4; j++)
#pragma unroll
            for (int r = 0; r < 4; r++) acc[i][j][r] = 0.f;

    uint32_t a_off = ((wm + (lane & 15)) * LDSR + (lane >> 4) * 8) * 2;
    uint32_t b_off = (uint32_t)(((((lane >> 3) & 1) * 8 + (lane & 7)) * LDSB
                                 + wn + (lane >> 4) * 8) * 2);
    int kq = K / 32;

    auto issue = [&](int ch){
        uint32_t st = sb + (ch % NSTAGE) * ST_SIZE;
        int kb = ch * 32;
#pragma unroll
        for (int r = 0; r < 2; r++) {
            int seg = tid + r * 256;
            int ar = seg >> 2, ac = (seg & 3) * 8;
            size_t ga = (size_t)(crow + ar) * K + kb + ac;
            uint32_t sa = st + ST_AHI + (uint32_t)(ar * LDSR + ac) * 2;
            cp16(sa, Ahi + ga);
            cp16(sa + (ST_ALO - ST_AHI), Alo + ga);
            int br = seg >> 4, bcx = (seg & 15) * 8;
            size_t gb = (size_t)(kb + br) * Nc + ccol + bcx;
            uint32_t sbo = st + ST_BHI + (uint32_t)(br * LDSB + bcx) * 2;
            cp16(sbo, Bhi + gb);
            cp16(sbo + (ST_BLO - ST_BHI), Blo + gb);
        }
    };

    issue(0); cp_commit();
    issue(1); cp_commit();

    for (int ch = 0; ch < kq; ch++) {
        cp_wait<NSTAGE - 2>();
        __syncthreads();
        if (ch + 2 < kq) issue(ch + 2);
        cp_commit();

        uint32_t base = sb + (ch % NSTAGE) * ST_SIZE;
#pragma unroll
        for (int ks = 0; ks < 2; ks++) {
            uint32_t bh4[2][4], bl4[2][4];
#pragma unroll
            for (int p = 0; p < 2; p++) {
                uint32_t adr = base + ST_BHI + b_off + ks * (16 * LDSB * 2) + p * 32;
                ldsm4t(bh4[p][0], bh4[p][1], bh4[p][2], bh4[p][3], adr);
                ldsm4t(bl4[p][0], bl4[p][1], bl4[p][2], bl4[p][3], adr + (ST_BLO - ST_BHI));
            }
#pragma unroll
            for (int mi = 0; mi < 4; mi++) {
                uint32_t ah[4], al[4];
                uint32_t adr = base + ST_AHI + a_off + mi * (16 * LDSR * 2) + ks * 32;
                ldsm4(ah[0], ah[1], ah[2], ah[3], adr);
                ldsm4(al[0], al[1], al[2], al[3], adr + (ST_ALO - ST_AHI));
#pragma unroll
                for (int ni = 0; ni < 4; ni++) {
                    uint32_t b0h = bh4[ni >> 1][(ni & 1) * 2], b1h = bh4[ni >> 1][(ni & 1) * 2 + 1];
                    uint32_t b0l = bl4[ni >> 1][(ni & 1) * 2], b1l = bl4[ni >> 1][(ni & 1) * 2 + 1];
                    mma_bf16(acc[mi][ni], ah, b0h, b1h);
                    mma_bf16(acc[mi][ni], ah, b0l, b1l);
                    mma_bf16(acc[mi][ni], al, b0h, b1h);
                }
            }
        }
    }

#pragma unroll
    for (int mi = 0; mi < 4; mi++)
#pragma unroll
        for (int ni = 0; ni < 4; ni++) {
            size_t r0 = (size_t)(crow + wm + mi * 16 + (lane >> 2));
            int    cc = ccol + wn + ni * 8 + (lane & 3) * 2;
            float2 v0 = make_float2(acc[mi][ni][0], acc[mi][ni][1]);
            float2 v1 = make_float2(acc[mi][ni][2], acc[mi][ni][3]);
            if (D) {
                const float2 d0 = *(const float2*)(D + r0 * Nc + cc);
                const float2 d1 = *(const float2*)(D + (r0 + 8) * Nc + cc);
                v0.x += d0.x; v0.y += d0.y; v1.x += d1.x; v1.y += d1.y;
            }
            *(float2*)(C + r0 * Nc + cc)       = v0;
            *(float2*)(C + (r0 + 8) * Nc + cc) = v1;
        }
}

__global__ __launch_bounds__(256, 2) void hgemm_kernel(
    int M, int Nc, int K,
    const __nv_bfloat16* __restrict__ Ahi, const __nv_bfloat16* __restrict__ Alo,
    const __nv_bfloat16* __restrict__ Bhi, const __nv_bfloat16* __restrict__ Blo,
    float* __restrict__ C, const float* __restrict__ D)
{
    extern __shared__ char sm[];
    gemm_core(Nc, K, blockIdx.x * 128, blockIdx.y * 128, Ahi, Alo, Bhi, Blo, C, D, sm);
}

__global__ __launch_bounds__(256, 2) void hgemm_qkv_kernel(
    const __nv_bfloat16* __restrict__ Ahi, const __nv_bfloat16* __restrict__ Alo,
    const __nv_bfloat16* __restrict__ qh, const __nv_bfloat16* __restrict__ ql,
    const __nv_bfloat16* __restrict__ kh, const __nv_bfloat16* __restrict__ kl,
    const __nv_bfloat16* __restrict__ vh, const __nv_bfloat16* __restrict__ vl,
    float* __restrict__ q, float* __restrict__ k, float* __restrict__ v)
{
    extern __shared__ char sm[];
    const __nv_bfloat16 *Bhi, *Blo;
    float* C;
    if (blockIdx.z == 0)      { Bhi = qh; Blo = ql; C = q; }
    else if (blockIdx.z == 1) { Bhi = kh; Blo = kl; C = k; }
    else                      { Bhi = vh; Blo = vl; C = v; }
    gemm_core(H_, H_, blockIdx.x * 128, blockIdx.y * 128, Ahi, Alo, Bhi, Blo, C, nullptr, sm);
}

// ---------------- fused split of all 5 weight matrices ----------------
__device__ __forceinline__ void split4(const float* __restrict__ in, size_t i,
                                       __nv_bfloat16* __restrict__ hi,
                                       __nv_bfloat16* __restrict__ lo)
{
    float4 v = *(const float4*)(in + i);
    uint32_t h01, l01, h23, l23;
    split2(v.x, v.y, h01, l01);
    split2(v.z, v.w, h23, l23);
    *(uint2*)(hi + i) = make_uint2(h01, h23);
    *(uint2*)(lo + i) = make_uint2(l01, l23);
}

#define SPLIT_BLKS_SMALL (H_*H_/1024)
#define SPLIT_BLKS_LM    ((int)((size_t)V_*H_/1024))
#define SPLIT_BLKS_ALL   (4*SPLIT_BLKS_SMALL + SPLIT_BLKS_LM)

__global__ __launch_bounds__(256) void split_all_kernel(
    const float* __restrict__ Wq, const float* __restrict__ Wk,
    const float* __restrict__ Wv, const float* __restrict__ Wo,
    const float* __restrict__ lmw,
    __nv_bfloat16* __restrict__ wqhi, __nv_bfloat16* __restrict__ wqlo,
    __nv_bfloat16* __restrict__ wkhi, __nv_bfloat16* __restrict__ wklo,
    __nv_bfloat16* __restrict__ wvhi, __nv_bfloat16* __restrict__ wvlo,
    __nv_bfloat16* __restrict__ wohi, __nv_bfloat16* __restrict__ wolo,
    __nv_bfloat16* __restrict__ lmhi, __nv_bfloat16* __restrict__ lmlo)
{
    int b = blockIdx.x;
    const float* src; __nv_bfloat16 *hi, *lo; int base;
    if      (b < 1 * SPLIT_BLKS_SMALL) { src = Wq;  hi = wqhi; lo = wqlo; base = 0; }
    else if (b < 2 * SPLIT_BLKS_SMALL) { src = Wk;  hi = wkhi; lo = wklo; base = SPLIT_BLKS_SMALL; }
    else if (b < 3 * SPLIT_BLKS_SMALL) { src = Wv;  hi = wvhi; lo = wvlo; base = 2 * SPLIT_BLKS_SMALL; }
    else if (b < 4 * SPLIT_BLKS_SMALL) { src = Wo;  hi = wohi; lo = wolo; base = 3 * SPLIT_BLKS_SMALL; }
    else                               { src = lmw; hi = lmhi; lo = lmlo; base = 4 * SPLIT_BLKS_SMALL; }
    size_t i = ((size_t)(b - base) * 256 + threadIdx.x) * 4;
    split4(src, i, hi, lo);
}

// ---------------- inj ----------------
__global__ void inj_kernel(const float* __restrict__ hs, const int* __restrict__ anchors,
                           const float* __restrict__ fcw, float* __restrict__ inj)
{
    int n = blockIdx.x;
    int c = blockIdx.y * 128 + threadIdx.x;
    int a = anchors[n];
    int ctx = a - 1; if (ctx < 0) ctx = 0;
    const float* h0 = hs + (size_t)ctx * H_;
    const float* h1 = hs + (size_t)S_ * H_ + (size_t)ctx * H_;
    float acc = 0.f;
    for (int k = 0; k < H_; k++) acc += h0[k] * fcw[(size_t)k * H_ + c];
    for (int k = 0; k < H_; k++) acc += h1[k] * fcw[(size_t)(H_ + k) * H_ + c];
    inj[(size_t)n * H_ + c] = acc;
}

// ---------------- fused build h + rmsnorm + split ----------------
__global__ __launch_bounds__(256) void buildnorm_kernel(
    const int* __restrict__ ids, const int* __restrict__ anchors,
    const float* __restrict__ embed, const float* __restrict__ inj,
    const float* __restrict__ w,
    float* __restrict__ h, int* __restrict__ pos,
    __nv_bfloat16* __restrict__ hi, __nv_bfloat16* __restrict__ lo)
{
    int t = blockIdx.x;
    int tok;
    const float* add = nullptr;
    if (t < S_) {
        tok = ids[t];
        if (threadIdx.x == 0) pos[t] = t;
    } else {
        int n = (t - S_) / BS_, j = (t - S_) % BS_;
        int a = anchors[n];
        int ap = a; if (ap < 0) ap = 0; if (ap > S_-1) ap = S_-1;
        tok = (j == 0) ? ids[ap] : 0;
        add = inj + (size_t)n * H_;
        if (threadIdx.x == 0) pos[t] = a + j;
    }
    int c = threadIdx.x * 4;
    float4 v = *(const float4*)(embed + (size_t)tok * H_ + c);
    if (add) {
        float4 a4 = *(const float4*)(add + c);
        v.x += a4.x; v.y += a4.y; v.z += a4.z; v.w += a4.w;
    }
    *(float4*)(h + (size_t)t * H_ + c) = v;

    float ss = v.x * v.x + v.y * v.y + v.z * v.z + v.w * v.w;
    ss = wsum(ss);
    __shared__ float sred[8];
    if ((threadIdx.x & 31) == 0) sred[threadIdx.x >> 5] = ss;
    __syncthreads();
    float tot = 0.f;
#pragma unroll
    for (int i = 0; i < 8; i++) tot += sred[i];
    float inv = rsqrtf(tot * (1.0f / H_) + 1e-6f);
    float4 wv = *(const float4*)(w + c);
    float o0 = v.x * inv * wv.x, o1 = v.y * inv * wv.y;
    float o2 = v.z * inv * wv.z, o3 = v.w * inv * wv.w;
    uint32_t h01, l01, h23, l23;
    split2(o0, o1, h01, l01);
    split2(o2, o3, h23, l23);
    *(uint2*)(hi + (size_t)t * H_ + c) = make_uint2(h01, h23);
    *(uint2*)(lo + (size_t)t * H_ + c) = make_uint2(l01, l23);
}

// ---------------- rmsnorm + split (float4) ----------------
__global__ __launch_bounds__(256) void rmsnorm_split_kernel(const float* __restrict__ in,
                                                            const float* __restrict__ w,
                                                            __nv_bfloat16* __restrict__ hi,
                                                            __nv_bfloat16* __restrict__ lo)
{
    int t = blockIdx.x;
    int c = threadIdx.x * 4;
    float4 v = *(const float4*)(in + (size_t)t * H_ + c);
    float ss = v.x * v.x + v.y * v.y + v.z * v.z + v.w * v.w;
    ss = wsum(ss);
    __shared__ float sred[8];
    if ((threadIdx.x & 31) == 0) sred[threadIdx.x >> 5] = ss;
    __syncthreads();
    float tot = 0.f;
#pragma unroll
    for (int i = 0; i < 8; i++) tot += sred[i];
    float inv = rsqrtf(tot * (1.0f / H_) + 1e-6f);
    float4 wv = *(const float4*)(w + c);
    float o0 = v.x * inv * wv.x, o1 = v.y * inv * wv.y;
    float o2 = v.z * inv * wv.z, o3 = v.w * inv * wv.w;
    uint32_t h01, l01, h23, l23;
    split2(o0, o1, h01, l01);
    split2(o2, o3, h23, l23);
    *(uint2*)(hi + (size_t)t * H_ + c) = make_uint2(h01, h23);
    *(uint2*)(lo + (size_t)t * H_ + c) = make_uint2(l01, l23);
}

// ---------------- RoPE + split q(scaled)/k/v to bf16 hi/lo ----------------
__global__ void rope_split_kernel(float* __restrict__ q, float* __restrict__ k,
                                  const float* __restrict__ v, const int* __restrict__ pos,
                                  __nv_bfloat16* __restrict__ qhi, __nv_bfloat16* __restrict__ qlo,
                                  __nv_bfloat16* __restrict__ khi, __nv_bfloat16* __restrict__ klo,
                                  __nv_bfloat16* __restrict__ vhi, __nv_bfloat16* __restrict__ vlo)
{
    int t = blockIdx.x;
    int idx = threadIdx.x;          // 0..511
    int hh = idx >> 6, i = idx & 63;
    int p = pos[t];
    float inv_freq = exp2f(-(float)i * (13.287712379549449f / 64.0f));
    float ang = (float)p * inv_freq;
    float s, c;
    sincosf(ang, &s, &c);
    size_t b = (size_t)t * H_ + hh * DH_ + i;
    float x1 = q[b], x2 = q[b + 64];
    float q1 = x1 * c - x2 * s;
    float q2 = x2 * c + x1 * s;
    q[b] = q1; q[b + 64] = q2;
    {   // scaled split for MMA path
        float a1 = q1 * SCALE, a2 = q2 * SCALE;
        __nv_bfloat16 h1 = __float2bfloat16(a1), h2 = __float2bfloat16(a2);
        qhi[b] = h1;      qhi[b + 64] = h2;
        qlo[b] = __float2bfloat16(a1 - __bfloat162float(h1));
        qlo[b + 64] = __float2bfloat16(a2 - __bfloat162float(h2));
    }
    x1 = k[b]; x2 = k[b + 64];
    float k1 = x1 * c - x2 * s;
    float k2 = x2 * c + x1 * s;
    k[b] = k1; k[b + 64] = k2;
    {
        __nv_bfloat16 h1 = __float2bfloat16(k1), h2 = __float2bfloat16(k2);
        khi[b] = h1;      khi[b + 64] = h2;
        klo[b] = __float2bfloat16(k1 - __bfloat162float(h1));
        klo[b + 64] = __float2bfloat16(k2 - __bfloat162float(h2));
    }
    // v split: two consecutive elems per thread
    size_t vb = (size_t)t * H_ + idx * 2;
    float v0 = v[vb], v1 = v[vb + 1];
    __nv_bfloat16 hv0 = __float2bfloat16(v0), hv1 = __float2bfloat16(v1);
    vhi[vb] = hv0; vhi[vb + 1] = hv1;
    vlo[vb] = __float2bfloat16(v0 - __bfloat162float(hv0));
    vlo[vb + 1] = __float2bfloat16(v1 - __bfloat162float(hv1));
}

// ---------------- transpose in[Kd][Nd] -> out[Nd][Kd] ----------------
__global__ void transposeKN_kernel(const float* __restrict__ in, float* __restrict__ out,
                                   int Kd, int Nd)
{
    __shared__ float tile[32][33];
    int n0 = blockIdx.x * 32;
    int k0 = blockIdx.y * 32;
    int x = threadIdx.x, y0 = threadIdx.y;
#pragma unroll
    for (int dy = 0; dy < 32; dy += 8)
        tile[y0 + dy][x] = in[(size_t)(k0 + y0 + dy) * Nd + n0 + x];
    __syncthreads();
#pragma unroll
    for (int dy = 0; dy < 32; dy += 8)
        out[(size_t)(n0 + y0 + dy) * Kd + k0 + x] = tile[x][y0 + dy];
}

// ================ tensor-core attention for FULL queries (causal) ================
// CTA: 64 queries x 1 head. 64-key chunks, bf16-split, fp32 online softmax.
#define LQ 136
#define LP 72
#define AS_QHI 0
#define AS_QLO 17408
#define AS_PHI 34816
#define AS_PLO 44032
#define AS_M   53248
#define AS_L   53504
#define AS_F   53760
#define AS_PMAX 54016
#define AS_PSUM 54528
#define AS_KV   55040
#define KV_ARR  17408
#define KV_STAGE (4*KV_ARR)
#define AT_SMEM (AS_KV + 2*KV_STAGE)   // 194304

__global__ __launch_bounds__(256, 1) void attn_mma_kernel(
    const __nv_bfloat16* __restrict__ qhi, const __nv_bfloat16* __restrict__ qlo,
    const __nv_bfloat16* __restrict__ khi, const __nv_bfloat16* __restrict__ klo,
    const __nv_bfloat16* __restrict__ vhi, const __nv_bfloat16* __restrict__ vlo,
    __nv_bfloat16* __restrict__ ohi_out, __nv_bfloat16* __restrict__ olo_out)
{
    extern __shared__ char sm[];
    uint32_t sb = smem_u32(sm);
    int tid = threadIdx.x, lane = tid & 31, w = tid >> 5;
    int h = blockIdx.y, t0 = blockIdx.x * 64;
    int nch = t0 / 64 + 1;

    const __nv_bfloat16* qh = qhi + (size_t)t0 * H_ + h * DH_;
    const __nv_bfloat16* ql = qlo + (size_t)t0 * H_ + h * DH_;
    const __nv_bfloat16* kh = khi + h * DH_;
    const __nv_bfloat16* kl = klo + h * DH_;
    const __nv_bfloat16* vh = vhi + h * DH_;
    const __nv_bfloat16* vl = vlo + h * DH_;

    // load Q tiles
#pragma unroll
    for (int i = 0; i < 4; i++) {
        int lin = i * 256 + tid;
        int row = lin >> 4, seg = lin & 15;
        size_t go = (size_t)row * H_ + seg * 8;
        uint32_t so = (uint32_t)(row * 272 + seg * 16);
        cp16(sb + AS_QHI + so, qh + go);
        cp16(sb + AS_QLO + so, ql + go);
    }
    cp_commit();

    float* Ms = (float*)(sm + AS_M);
    float* Ls = (float*)(sm + AS_L);
    float* Fs = (float*)(sm + AS_F);
    float* Pm = (float*)(sm + AS_PMAX);
    float* Ps = (float*)(sm + AS_PSUM);
    if (tid < 64) { Ms[tid] = -3e38f; Ls[tid] = 0.f; }

    auto issueKV = [&](int ch){
        if (ch < nch) {
            uint32_t st = sb + AS_KV + (ch & 1) * KV_STAGE;
            int kb = ch * 64;
#pragma unroll
            for (int i = 0; i < 4; i++) {
                int lin = i * 256 + tid;
                int row = lin >> 4, seg = lin & 15;
                size_t go = (size_t)(kb + row) * H_ + seg * 8;
                uint32_t so = (uint32_t)(row * 272 + seg * 16);
                cp16(st + 0 * KV_ARR + so, kh + go);
                cp16(st + 1 * KV_ARR + so, kl + go);
                cp16(st + 2 * KV_ARR + so, vh + go);
                cp16(st + 3 * KV_ARR + so, vl + go);
            }
        }
        cp_commit();
    };
    issueKV(0);

    int wrow = (w & 3) * 16, wcol = (w >> 2) * 32;
    int prow = wrow, pcol = (w >> 2) * 64;
    int wc = w >> 2;
    uint32_t qa_off = (uint32_t)(((wrow + (lane & 15)) * LQ + (lane >> 4) * 8) * 2);
    uint32_t kb_off = (uint32_t)(((wcol + (lane >> 4) * 8 + (lane & 7)) * LQ + ((lane >> 3) & 1) * 8) * 2);
    uint32_t pa_off = (uint32_t)(((prow + (lane & 15)) * LP + (lane >> 4) * 8) * 2);
    uint32_t vb_off = (uint32_t)(((((lane >> 3) & 1) * 8 + (lane & 7)) * LQ + pcol + (lane >> 4) * 8) * 2);

    float accO[8][4];
#pragma unroll
    for (int i = 0; i < 8; i++)
#pragma unroll
        for (int r = 0; r < 4; r++) accO[i][r] = 0.f;

    for (int ch = 0; ch < nch; ch++) {
        issueKV(ch + 1);
        cp_wait<1>();
        __syncthreads();
        uint32_t kst = sb + AS_KV + (ch & 1) * KV_STAGE;

        // ---- scores S = Qs @ K^T  (3-term split) ----
        float sAcc[4][4];
#pragma unroll
        for (int i = 0; i < 4; i++)
#pragma unroll
            for (int r = 0; r < 4; r++) sAcc[i][r] = 0.f;
#pragma unroll
        for (int ks = 0; ks < 8; ks++) {
            uint32_t ah[4], al[4], bh[2][4], bl[2][4];
            uint32_t adr = sb + AS_QHI + qa_off + ks * 32;
            ldsm4(ah[0], ah[1], ah[2], ah[3], adr);
            ldsm4(al[0], al[1], al[2], al[3], adr + (AS_QLO - AS_QHI));
#pragma unroll
            for (int p = 0; p < 2; p++) {
                uint32_t badr = kst + kb_off + p * (16 * LQ * 2) + ks * 32;
                ldsm4(bh[p][0], bh[p][1], bh[p][2], bh[p][3], badr);
                ldsm4(bl[p][0], bl[p][1], bl[p][2], bl[p][3], badr + KV_ARR);
            }
#pragma unroll
            for (int c8 = 0; c8 < 4; c8++) {
                uint32_t b0h = bh[c8 >> 1][(c8 & 1) * 2], b1h = bh[c8 >> 1][(c8 & 1) * 2 + 1];
                uint32_t b0l = bl[c8 >> 1][(c8 & 1) * 2], b1l = bl[c8 >> 1][(c8 & 1) * 2 + 1];
                mma_bf16(sAcc[c8], ah, b0h, b1h);
                mma_bf16(sAcc[c8], ah, b0l, b1l);
                mma_bf16(sAcc[c8], al, b0h, b1h);
            }
        }
        // diagonal mask (kb == t0)
        if (ch == nch - 1) {
#pragma unroll
            for (int c8 = 0; c8 < 4; c8++)
#pragma unroll
                for (int r = 0; r < 4; r++) {
                    int rl = wrow + (lane >> 2) + ((r >> 1) ? 8 : 0);
                    int cl = wcol + c8 * 8 + (lane & 3) * 2 + (r & 1);
                    if (cl > rl) sAcc[c8][r] = -3e38f;
                }
        }
        // partial row max
        {
            float mx0 = -3e38f, mx1 = -3e38f;
#pragma unroll
            for (int c8 = 0; c8 < 4; c8++) {
                mx0 = fmaxf(mx0, fmaxf(sAcc[c8][0], sAcc[c8][1]));
                mx1 = fmaxf(mx1, fmaxf(sAcc[c8][2], sAcc[c8][3]));
            }
            mx0 = fmaxf(mx0, __shfl_xor_sync(0xffffffffu, mx0, 1));
            mx0 = fmaxf(mx0, __shfl_xor_sync(0xffffffffu, mx0, 2));
            mx1 = fmaxf(mx1, __shfl_xor_sync(0xffffffffu, mx1, 1));
            mx1 = fmaxf(mx1, __shfl_xor_sync(0xffffffffu, mx1, 2));
            if ((lane & 3) == 0) {
                int r0 = wrow + (lane >> 2);
                Pm[r0 * 2 + wc]       = mx0;
                Pm[(r0 + 8) * 2 + wc] = mx1;
            }
        }
        __syncthreads();
        if (w < 4 && lane < 16) {
            int r = w * 16 + lane;
            float mold = Ms[r];
            float mnew = fmaxf(mold, fmaxf(Pm[r * 2], Pm[r * 2 + 1]));
            Fs[r] = expf(mold - mnew);
            Ms[r] = mnew;
        }
        __syncthreads();
        // P = exp(S - m), write split P; partial row sums; rescale O
        {
            int r0 = wrow + (lane >> 2);
            float m0 = Ms[r0], m1 = Ms[r0 + 8];
            float s0 = 0.f, s1 = 0.f;
#pragma unroll
            for (int c8 = 0; c8 < 4; c8++) {
                float p0 = expf(sAcc[c8][0] - m0), p1 = expf(sAcc[c8][1] - m0);
                float p2 = expf(sAcc[c8][2] - m1), p3 = expf(sAcc[c8][3] - m1);
                s0 += p0 + p1; s1 += p2 + p3;
                int colb = wcol + c8 * 8 + (lane & 3) * 2;
                uint32_t hi01, lo01, hi23, lo23;
                split2(p0, p1, hi01, lo01);
                split2(p2, p3, hi23, lo23);
                *(uint32_t*)(sm + AS_PHI + (r0 * LP + colb) * 2)       = hi01;
                *(uint32_t*)(sm + AS_PLO + (r0 * LP + colb) * 2)       = lo01;
                *(uint32_t*)(sm + AS_PHI + ((r0 + 8) * LP + colb) * 2) = hi23;
                *(uint32_t*)(sm + AS_PLO + ((r0 + 8) * LP + colb) * 2) = lo23;
            }
            s0 += __shfl_xor_sync(0xffffffffu, s0, 1);
            s0 += __shfl_xor_sync(0xffffffffu, s0, 2);
            s1 += __shfl_xor_sync(0xffffffffu, s1, 1);
            s1 += __shfl_xor_sync(0xffffffffu, s1, 2);
            if ((lane & 3) == 0) {
                Ps[r0 * 2 + wc]       = s0;
                Ps[(r0 + 8) * 2 + wc] = s1;
            }
            float f0 = Fs[prow + (lane >> 2)], f1 = Fs[prow + (lane >> 2) + 8];
#pragma unroll
            for (int nt = 0; nt < 8; nt++) {
                accO[nt][0] *= f0; accO[nt][1] *= f0;
                accO[nt][2] *= f1; accO[nt][3] *= f1;
            }
        }
        __syncthreads();
        // ---- O += P @ V  (3-term split) ----
#pragma unroll
        for (int ks = 0; ks < 4; ks++) {
            uint32_t ah[4], al[4];
            uint32_t padr = sb + AS_PHI + pa_off + ks * 32;
            ldsm4(ah[0], ah[1], ah[2], ah[3], padr);
            ldsm4(al[0], al[1], al[2], al[3], padr + (AS_PLO - AS_PHI));
            uint32_t bh[4][4], bl[4][4];
#pragma unroll
            for (int p = 0; p < 4; p++) {
                uint32_t vadr = kst + 2 * KV_ARR + vb_off + ks * (16 * LQ * 2) + p * 32;
                ldsm4t(bh[p][0], bh[p][1], bh[p][2], bh[p][3], vadr);
                ldsm4t(bl[p][0], bl[p][1], bl[p][2], bl[p][3], vadr + KV_ARR);
            }
#pragma unroll
            for (int nt = 0; nt < 8; nt++) {
                uint32_t b0h = bh[nt >> 1][(nt & 1) * 2], b1h = bh[nt >> 1][(nt & 1) * 2 + 1];
                uint32_t b0l = bl[nt >> 1][(nt & 1) * 2], b1l = bl[nt >> 1][(nt & 1) * 2 + 1];
                mma_bf16(accO[nt], ah, b0h, b1h);
                mma_bf16(accO[nt], ah, b0l, b1l);
                mma_bf16(accO[nt], al, b0h, b1h);
            }
        }
        if (w < 4 && lane < 16) {
            int r = w * 16 + lane;
            Ls[r] = Ls[r] * Fs[r] + Ps[r * 2] + Ps[r * 2 + 1];
        }
    }
    __syncthreads();
    // epilogue: O / l, split to bf16 hi/lo
    {
        int r0 = prow + (lane >> 2);
        float l0 = Ls[r0], l1 = Ls[r0 + 8];
#pragma unroll
        for (int nt = 0; nt < 8; nt++) {
            int colb = pcol + nt * 8 + (lane & 3) * 2;
            float o0 = accO[nt][0] / l0, o1 = accO[nt][1] / l0;
            float o2 = accO[nt][2] / l1, o3 = accO[nt][3] / l1;
            uint32_t hi01, lo01, hi23, lo23;
            split2(o0, o1, hi01, lo01);
            split2(o2, o3, hi23, lo23);
            size_t i0 = (size_t)(t0 + r0) * H_ + h * DH_ + colb;
            size_t i1 = (size_t)(t0 + r0 + 8) * H_ + h * DH_ + colb;
            *(uint32_t*)(ohi_out + i0) = hi01;
            *(uint32_t*)(olo_out + i0) = lo01;
            *(uint32_t*)(ohi_out + i1) = hi23;
            *(uint32_t*)(olo_out + i1) = lo23;
        }
    }
}

// ---------------- SIMT attention for BLOCK queries only ----------------
__global__ __launch_bounds__(128) void attn_blk_kernel(
    const float* __restrict__ q, const float* __restrict__ kT,
    const float* __restrict__ v, const int* __restrict__ anchors,
    __nv_bfloat16* __restrict__ ohi, __nv_bfloat16* __restrict__ olo)
{
    __shared__ float qs[QB][DH_];
    __shared__ float pbuf[QB][128];
    __shared__ float redm[QB][4];
    __shared__ float reds[QB][4];

    int h   = blockIdx.y;
    int nb  = blockIdx.x;
    int t0  = S_ + nb * QB;
    int tid = threadIdx.x;
    int w   = tid >> 5, lane = tid & 31;

#pragma unroll
    for (int qi = 0; qi < QB; qi++)
        qs[qi][tid] = q[(size_t)(t0 + qi) * H_ + h * DH_ + tid] * SCALE;
    __syncthreads();

    float m[QB], l[QB], acc[QB];
#pragma unroll
    for (int qi = 0; qi < QB; qi++) { m[qi] = -INFINITY; l[qi] = 0.f; acc[qi] = 0.f; }

    int lo_[1], hi_[1];   // shared range for all 16 queries of the block

    auto proc = [&](int base, int cnt) {
        int k = base + tid;
        bool act = (tid < cnt) && (k >= lo_[0]) && (k <= hi_[0]);
        float s[QB];
#pragma unroll
        for (int qi = 0; qi < QB; qi++) s[qi] = -INFINITY;
        if (act) {
#pragma unroll
            for (int qi = 0; qi < QB; qi++) s[qi] = 0.f;
            const float* kp = kT + (size_t)(h * DH_) * T_ + k;
            for (int d = 0; d < DH_; d += 4) {
                float kv0 = kp[(size_t)(d + 0) * T_];
                float kv1 = kp[(size_t)(d + 1) * T_];
                float kv2 = kp[(size_t)(d + 2) * T_];
                float kv3 = kp[(size_t)(d + 3) * T_];
#pragma unroll
                for (int qi = 0; qi < QB; qi++) {
                    float4 qv = *(const float4*)&qs[qi][d];
                    s[qi] += qv.x * kv0 + qv.y * kv1 + qv.z * kv2 + qv.w * kv3;
                }
            }
        }
        __syncthreads();
#pragma unroll
        for (int qi = 0; qi < QB; qi++) {
            float x = wmax(s[qi]);
            if (lane == 0) redm[qi][w] = x;
        }
        __syncthreads();
        float nm[QB];
#pragma unroll
        for (int qi = 0; qi < QB; qi++) {
            float cm = fmaxf(fmaxf(redm[qi][0], redm[qi][1]), fmaxf(redm[qi][2], redm[qi][3]));
            nm[qi] = fmaxf(m[qi], cm);
            float p = (s[qi] == -INFINITY) ? 0.f : expf(s[qi] - nm[qi]);
            pbuf[qi][tid] = p;
            float sp = wsum(p);
            if (lane == 0) reds[qi][w] = sp;
        }
        __syncthreads();
#pragma unroll
        for (int qi = 0; qi < QB; qi++) {
            float f = (m[qi] == -INFINITY) ? 0.f : expf(m[qi] - nm[qi]);
            float cs = reds[qi][0] + reds[qi][1] + reds[qi][2] + reds[qi][3];
            l[qi] = l[qi] * f + cs;
            acc[qi] *= f;
            m[qi] = nm[qi];
        }
        const float* vp = v + (size_t)base * H_ + h * DH_ + tid;
        for (int j = 0; j < cnt; j += 4) {
            float vv0 = vp[(size_t)(j + 0) * H_];
            float vv1 = vp[(size_t)(j + 1) * H_];
            float vv2 = vp[(size_t)(j + 2) * H_];
            float vv3 = vp[(size_t)(j + 3) * H_];
#pragma unroll
            for (int qi = 0; qi < QB; qi++) {
                float4 pv = *(const float4*)&pbuf[qi][j];
                acc[qi] += pv.x * vv0 + pv.y * vv1 + pv.z * vv2 + pv.w * vv3;
            }
        }
    };

    int a  = anchors[nb];
    int ws = a - W_ + 1; if (ws < 0) ws = 0;
    int we = a - 1;
    lo_[0] = ws; hi_[0] = we;
    for (int base = (ws >> 7) << 7; base <= we; base += 128) proc(base, 128);
    int kb = S_ + nb * BS_;
    lo_[0] = kb; hi_[0] = kb + BS_ - 1;
    proc(kb, BS_);

#pragma unroll
    for (int qi = 0; qi < QB; qi++) {
        float o = acc[qi] / l[qi];
        size_t idx = (size_t)(t0 + qi) * H_ + h * DH_ + tid;
        __nv_bfloat16 hb = __float2bfloat16(o);
        ohi[idx] = hb;
        olo[idx] = __float2bfloat16(o - __bfloat162float(hb));
    }
}

// ---------------- launch ----------------
extern "C" void kernel_launch(void* const* d_in, const int* in_sizes, int n_in,
                              void* d_out, int out_size)
{
    const int*   ids     = (const int*)  d_in[0];
    const float* hs      = (const float*)d_in[1];
    const int*   anchors = (const int*)  d_in[2];
    // d_in[3] block_keep_mask: all-true by construction; intentionally unused
    const float* embed   = (const float*)d_in[4];
    const float* Wq      = (const float*)d_in[5];
    const float* Wk      = (const float*)d_in[6];
    const float* Wv      = (const float*)d_in[7];
    const float* Wo      = (const float*)d_in[8];
    const float* fcw     = (const float*)d_in[9];
    const float* lmw     = (const float*)d_in[10];
    const float* normw   = (const float*)d_in[11];

    float *h, *q, *k, *v, *kT, *h2, *inj;
    int* pos;
    __nv_bfloat16 *xhi, *xlo, *aohi, *aolo, *qhi, *qlo, *khi, *klo, *vhi, *vlo;
    __nv_bfloat16 *wqhi, *wqlo, *wkhi, *wklo, *wvhi, *wvlo, *wohi, *wolo, *lmhi, *lmlo;
    cudaGetSymbolAddress((void**)&h,    g_h);
    cudaGetSymbolAddress((void**)&q,    g_q);
    cudaGetSymbolAddress((void**)&k,    g_k);
    cudaGetSymbolAddress((void**)&v,    g_v);
    cudaGetSymbolAddress((void**)&kT,   g_kT);
    cudaGetSymbolAddress((void**)&h2,   g_h2);
    cudaGetSymbolAddress((void**)&inj,  g_inj);
    cudaGetSymbolAddress((void**)&pos,  g_pos);
    cudaGetSymbolAddress((void**)&xhi,  g_xhi);
    cudaGetSymbolAddress((void**)&xlo,  g_xlo);
    cudaGetSymbolAddress((void**)&aohi, g_aohi);
    cudaGetSymbolAddress((void**)&aolo, g_aolo);
    cudaGetSymbolAddress((void**)&qhi,  g_qhi);
    cudaGetSymbolAddress((void**)&qlo,  g_qlo);
    cudaGetSymbolAddress((void**)&khi,  g_khi);
    cudaGetSymbolAddress((void**)&klo,  g_klo);
    cudaGetSymbolAddress((void**)&vhi,  g_vhi);
    cudaGetSymbolAddress((void**)&vlo,  g_vlo);
    cudaGetSymbolAddress((void**)&wqhi, g_wqhi);
    cudaGetSymbolAddress((void**)&wqlo, g_wqlo);
    cudaGetSymbolAddress((void**)&wkhi, g_wkhi);
    cudaGetSymbolAddress((void**)&wklo, g_wklo);
    cudaGetSymbolAddress((void**)&wvhi, g_wvhi);
    cudaGetSymbolAddress((void**)&wvlo, g_wvlo);
    cudaGetSymbolAddress((void**)&wohi, g_wohi);
    cudaGetSymbolAddress((void**)&wolo, g_wolo);
    cudaGetSymbolAddress((void**)&lmhi, g_lmhi);
    cudaGetSymbolAddress((void**)&lmlo, g_lmlo);

    cudaFuncSetAttribute(hgemm_kernel, cudaFuncAttributeMaxDynamicSharedMemorySize, HS_TOTAL);
    cudaFuncSetAttribute(hgemm_qkv_kernel, cudaFuncAttributeMaxDynamicSharedMemorySize, HS_TOTAL);
    cudaFuncSetAttribute(attn_mma_kernel, cudaFuncAttributeMaxDynamicSharedMemorySize, AT_SMEM);

    split_all_kernel<<<SPLIT_BLKS_ALL, 256>>>(Wq, Wk, Wv, Wo, lmw,
                                              wqhi, wqlo, wkhi, wklo, wvhi, wvlo,
                                              wohi, wolo, lmhi, lmlo);
    inj_kernel<<<dim3(N_, H_ / 128), 128>>>(hs, anchors, fcw, inj);
    buildnorm_kernel<<<T_, 256>>>(ids, anchors, embed, inj, normw, h, pos, xhi, xlo);
    hgemm_qkv_kernel<<<dim3(T_ / 128, H_ / 128, 3), 256, HS_TOTAL>>>(
        xhi, xlo, wqhi, wqlo, wkhi, wklo, wvhi, wvlo, q, k, v);
    rope_split_kernel<<<T_, 512>>>(q, k, v, pos, qhi, qlo, khi, klo, vhi, vlo);
    transposeKN_kernel<<<dim3(H_ / 32, T_ / 32), dim3(32, 8)>>>(k, kT, T_, H_);
    attn_mma_kernel<<<dim3(S_ / 64, NH_), 256, AT_SMEM>>>(
        qhi, qlo, khi, klo, vhi, vlo, aohi, aolo);
    attn_blk_kernel<<<dim3(N_, NH_), 128>>>(q, kT, v, anchors, aohi, aolo);
    hgemm_kernel<<<dim3(T_ / 128, H_ / 128), 256, HS_TOTAL>>>(
        T_, H_, H_, aohi, aolo, wohi, wolo, h2, h);
    rmsnorm_split_kernel<<<T_, 256>>>(h2, normw, xhi, xlo);
    hgemm_kernel<<<dim3(T_ / 128, V_ / 128), 256, HS_TOTAL>>>(
        T_, V_, H_, xhi, xlo, lmhi, lmlo, (float*)d_out, nullptr);
}

// round 17
// speedup vs baseline: 3.6786x; 1.2382x over previous
#include <cuda_runtime.h>
#include <cuda_bf16.h>
#include <cuda_fp16.h>
#include <math.h>
#include <stdint.h>

#define S_  2048
#define N_  64
#define BS_ 16
#define W_  512
#define NH_ 8
#define H_  1024
#define V_  32000
#define DH_ 128
#define T_  3072
#define QB  16
#define SCALE 0.08838834764831845f  // 1/sqrt(128)

// ---------------- scratch (device globals; no allocation) ----------------
__device__ float g_h [T_*H_];
__device__ float g_q [T_*H_];
__device__ float g_k [T_*H_];
__device__ float g_v [T_*H_];
__device__ float g_kT[T_*H_];
__device__ float g_h2[T_*H_];
__device__ float g_inj[N_*H_];
__device__ int   g_pos[T_];
__device__ __nv_bfloat16 g_xhi[T_*H_], g_xlo[T_*H_];
__device__ __nv_bfloat16 g_aohi[T_*H_], g_aolo[T_*H_];
__device__ __nv_bfloat16 g_qhi[T_*H_], g_qlo[T_*H_];
__device__ __nv_bfloat16 g_khi[T_*H_], g_klo[T_*H_];
__device__ __nv_bfloat16 g_vhi[T_*H_], g_vlo[T_*H_];
__device__ __nv_bfloat16 g_wqhi[H_*H_], g_wqlo[H_*H_];
__device__ __nv_bfloat16 g_wkhi[H_*H_], g_wklo[H_*H_];
__device__ __nv_bfloat16 g_wvhi[H_*H_], g_wvlo[H_*H_];
__device__ __nv_bfloat16 g_wohi[H_*H_], g_wolo[H_*H_];
__device__ __half g_xh16[T_*H_];
__device__ __half g_lm16hi[(size_t)V_*H_], g_lm16lo[(size_t)V_*H_];

// ---------------- helpers ----------------
__device__ __forceinline__ float wsum(float v){
#pragma unroll
    for (int o=16;o>0;o>>=1) v += __shfl_xor_sync(0xffffffffu, v, o);
    return v;
}
__device__ __forceinline__ float wmax(float v){
#pragma unroll
    for (int o=16;o>0;o>>=1) v = fmaxf(v, __shfl_xor_sync(0xffffffffu, v, o));
    return v;
}
__device__ __forceinline__ uint32_t smem_u32(const void* p){
    uint32_t a;
    asm("{ .reg .u64 t; cvta.to.shared.u64 t, %1; cvt.u32.u64 %0, t; }" : "=r"(a) : "l"(p));
    return a;
}
__device__ __forceinline__ void ldsm4(uint32_t& r0, uint32_t& r1, uint32_t& r2, uint32_t& r3,
                                      uint32_t addr){
    asm volatile("ldmatrix.sync.aligned.m8n8.x4.shared.b16 {%0,%1,%2,%3}, [%4];"
                 : "=r"(r0), "=r"(r1), "=r"(r2), "=r"(r3) : "r"(addr));
}
__device__ __forceinline__ void ldsm4t(uint32_t& r0, uint32_t& r1, uint32_t& r2, uint32_t& r3,
                                       uint32_t addr){
    asm volatile("ldmatrix.sync.aligned.m8n8.x4.trans.shared.b16 {%0,%1,%2,%3}, [%4];"
                 : "=r"(r0), "=r"(r1), "=r"(r2), "=r"(r3) : "r"(addr));
}
__device__ __forceinline__ void mma_bf16(float* c, const uint32_t* a, uint32_t b0, uint32_t b1){
    asm volatile("mma.sync.aligned.m16n8k16.row.col.f32.bf16.bf16.f32 "
                 "{%0,%1,%2,%3}, {%4,%5,%6,%7}, {%8,%9}, {%0,%1,%2,%3};"
                 : "+f"(c[0]), "+f"(c[1]), "+f"(c[2]), "+f"(c[3])
                 : "r"(a[0]), "r"(a[1]), "r"(a[2]), "r"(a[3]), "r"(b0), "r"(b1));
}
__device__ __forceinline__ void mma_f16(float* c, const uint32_t* a, uint32_t b0, uint32_t b1){
    asm volatile("mma.sync.aligned.m16n8k16.row.col.f32.f16.f16.f32 "
                 "{%0,%1,%2,%3}, {%4,%5,%6,%7}, {%8,%9}, {%0,%1,%2,%3};"
                 : "+f"(c[0]), "+f"(c[1]), "+f"(c[2]), "+f"(c[3])
                 : "r"(a[0]), "r"(a[1]), "r"(a[2]), "r"(a[3]), "r"(b0), "r"(b1));
}
__device__ __forceinline__ void cp16(uint32_t saddr, const void* g){
    asm volatile("cp.async.cg.shared.global [%0], [%1], 16;"
                 :: "r"(saddr), "l"(__cvta_generic_to_global(g)));
}
__device__ __forceinline__ void cp_commit(){ asm volatile("cp.async.commit_group;" ::: "memory"); }
template<int Nn> __device__ __forceinline__ void cp_wait(){
    asm volatile("cp.async.wait_group %0;" :: "n"(Nn) : "memory");
}
__device__ __forceinline__ uint32_t bf16pair(float a, float b){
    __nv_bfloat162 p = __halves2bfloat162(__float2bfloat16(a), __float2bfloat16(b));
    return *(uint32_t*)&p;
}
__device__ __forceinline__ void split2(float a, float b, uint32_t& hi, uint32_t& lo){
    __nv_bfloat16 ha = __float2bfloat16(a), hb = __float2bfloat16(b);
    hi = bf16pair(a, b);
    lo = bf16pair(a - __bfloat162float(ha), b - __bfloat162float(hb));
}
__device__ __forceinline__ void split2h(float a, float b, uint32_t& hi, uint32_t& lo){
    __half ha = __float2half(a), hb = __float2half(b);
    __half2 h = __halves2half2(ha, hb);
    __half2 l = __halves2half2(__float2half(a - __half2float(ha)),
                               __float2half(b - __half2float(hb)));
    hi = *(uint32_t*)&h;
    lo = *(uint32_t*)&l;
}

// ================ bf16-split tensor-core GEMM core (3-term) ================
#define LDSR 40
#define LDSB 136
#define ST_AHI 0
#define ST_ALO 10240
#define ST_BHI 20480
#define ST_BLO 29184
#define ST_SIZE 37888
#define NSTAGE 3
#define HS_TOTAL (NSTAGE*ST_SIZE)

__device__ __forceinline__ void gemm_core(
    int Nc, int K, int crow, int ccol,
    const __nv_bfloat16* __restrict__ Ahi, const __nv_bfloat16* __restrict__ Alo,
    const __nv_bfloat16* __restrict__ Bhi, const __nv_bfloat16* __restrict__ Blo,
    float* __restrict__ C, const float* __restrict__ D, char* sm)
{
    uint32_t sb = smem_u32(sm);
    int tid  = threadIdx.x, lane = tid & 31, wid = tid >> 5;
    int wm   = (wid & 1) * 64,  wn   = (wid >> 1) * 32;

    float acc[4][4][4];
#pragma unroll
    for (int i = 0; i < 4; i++)
#pragma unroll
        for (int j = 0; j < 4; j++)
#pragma unroll
            for (int r = 0; r < 4; r++) acc[i][j][r] = 0.f;

    uint32_t a_off = ((wm + (lane & 15)) * LDSR + (lane >> 4) * 8) * 2;
    uint32_t b_off = (uint32_t)(((((lane >> 3) & 1) * 8 + (lane & 7)) * LDSB
                                 + wn + (lane >> 4) * 8) * 2);
    int kq = K / 32;

    auto issue = [&](int ch){
        uint32_t st = sb + (ch % NSTAGE) * ST_SIZE;
        int kb = ch * 32;
#pragma unroll
        for (int r = 0; r < 2; r++) {
            int seg = tid + r * 256;
            int ar = seg >> 2, ac = (seg & 3) * 8;
            size_t ga = (size_t)(crow + ar) * K + kb + ac;
            uint32_t sa = st + ST_AHI + (uint32_t)(ar * LDSR + ac) * 2;
            cp16(sa, Ahi + ga);
            cp16(sa + (ST_ALO - ST_AHI), Alo + ga);
            int br = seg >> 4, bcx = (seg & 15) * 8;
            size_t gb = (size_t)(kb + br) * Nc + ccol + bcx;
            uint32_t sbo = st + ST_BHI + (uint32_t)(br * LDSB + bcx) * 2;
            cp16(sbo, Bhi + gb);
            cp16(sbo + (ST_BLO - ST_BHI), Blo + gb);
        }
    };

    issue(0); cp_commit();
    issue(1); cp_commit();

    for (int ch = 0; ch < kq; ch++) {
        cp_wait<NSTAGE - 2>();
        __syncthreads();
        if (ch + 2 < kq) issue(ch + 2);
        cp_commit();

        uint32_t base = sb + (ch % NSTAGE) * ST_SIZE;
#pragma unroll
        for (int ks = 0; ks < 2; ks++) {
            uint32_t bh4[2][4], bl4[2][4];
#pragma unroll
            for (int p = 0; p < 2; p++) {
                uint32_t adr = base + ST_BHI + b_off + ks * (16 * LDSB * 2) + p * 32;
                ldsm4t(bh4[p][0], bh4[p][1], bh4[p][2], bh4[p][3], adr);
                ldsm4t(bl4[p][0], bl4[p][1], bl4[p][2], bl4[p][3], adr + (ST_BLO - ST_BHI));
            }
#pragma unroll
            for (int mi = 0; mi < 4; mi++) {
                uint32_t ah[4], al[4];
                uint32_t adr = base + ST_AHI + a_off + mi * (16 * LDSR * 2) + ks * 32;
                ldsm4(ah[0], ah[1], ah[2], ah[3], adr);
                ldsm4(al[0], al[1], al[2], al[3], adr + (ST_ALO - ST_AHI));
#pragma unroll
                for (int ni = 0; ni < 4; ni++) {
                    uint32_t b0h = bh4[ni >> 1][(ni & 1) * 2], b1h = bh4[ni >> 1][(ni & 1) * 2 + 1];
                    uint32_t b0l = bl4[ni >> 1][(ni & 1) * 2], b1l = bl4[ni >> 1][(ni & 1) * 2 + 1];
                    mma_bf16(acc[mi][ni], ah, b0h, b1h);
                    mma_bf16(acc[mi][ni], ah, b0l, b1l);
                    mma_bf16(acc[mi][ni], al, b0h, b1h);
                }
            }
        }
    }

#pragma unroll
    for (int mi = 0; mi < 4; mi++)
#pragma unroll
        for (int ni = 0; ni < 4; ni++) {
            size_t r0 = (size_t)(crow + wm + mi * 16 + (lane >> 2));
            int    cc = ccol + wn + ni * 8 + (lane & 3) * 2;
            float2 v0 = make_float2(acc[mi][ni][0], acc[mi][ni][1]);
            float2 v1 = make_float2(acc[mi][ni][2], acc[mi][ni][3]);
            if (D) {
                const float2 d0 = *(const float2*)(D + r0 * Nc + cc);
                const float2 d1 = *(const float2*)(D + (r0 + 8) * Nc + cc);
                v0.x += d0.x; v0.y += d0.y; v1.x += d1.x; v1.y += d1.y;
            }
            *(float2*)(C + r0 * Nc + cc)       = v0;
            *(float2*)(C + (r0 + 8) * Nc + cc) = v1;
        }
}

__global__ __launch_bounds__(256, 2) void hgemm_kernel(
    int M, int Nc, int K,
    const __nv_bfloat16* __restrict__ Ahi, const __nv_bfloat16* __restrict__ Alo,
    const __nv_bfloat16* __restrict__ Bhi, const __nv_bfloat16* __restrict__ Blo,
    float* __restrict__ C, const float* __restrict__ D)
{
    extern __shared__ char sm[];
    gemm_core(Nc, K, blockIdx.x * 128, blockIdx.y * 128, Ahi, Alo, Bhi, Blo, C, D, sm);
}

__global__ __launch_bounds__(256, 2) void hgemm_qkv_kernel(
    const __nv_bfloat16* __restrict__ Ahi, const __nv_bfloat16* __restrict__ Alo,
    const __nv_bfloat16* __restrict__ qh, const __nv_bfloat16* __restrict__ ql,
    const __nv_bfloat16* __restrict__ kh, const __nv_bfloat16* __restrict__ kl,
    const __nv_bfloat16* __restrict__ vh, const __nv_bfloat16* __restrict__ vl,
    float* __restrict__ q, float* __restrict__ k, float* __restrict__ v)
{
    extern __shared__ char sm[];
    const __nv_bfloat16 *Bhi, *Blo;
    float* C;
    if (blockIdx.z == 0)      { Bhi = qh; Blo = ql; C = q; }
    else if (blockIdx.z == 1) { Bhi = kh; Blo = kl; C = k; }
    else                      { Bhi = vh; Blo = vl; C = v; }
    gemm_core(H_, H_, blockIdx.x * 128, blockIdx.y * 128, Ahi, Alo, Bhi, Blo, C, nullptr, sm);
}

// ================ fp16 2-term GEMM for lm_head ================
// C = A(fp16) @ (Bhi + Blo),  A rounded once, B exactly split. 2 MMAs per step.
#define S2_A   0
#define S2_BHI 10240
#define S2_BLO 18944
#define S2_SIZE 27648
#define H2_TOTAL (3*S2_SIZE)   // 82944

__global__ __launch_bounds__(256, 2) void hgemm2_kernel(
    int Nc, int K,
    const __half* __restrict__ A,
    const __half* __restrict__ Bhi, const __half* __restrict__ Blo,
    float* __restrict__ C)
{
    extern __shared__ char sm[];
    uint32_t sb = smem_u32(sm);
    int tid  = threadIdx.x, lane = tid & 31, wid = tid >> 5;
    int crow = blockIdx.x * 128, ccol = blockIdx.y * 128;
    int wm   = (wid & 1) * 64,  wn   = (wid >> 1) * 32;

    float acc[4][4][4];
#pragma unroll
    for (int i = 0; i < 4; i++)
#pragma unroll
        for (int j = 0; j < 4; j++)
#pragma unroll
            for (int r = 0; r < 4; r++) acc[i][j][r] = 0.f;

    uint32_t a_off = ((wm + (lane & 15)) * LDSR + (lane >> 4) * 8) * 2;
    uint32_t b_off = (uint32_t)(((((lane >> 3) & 1) * 8 + (lane & 7)) * LDSB
                                 + wn + (lane >> 4) * 8) * 2);
    int kq = K / 32;

    auto issue = [&](int ch){
        uint32_t st = sb + (ch % 3) * S2_SIZE;
        int kb = ch * 32;
#pragma unroll
        for (int r = 0; r < 2; r++) {
            int seg = tid + r * 256;
            int ar = seg >> 2, ac = (seg & 3) * 8;
            size_t ga = (size_t)(crow + ar) * K + kb + ac;
            cp16(st + S2_A + (uint32_t)(ar * LDSR + ac) * 2, A + ga);
            int br = seg >> 4, bcx = (seg & 15) * 8;
            size_t gb = (size_t)(kb + br) * Nc + ccol + bcx;
            uint32_t sbo = st + S2_BHI + (uint32_t)(br * LDSB + bcx) * 2;
            cp16(sbo, Bhi + gb);
            cp16(sbo + (S2_BLO - S2_BHI), Blo + gb);
        }
    };

    issue(0); cp_commit();
    issue(1); cp_commit();

    for (int ch = 0; ch < kq; ch++) {
        cp_wait<1>();
        __syncthreads();
        if (ch + 2 < kq) issue(ch + 2);
        cp_commit();

        uint32_t base = sb + (ch % 3) * S2_SIZE;
#pragma unroll
        for (int ks = 0; ks < 2; ks++) {
            uint32_t bh4[2][4], bl4[2][4];
#pragma unroll
            for (int p = 0; p < 2; p++) {
                uint32_t adr = base + S2_BHI + b_off + ks * (16 * LDSB * 2) + p * 32;
                ldsm4t(bh4[p][0], bh4[p][1], bh4[p][2], bh4[p][3], adr);
                ldsm4t(bl4[p][0], bl4[p][1], bl4[p][2], bl4[p][3], adr + (S2_BLO - S2_BHI));
            }
#pragma unroll
            for (int mi = 0; mi < 4; mi++) {
                uint32_t ah[4];
                uint32_t adr = base + S2_A + a_off + mi * (16 * LDSR * 2) + ks * 32;
                ldsm4(ah[0], ah[1], ah[2], ah[3], adr);
#pragma unroll
                for (int ni = 0; ni < 4; ni++) {
                    uint32_t b0h = bh4[ni >> 1][(ni & 1) * 2], b1h = bh4[ni >> 1][(ni & 1) * 2 + 1];
                    uint32_t b0l = bl4[ni >> 1][(ni & 1) * 2], b1l = bl4[ni >> 1][(ni & 1) * 2 + 1];
                    mma_f16(acc[mi][ni], ah, b0h, b1h);
                    mma_f16(acc[mi][ni], ah, b0l, b1l);
                }
            }
        }
    }

#pragma unroll
    for (int mi = 0; mi < 4; mi++)
#pragma unroll
        for (int ni = 0; ni < 4; ni++) {
            size_t r0 = (size_t)(crow + wm + mi * 16 + (lane >> 2));
            int    cc = ccol + wn + ni * 8 + (lane & 3) * 2;
            *(float2*)(C + r0 * Nc + cc)       = make_float2(acc[mi][ni][0], acc[mi][ni][1]);
            *(float2*)(C + (r0 + 8) * Nc + cc) = make_float2(acc[mi][ni][2], acc[mi][ni][3]);
        }
}

// ---------------- fused split of 4 small weight matrices (bf16) ----------------
__device__ __forceinline__ void split4(const float* __restrict__ in, size_t i,
                                       __nv_bfloat16* __restrict__ hi,
                                       __nv_bfloat16* __restrict__ lo)
{
    float4 v = *(const float4*)(in + i);
    uint32_t h01, l01, h23, l23;
    split2(v.x, v.y, h01, l01);
    split2(v.z, v.w, h23, l23);
    *(uint2*)(hi + i) = make_uint2(h01, h23);
    *(uint2*)(lo + i) = make_uint2(l01, l23);
}

#define SPLIT_BLKS_SMALL (H_*H_/1024)
#define SPLIT_BLKS_ALL   (4*SPLIT_BLKS_SMALL)

__global__ __launch_bounds__(256) void split_all_kernel(
    const float* __restrict__ Wq, const float* __restrict__ Wk,
    const float* __restrict__ Wv, const float* __restrict__ Wo,
    __nv_bfloat16* __restrict__ wqhi, __nv_bfloat16* __restrict__ wqlo,
    __nv_bfloat16* __restrict__ wkhi, __nv_bfloat16* __restrict__ wklo,
    __nv_bfloat16* __restrict__ wvhi, __nv_bfloat16* __restrict__ wvlo,
    __nv_bfloat16* __restrict__ wohi, __nv_bfloat16* __restrict__ wolo)
{
    int b = blockIdx.x;
    const float* src; __nv_bfloat16 *hi, *lo; int base;
    if      (b < 1 * SPLIT_BLKS_SMALL) { src = Wq; hi = wqhi; lo = wqlo; base = 0; }
    else if (b < 2 * SPLIT_BLKS_SMALL) { src = Wk; hi = wkhi; lo = wklo; base = SPLIT_BLKS_SMALL; }
    else if (b < 3 * SPLIT_BLKS_SMALL) { src = Wv; hi = wvhi; lo = wvlo; base = 2 * SPLIT_BLKS_SMALL; }
    else                               { src = Wo; hi = wohi; lo = wolo; base = 3 * SPLIT_BLKS_SMALL; }
    size_t i = ((size_t)(b - base) * 256 + threadIdx.x) * 4;
    split4(src, i, hi, lo);
}

// ---------------- lm weight split: fp32 -> fp16 hi/lo, 4x ILP ----------------
__global__ __launch_bounds__(256) void split_lm16_kernel(
    const float* __restrict__ in, __half* __restrict__ hi, __half* __restrict__ lo)
{
    size_t base = ((size_t)blockIdx.x * 256 + threadIdx.x) * 16;
    float4 v[4];
#pragma unroll
    for (int i = 0; i < 4; i++) v[i] = *(const float4*)(in + base + i * 4);
#pragma unroll
    for (int i = 0; i < 4; i++) {
        uint32_t h01, l01, h23, l23;
        split2h(v[i].x, v[i].y, h01, l01);
        split2h(v[i].z, v[i].w, h23, l23);
        *(uint2*)(hi + base + i * 4) = make_uint2(h01, h23);
        *(uint2*)(lo + base + i * 4) = make_uint2(l01, l23);
    }
}

// ---------------- inj ----------------
__global__ void inj_kernel(const float* __restrict__ hs, const int* __restrict__ anchors,
                           const float* __restrict__ fcw, float* __restrict__ inj)
{
    int n = blockIdx.x;
    int c = blockIdx.y * 128 + threadIdx.x;
    int a = anchors[n];
    int ctx = a - 1; if (ctx < 0) ctx = 0;
    const float* h0 = hs + (size_t)ctx * H_;
    const float* h1 = hs + (size_t)S_ * H_ + (size_t)ctx * H_;
    float acc = 0.f;
    for (int k = 0; k < H_; k++) acc += h0[k] * fcw[(size_t)k * H_ + c];
    for (int k = 0; k < H_; k++) acc += h1[k] * fcw[(size_t)(H_ + k) * H_ + c];
    inj[(size_t)n * H_ + c] = acc;
}

// ---------------- fused build h + rmsnorm + bf16 split ----------------
__global__ __launch_bounds__(256) void buildnorm_kernel(
    const int* __restrict__ ids, const int* __restrict__ anchors,
    const float* __restrict__ embed, const float* __restrict__ inj,
    const float* __restrict__ w,
    float* __restrict__ h, int* __restrict__ pos,
    __nv_bfloat16* __restrict__ hi, __nv_bfloat16* __restrict__ lo)
{
    int t = blockIdx.x;
    int tok;
    const float* add = nullptr;
    if (t < S_) {
        tok = ids[t];
        if (threadIdx.x == 0) pos[t] = t;
    } else {
        int n = (t - S_) / BS_, j = (t - S_) % BS_;
        int a = anchors[n];
        int ap = a; if (ap < 0) ap = 0; if (ap > S_-1) ap = S_-1;
        tok = (j == 0) ? ids[ap] : 0;
        add = inj + (size_t)n * H_;
        if (threadIdx.x == 0) pos[t] = a + j;
    }
    int c = threadIdx.x * 4;
    float4 v = *(const float4*)(embed + (size_t)tok * H_ + c);
    if (add) {
        float4 a4 = *(const float4*)(add + c);
        v.x += a4.x; v.y += a4.y; v.z += a4.z; v.w += a4.w;
    }
    *(float4*)(h + (size_t)t * H_ + c) = v;

    float ss = v.x * v.x + v.y * v.y + v.z * v.z + v.w * v.w;
    ss = wsum(ss);
    __shared__ float sred[8];
    if ((threadIdx.x & 31) == 0) sred[threadIdx.x >> 5] = ss;
    __syncthreads();
    float tot = 0.f;
#pragma unroll
    for (int i = 0; i < 8; i++) tot += sred[i];
    float inv = rsqrtf(tot * (1.0f / H_) + 1e-6f);
    float4 wv = *(const float4*)(w + c);
    float o0 = v.x * inv * wv.x, o1 = v.y * inv * wv.y;
    float o2 = v.z * inv * wv.z, o3 = v.w * inv * wv.w;
    uint32_t h01, l01, h23, l23;
    split2(o0, o1, h01, l01);
    split2(o2, o3, h23, l23);
    *(uint2*)(hi + (size_t)t * H_ + c) = make_uint2(h01, h23);
    *(uint2*)(lo + (size_t)t * H_ + c) = make_uint2(l01, l23);
}

// ---------------- rmsnorm -> single fp16 output (lm_head A) ----------------
__global__ __launch_bounds__(256) void rmsnorm_h16_kernel(const float* __restrict__ in,
                                                          const float* __restrict__ w,
                                                          __half* __restrict__ out)
{
    int t = blockIdx.x;
    int c = threadIdx.x * 4;
    float4 v = *(const float4*)(in + (size_t)t * H_ + c);
    float ss = v.x * v.x + v.y * v.y + v.z * v.z + v.w * v.w;
    ss = wsum(ss);
    __shared__ float sred[8];
    if ((threadIdx.x & 31) == 0) sred[threadIdx.x >> 5] = ss;
    __syncthreads();
    float tot = 0.f;
#pragma unroll
    for (int i = 0; i < 8; i++) tot += sred[i];
    float inv = rsqrtf(tot * (1.0f / H_) + 1e-6f);
    float4 wv = *(const float4*)(w + c);
    __half2 a01 = __halves2half2(__float2half(v.x * inv * wv.x), __float2half(v.y * inv * wv.y));
    __half2 a23 = __halves2half2(__float2half(v.z * inv * wv.z), __float2half(v.w * inv * wv.w));
    *(uint2*)(out + (size_t)t * H_ + c) = make_uint2(*(uint32_t*)&a01, *(uint32_t*)&a23);
}

// ---------------- RoPE + split q(scaled)/k/v to bf16 hi/lo ----------------
__global__ void rope_split_kernel(float* __restrict__ q, float* __restrict__ k,
                                  const float* __restrict__ v, const int* __restrict__ pos,
                                  __nv_bfloat16* __restrict__ qhi, __nv_bfloat16* __restrict__ qlo,
                                  __nv_bfloat16* __restrict__ khi, __nv_bfloat16* __restrict__ klo,
                                  __nv_bfloat16* __restrict__ vhi, __nv_bfloat16* __restrict__ vlo)
{
    int t = blockIdx.x;
    int idx = threadIdx.x;
    int hh = idx >> 6, i = idx & 63;
    int p = pos[t];
    float inv_freq = exp2f(-(float)i * (13.287712379549449f / 64.0f));
    float ang = (float)p * inv_freq;
    float s, c;
    sincosf(ang, &s, &c);
    size_t b = (size_t)t * H_ + hh * DH_ + i;
    float x1 = q[b], x2 = q[b + 64];
    float q1 = x1 * c - x2 * s;
    float q2 = x2 * c + x1 * s;
    q[b] = q1; q[b + 64] = q2;
    {
        float a1 = q1 * SCALE, a2 = q2 * SCALE;
        __nv_bfloat16 h1 = __float2bfloat16(a1), h2 = __float2bfloat16(a2);
        qhi[b] = h1;      qhi[b + 64] = h2;
        qlo[b] = __float2bfloat16(a1 - __bfloat162float(h1));
        qlo[b + 64] = __float2bfloat16(a2 - __bfloat162float(h2));
    }
    x1 = k[b]; x2 = k[b + 64];
    float k1 = x1 * c - x2 * s;
    float k2 = x2 * c + x1 * s;
    k[b] = k1; k[b + 64] = k2;
    {
        __nv_bfloat16 h1 = __float2bfloat16(k1), h2 = __float2bfloat16(k2);
        khi[b] = h1;      khi[b + 64] = h2;
        klo[b] = __float2bfloat16(k1 - __bfloat162float(h1));
        klo[b + 64] = __float2bfloat16(k2 - __bfloat162float(h2));
    }
    size_t vb = (size_t)t * H_ + idx * 2;
    float v0 = v[vb], v1 = v[vb + 1];
    __nv_bfloat16 hv0 = __float2bfloat16(v0), hv1 = __float2bfloat16(v1);
    vhi[vb] = hv0; vhi[vb + 1] = hv1;
    vlo[vb] = __float2bfloat16(v0 - __bfloat162float(hv0));
    vlo[vb + 1] = __float2bfloat16(v1 - __bfloat162float(hv1));
}

// ---------------- transpose in[Kd][Nd] -> out[Nd][Kd] ----------------
__global__ void transposeKN_kernel(const float* __restrict__ in, float* __restrict__ out,
                                   int Kd, int Nd)
{
    __shared__ float tile[32][33];
    int n0 = blockIdx.x * 32;
    int k0 = blockIdx.y * 32;
    int x = threadIdx.x, y0 = threadIdx.y;
#pragma unroll
    for (int dy = 0; dy < 32; dy += 8)
        tile[y0 + dy][x] = in[(size_t)(k0 + y0 + dy) * Nd + n0 + x];
    __syncthreads();
#pragma unroll
    for (int dy = 0; dy < 32; dy += 8)
        out[(size_t)(n0 + y0 + dy) * Kd + k0 + x] = tile[x][y0 + dy];
}

// ================ tensor-core attention for FULL queries (causal) ================
#define LQ 136
#define LP 72
#define AS_QHI 0
#define AS_QLO 17408
#define AS_PHI 34816
#define AS_PLO 44032
#define AS_M   53248
#define AS_L   53504
#define AS_F   53760
#define AS_PMAX 54016
#define AS_PSUM 54528
#define AS_KV   55040
#define KV_ARR  17408
#define KV_STAGE (4*KV_ARR)
#define AT_SMEM (AS_KV + 2*KV_STAGE)

__global__ __launch_bounds__(256, 1) void attn_mma_kernel(
    const __nv_bfloat16* __restrict__ qhi, const __nv_bfloat16* __restrict__ qlo,
    const __nv_bfloat16* __restrict__ khi, const __nv_bfloat16* __restrict__ klo,
    const __nv_bfloat16* __restrict__ vhi, const __nv_bfloat16* __restrict__ vlo,
    __nv_bfloat16* __restrict__ ohi_out, __nv_bfloat16* __restrict__ olo_out)
{
    extern __shared__ char sm[];
    uint32_t sb = smem_u32(sm);
    int tid = threadIdx.x, lane = tid & 31, w = tid >> 5;
    int h = blockIdx.y, t0 = blockIdx.x * 64;
    int nch = t0 / 64 + 1;

    const __nv_bfloat16* qh = qhi + (size_t)t0 * H_ + h * DH_;
    const __nv_bfloat16* ql = qlo + (size_t)t0 * H_ + h * DH_;
    const __nv_bfloat16* kh = khi + h * DH_;
    const __nv_bfloat16* kl = klo + h * DH_;
    const __nv_bfloat16* vh = vhi + h * DH_;
    const __nv_bfloat16* vl = vlo + h * DH_;

#pragma unroll
    for (int i = 0; i < 4; i++) {
        int lin = i * 256 + tid;
        int row = lin >> 4, seg = lin & 15;
        size_t go = (size_t)row * H_ + seg * 8;
        uint32_t so = (uint32_t)(row * 272 + seg * 16);
        cp16(sb + AS_QHI + so, qh + go);
        cp16(sb + AS_QLO + so, ql + go);
    }
    cp_commit();

    float* Ms = (float*)(sm + AS_M);
    float* Ls = (float*)(sm + AS_L);
    float* Fs = (float*)(sm + AS_F);
    float* Pm = (float*)(sm + AS_PMAX);
    float* Ps = (float*)(sm + AS_PSUM);
    if (tid < 64) { Ms[tid] = -3e38f; Ls[tid] = 0.f; }

    auto issueKV = [&](int ch){
        if (ch < nch) {
            uint32_t st = sb + AS_KV + (ch & 1) * KV_STAGE;
            int kb = ch * 64;
#pragma unroll
            for (int i = 0; i < 4; i++) {
                int lin = i * 256 + tid;
                int row = lin >> 4, seg = lin & 15;
                size_t go = (size_t)(kb + row) * H_ + seg * 8;
                uint32_t so = (uint32_t)(row * 272 + seg * 16);
                cp16(st + 0 * KV_ARR + so, kh + go);
                cp16(st + 1 * KV_ARR + so, kl + go);
                cp16(st + 2 * KV_ARR + so, vh + go);
                cp16(st + 3 * KV_ARR + so, vl + go);
            }
        }
        cp_commit();
    };
    issueKV(0);

    int wrow = (w & 3) * 16, wcol = (w >> 2) * 32;
    int prow = wrow, pcol = (w >> 2) * 64;
    int wc = w >> 2;
    uint32_t qa_off = (uint32_t)(((wrow + (lane & 15)) * LQ + (lane >> 4) * 8) * 2);
    uint32_t kb_off = (uint32_t)(((wcol + (lane >> 4) * 8 + (lane & 7)) * LQ + ((lane >> 3) & 1) * 8) * 2);
    uint32_t pa_off = (uint32_t)(((prow + (lane & 15)) * LP + (lane >> 4) * 8) * 2);
    uint32_t vb_off = (uint32_t)(((((lane >> 3) & 1) * 8 + (lane & 7)) * LQ + pcol + (lane >> 4) * 8) * 2);

    float accO[8][4];
#pragma unroll
    for (int i = 0; i < 8; i++)
#pragma unroll
        for (int r = 0; r < 4; r++) accO[i][r] = 0.f;

    for (int ch = 0; ch < nch; ch++) {
        issueKV(ch + 1);
        cp_wait<1>();
        __syncthreads();
        uint32_t kst = sb + AS_KV + (ch & 1) * KV_STAGE;

        float sAcc[4][4];
#pragma unroll
        for (int i = 0; i < 4; i++)
#pragma unroll
            for (int r = 0; r < 4; r++) sAcc[i][r] = 0.f;
#pragma unroll
        for (int ks = 0; ks < 8; ks++) {
            uint32_t ah[4], al[4], bh[2][4], bl[2][4];
            uint32_t adr = sb + AS_QHI + qa_off + ks * 32;
            ldsm4(ah[0], ah[1], ah[2], ah[3], adr);
            ldsm4(al[0], al[1], al[2], al[3], adr + (AS_QLO - AS_QHI));
#pragma unroll
            for (int p = 0; p < 2; p++) {
                uint32_t badr = kst + kb_off + p * (16 * LQ * 2) + ks * 32;
                ldsm4(bh[p][0], bh[p][1], bh[p][2], bh[p][3], badr);
                ldsm4(bl[p][0], bl[p][1], bl[p][2], bl[p][3], badr + KV_ARR);
            }
#pragma unroll
            for (int c8 = 0; c8 < 4; c8++) {
                uint32_t b0h = bh[c8 >> 1][(c8 & 1) * 2], b1h = bh[c8 >> 1][(c8 & 1) * 2 + 1];
                uint32_t b0l = bl[c8 >> 1][(c8 & 1) * 2], b1l = bl[c8 >> 1][(c8 & 1) * 2 + 1];
                mma_bf16(sAcc[c8], ah, b0h, b1h);
                mma_bf16(sAcc[c8], ah, b0l, b1l);
                mma_bf16(sAcc[c8], al, b0h, b1h);
            }
        }
        if (ch == nch - 1) {
#pragma unroll
            for (int c8 = 0; c8 < 4; c8++)
#pragma unroll
                for (int r = 0; r < 4; r++) {
                    int rl = wrow + (lane >> 2) + ((r >> 1) ? 8 : 0);
                    int cl = wcol + c8 * 8 + (lane & 3) * 2 + (r & 1);
                    if (cl > rl) sAcc[c8][r] = -3e38f;
                }
        }
        {
            float mx0 = -3e38f, mx1 = -3e38f;
#pragma unroll
            for (int c8 = 0; c8 < 4; c8++) {
                mx0 = fmaxf(mx0, fmaxf(sAcc[c8][0], sAcc[c8][1]));
                mx1 = fmaxf(mx1, fmaxf(sAcc[c8][2], sAcc[c8][3]));
            }
            mx0 = fmaxf(mx0, __shfl_xor_sync(0xffffffffu, mx0, 1));
            mx0 = fmaxf(mx0, __shfl_xor_sync(0xffffffffu, mx0, 2));
            mx1 = fmaxf(mx1, __shfl_xor_sync(0xffffffffu, mx1, 1));
            mx1 = fmaxf(mx1, __shfl_xor_sync(0xffffffffu, mx1, 2));
            if ((lane & 3) == 0) {
                int r0 = wrow + (lane >> 2);
                Pm[r0 * 2 + wc]       = mx0;
                Pm[(r0 + 8) * 2 + wc] = mx1;
            }
        }
        __syncthreads();
        if (w < 4 && lane < 16) {
            int r = w * 16 + lane;
            float mold = Ms[r];
            float mnew = fmaxf(mold, fmaxf(Pm[r * 2], Pm[r * 2 + 1]));
            Fs[r] = expf(mold - mnew);
            Ms[r] = mnew;
        }
        __syncthreads();
        {
            int r0 = wrow + (lane >> 2);
            float m0 = Ms[r0], m1 = Ms[r0 + 8];
            float s0 = 0.f, s1 = 0.f;
#pragma unroll
            for (int c8 = 0; c8 < 4; c8++) {
                float p0 = expf(sAcc[c8][0] - m0), p1 = expf(sAcc[c8][1] - m0);
                float p2 = expf(sAcc[c8][2] - m1), p3 = expf(sAcc[c8][3] - m1);
                s0 += p0 + p1; s1 += p2 + p3;
                int colb = wcol + c8 * 8 + (lane & 3) * 2;
                uint32_t hi01, lo01, hi23, lo23;
                split2(p0, p1, hi01, lo01);
                split2(p2, p3, hi23, lo23);
                *(uint32_t*)(sm + AS_PHI + (r0 * LP + colb) * 2)       = hi01;
                *(uint32_t*)(sm + AS_PLO + (r0 * LP + colb) * 2)       = lo01;
                *(uint32_t*)(sm + AS_PHI + ((r0 + 8) * LP + colb) * 2) = hi23;
                *(uint32_t*)(sm + AS_PLO + ((r0 + 8) * LP + colb) * 2) = lo23;
            }
            s0 += __shfl_xor_sync(0xffffffffu, s0, 1);
            s0 += __shfl_xor_sync(0xffffffffu, s0, 2);
            s1 += __shfl_xor_sync(0xffffffffu, s1, 1);
            s1 += __shfl_xor_sync(0xffffffffu, s1, 2);
            if ((lane & 3) == 0) {
                Ps[r0 * 2 + wc]       = s0;
                Ps[(r0 + 8) * 2 + wc] = s1;
            }
            float f0 = Fs[prow + (lane >> 2)], f1 = Fs[prow + (lane >> 2) + 8];
#pragma unroll
            for (int nt = 0; nt < 8; nt++) {
                accO[nt][0] *= f0; accO[nt][1] *= f0;
                accO[nt][2] *= f1; accO[nt][3] *= f1;
            }
        }
        __syncthreads();
#pragma unroll
        for (int ks = 0; ks < 4; ks++) {
            uint32_t ah[4], al[4];
            uint32_t padr = sb + AS_PHI + pa_off + ks * 32;
            ldsm4(ah[0], ah[1], ah[2], ah[3], padr);
            ldsm4(al[0], al[1], al[2], al[3], padr + (AS_PLO - AS_PHI));
            uint32_t bh[4][4], bl[4][4];
#pragma unroll
            for (int p = 0; p < 4; p++) {
                uint32_t vadr = kst + 2 * KV_ARR + vb_off + ks * (16 * LQ * 2) + p * 32;
                ldsm4t(bh[p][0], bh[p][1], bh[p][2], bh[p][3], vadr);
                ldsm4t(bl[p][0], bl[p][1], bl[p][2], bl[p][3], vadr + KV_ARR);
            }
#pragma unroll
            for (int nt = 0; nt < 8; nt++) {
                uint32_t b0h = bh[nt >> 1][(nt & 1) * 2], b1h = bh[nt >> 1][(nt & 1) * 2 + 1];
                uint32_t b0l = bl[nt >> 1][(nt & 1) * 2], b1l = bl[nt >> 1][(nt & 1) * 2 + 1];
                mma_bf16(accO[nt], ah, b0h, b1h);
                mma_bf16(accO[nt], ah, b0l, b1l);
                mma_bf16(accO[nt], al, b0h, b1h);
            }
        }
        if (w < 4 && lane < 16) {
            int r = w * 16 + lane;
            Ls[r] = Ls[r] * Fs[r] + Ps[r * 2] + Ps[r * 2 + 1];
        }
    }
    __syncthreads();
    {
        int r0 = prow + (lane >> 2);
        float l0 = Ls[r0], l1 = Ls[r0 + 8];
#pragma unroll
        for (int nt = 0; nt < 8; nt++) {
            int colb = pcol + nt * 8 + (lane & 3) * 2;
            float o0 = accO[nt][0] / l0, o1 = accO[nt][1] / l0;
            float o2 = accO[nt][2] / l1, o3 = accO[nt][3] / l1;
            uint32_t hi01, lo01, hi23, lo23;
            split2(o0, o1, hi01, lo01);
            split2(o2, o3, hi23, lo23);
            size_t i0 = (size_t)(t0 + r0) * H_ + h * DH_ + colb;
            size_t i1 = (size_t)(t0 + r0 + 8) * H_ + h * DH_ + colb;
            *(uint32_t*)(ohi_out + i0) = hi01;
            *(uint32_t*)(olo_out + i0) = lo01;
            *(uint32_t*)(ohi_out + i1) = hi23;
            *(uint32_t*)(olo_out + i1) = lo23;
        }
    }
}

// ---------------- SIMT attention for BLOCK queries only ----------------
__global__ __launch_bounds__(128) void attn_blk_kernel(
    const float* __restrict__ q, const float* __restrict__ kT,
    const float* __restrict__ v, const int* __restrict__ anchors,
    __nv_bfloat16* __restrict__ ohi, __nv_bfloat16* __restrict__ olo)
{
    __shared__ float qs[QB][DH_];
    __shared__ float pbuf[QB][128];
    __shared__ float redm[QB][4];
    __shared__ float reds[QB][4];

    int h   = blockIdx.y;
    int nb  = blockIdx.x;
    int t0  = S_ + nb * QB;
    int tid = threadIdx.x;
    int w   = tid >> 5, lane = tid & 31;

#pragma unroll
    for (int qi = 0; qi < QB; qi++)
        qs[qi][tid] = q[(size_t)(t0 + qi) * H_ + h * DH_ + tid] * SCALE;
    __syncthreads();

    float m[QB], l[QB], acc[QB];
#pragma unroll
    for (int qi = 0; qi < QB; qi++) { m[qi] = -INFINITY; l[qi] = 0.f; acc[qi] = 0.f; }

    int lo_[1], hi_[1];

    auto proc = [&](int base, int cnt) {
        int k = base + tid;
        bool act = (tid < cnt) && (k >= lo_[0]) && (k <= hi_[0]);
        float s[QB];
#pragma unroll
        for (int qi = 0; qi < QB; qi++) s[qi] = -INFINITY;
        if (act) {
#pragma unroll
            for (int qi = 0; qi < QB; qi++) s[qi] = 0.f;
            const float* kp = kT + (size_t)(h * DH_) * T_ + k;
            for (int d = 0; d < DH_; d += 4) {
                float kv0 = kp[(size_t)(d + 0) * T_];
                float kv1 = kp[(size_t)(d + 1) * T_];
                float kv2 = kp[(size_t)(d + 2) * T_];
                float kv3 = kp[(size_t)(d + 3) * T_];
#pragma unroll
                for (int qi = 0; qi < QB; qi++) {
                    float4 qv = *(const float4*)&qs[qi][d];
                    s[qi] += qv.x * kv0 + qv.y * kv1 + qv.z * kv2 + qv.w * kv3;
                }
            }
        }
        __syncthreads();
#pragma unroll
        for (int qi = 0; qi < QB; qi++) {
            float x = wmax(s[qi]);
            if (lane == 0) redm[qi][w] = x;
        }
        __syncthreads();
        float nm[QB];
#pragma unroll
        for (int qi = 0; qi < QB; qi++) {
            float cm = fmaxf(fmaxf(redm[qi][0], redm[qi][1]), fmaxf(redm[qi][2], redm[qi][3]));
            nm[qi] = fmaxf(m[qi], cm);
            float p = (s[qi] == -INFINITY) ? 0.f : expf(s[qi] - nm[qi]);
            pbuf[qi][tid] = p;
            float sp = wsum(p);
            if (lane == 0) reds[qi][w] = sp;
        }
        __syncthreads();
#pragma unroll
        for (int qi = 0; qi < QB; qi++) {
            float f = (m[qi] == -INFINITY) ? 0.f : expf(m[qi] - nm[qi]);
            float cs = reds[qi][0] + reds[qi][1] + reds[qi][2] + reds[qi][3];
            l[qi] = l[qi] * f + cs;
            acc[qi] *= f;
            m[qi] = nm[qi];
        }
        const float* vp = v + (size_t)base * H_ + h * DH_ + tid;
        for (int j = 0; j < cnt; j += 4) {
            float vv0 = vp[(size_t)(j + 0) * H_];
            float vv1 = vp[(size_t)(j + 1) * H_];
            float vv2 = vp[(size_t)(j + 2) * H_];
            float vv3 = vp[(size_t)(j + 3) * H_];
#pragma unroll
            for (int qi = 0; qi < QB; qi++) {
                float4 pv = *(const float4*)&pbuf[qi][j];
                acc[qi] += pv.x * vv0 + pv.y * vv1 + pv.z * vv2 + pv.w * vv3;
            }
        }
    };

    int a  = anchors[nb];
    int ws = a - W_ + 1; if (ws < 0) ws = 0;
    int we = a - 1;
    lo_[0] = ws; hi_[0] = we;
    for (int base = (ws >> 7) << 7; base <= we; base += 128) proc(base, 128);
    int kb = S_ + nb * BS_;
    lo_[0] = kb; hi_[0] = kb + BS_ - 1;
    proc(kb, BS_);

#pragma unroll
    for (int qi = 0; qi < QB; qi++) {
        float o = acc[qi] / l[qi];
        size_t idx = (size_t)(t0 + qi) * H_ + h * DH_ + tid;
        __nv_bfloat16 hb = __float2bfloat16(o);
        ohi[idx] = hb;
        olo[idx] = __float2bfloat16(o - __bfloat162float(hb));
    }
}

// ---------------- launch ----------------
extern "C" void kernel_launch(void* const* d_in, const int* in_sizes, int n_in,
                              void* d_out, int out_size)
{
    const int*   ids     = (const int*)  d_in[0];
    const float* hs      = (const float*)d_in[1];
    const int*   anchors = (const int*)  d_in[2];
    // d_in[3] block_keep_mask: all-true by construction; intentionally unused
    const float* embed   = (const float*)d_in[4];
    const float* Wq      = (const float*)d_in[5];
    const float* Wk      = (const float*)d_in[6];
    const float* Wv      = (const float*)d_in[7];
    const float* Wo      = (const float*)d_in[8];
    const float* fcw     = (const float*)d_in[9];
    const float* lmw     = (const float*)d_in[10];
    const float* normw   = (const float*)d_in[11];

    float *h, *q, *k, *v, *kT, *h2, *inj;
    int* pos;
    __nv_bfloat16 *xhi, *xlo, *aohi, *aolo, *qhi, *qlo, *khi, *klo, *vhi, *vlo;
    __nv_bfloat16 *wqhi, *wqlo, *wkhi, *wklo, *wvhi, *wvlo, *wohi, *wolo;
    __half *xh16, *lm16hi, *lm16lo;
    cudaGetSymbolAddress((void**)&h,    g_h);
    cudaGetSymbolAddress((void**)&q,    g_q);
    cudaGetSymbolAddress((void**)&k,    g_k);
    cudaGetSymbolAddress((void**)&v,    g_v);
    cudaGetSymbolAddress((void**)&kT,   g_kT);
    cudaGetSymbolAddress((void**)&h2,   g_h2);
    cudaGetSymbolAddress((void**)&inj,  g_inj);
    cudaGetSymbolAddress((void**)&pos,  g_pos);
    cudaGetSymbolAddress((void**)&xhi,  g_xhi);
    cudaGetSymbolAddress((void**)&xlo,  g_xlo);
    cudaGetSymbolAddress((void**)&aohi, g_aohi);
    cudaGetSymbolAddress((void**)&aolo, g_aolo);
    cudaGetSymbolAddress((void**)&qhi,  g_qhi);
    cudaGetSymbolAddress((void**)&qlo,  g_qlo);
    cudaGetSymbolAddress((void**)&khi,  g_khi);
    cudaGetSymbolAddress((void**)&klo,  g_klo);
    cudaGetSymbolAddress((void**)&vhi,  g_vhi);
    cudaGetSymbolAddress((void**)&vlo,  g_vlo);
    cudaGetSymbolAddress((void**)&wqhi, g_wqhi);
    cudaGetSymbolAddress((void**)&wqlo, g_wqlo);
    cudaGetSymbolAddress((void**)&wkhi, g_wkhi);
    cudaGetSymbolAddress((void**)&wklo, g_wklo);
    cudaGetSymbolAddress((void**)&wvhi, g_wvhi);
    cudaGetSymbolAddress((void**)&wvlo, g_wvlo);
    cudaGetSymbolAddress((void**)&wohi, g_wohi);
    cudaGetSymbolAddress((void**)&wolo, g_wolo);
    cudaGetSymbolAddress((void**)&xh16,  g_xh16);
    cudaGetSymbolAddress((void**)&lm16hi, g_lm16hi);
    cudaGetSymbolAddress((void**)&lm16lo, g_lm16lo);

    cudaFuncSetAttribute(hgemm_kernel, cudaFuncAttributeMaxDynamicSharedMemorySize, HS_TOTAL);
    cudaFuncSetAttribute(hgemm_qkv_kernel, cudaFuncAttributeMaxDynamicSharedMemorySize, HS_TOTAL);
    cudaFuncSetAttribute(hgemm2_kernel, cudaFuncAttributeMaxDynamicSharedMemorySize, H2_TOTAL);
    cudaFuncSetAttribute(attn_mma_kernel, cudaFuncAttributeMaxDynamicSharedMemorySize, AT_SMEM);

    split_all_kernel<<<SPLIT_BLKS_ALL, 256>>>(Wq, Wk, Wv, Wo,
                                              wqhi, wqlo, wkhi, wklo, wvhi, wvlo, wohi, wolo);
    inj_kernel<<<dim3(N_, H_ / 128), 128>>>(hs, anchors, fcw, inj);
    buildnorm_kernel<<<T_, 256>>>(ids, anchors, embed, inj, normw, h, pos, xhi, xlo);
    hgemm_qkv_kernel<<<dim3(T_ / 128, H_ / 128, 3), 256, HS_TOTAL>>>(
        xhi, xlo, wqhi, wqlo, wkhi, wklo, wvhi, wvlo, q, k, v);
    split_lm16_kernel<<<(int)((size_t)V_ * H_ / 4096), 256>>>(lmw, lm16hi, lm16lo);
    rope_split_kernel<<<T_, 512>>>(q, k, v, pos, qhi, qlo, khi, klo, vhi, vlo);
    transposeKN_kernel<<<dim3(H_ / 32, T_ / 32), dim3(32, 8)>>>(k, kT, T_, H_);
    attn_mma_kernel<<<dim3(S_ / 64, NH_), 256, AT_SMEM>>>(
        qhi, qlo, khi, klo, vhi, vlo, aohi, aolo);
    attn_blk_kernel<<<dim3(N_, NH_), 128>>>(q, kT, v, anchors, aohi, aolo);
    hgemm_kernel<<<dim3(T_ / 128, H_ / 128), 256, HS_TOTAL>>>(
        T_, H_, H_, aohi, aolo, wohi, wolo, h2, h);
    rmsnorm_h16_kernel<<<T_, 256>>>(h2, normw, xh16);
    hgemm2_kernel<<<dim3(T_ / 128, V_ / 128), 256, H2_TOTAL>>>(
        V_, H_, xh16, lm16hi, lm16lo, (float*)d_out);
}